// round 8
// baseline (speedup 1.0000x reference)
#include <cuda_runtime.h>
#include <cstdint>

#define NB 8
#define NSEQ 1024
#define CDIM 1280
#define NH 20
#define DH 64
#define MCTX 77
#define CTXC 768
#define FFD 5120
#define FF2D 10240
#define ROWS (NB*NSEQ)
#define BHD (NB*NH)
#define CROSSROWS (NB*MCTX)

static constexpr size_t SZ_XC = (size_t)ROWS * CDIM;
static constexpr size_t OFF_XN = 0;
static constexpr size_t OFF_Q  = OFF_XN + SZ_XC;
static constexpr size_t OFF_K  = OFF_Q + SZ_XC;
static constexpr size_t OFF_V  = OFF_K + SZ_XC;
static constexpr size_t OFF_O  = OFF_V + SZ_XC;
static constexpr size_t OFF_X1 = OFF_O + SZ_XC;
static constexpr size_t OFF_S  = OFF_X1 + SZ_XC;
static constexpr size_t SZ_S   = (size_t)BHD * NSEQ * NSEQ;
static constexpr size_t OFF_H  = OFF_S + SZ_S;
static constexpr size_t SZ_H   = (size_t)ROWS * FF2D;
static constexpr size_t OFF_G  = OFF_H + SZ_H;
static constexpr size_t SZ_G   = (size_t)ROWS * FFD;
static constexpr size_t OFF_RM = OFF_G + SZ_G;
static constexpr size_t OFF_RZ = OFF_RM + (size_t)BHD * NSEQ;
static constexpr size_t OFF_AM = OFF_RZ + (size_t)BHD * NSEQ;
static constexpr size_t SZ_W1  = (size_t)CDIM * CDIM;
static constexpr size_t SZ_WK2 = (size_t)CTXC * CDIM;
static constexpr size_t SZ_WF1 = (size_t)CDIM * FF2D;
static constexpr size_t SZ_WF2 = (size_t)FFD * CDIM;
static constexpr size_t SZ_CTXB = (size_t)CROSSROWS * CTXC;
static constexpr size_t OFF_WQ1 = OFF_AM + 8;
static constexpr size_t OFF_WK1 = OFF_WQ1 + SZ_W1;
static constexpr size_t OFF_WV1 = OFF_WK1 + SZ_W1;
static constexpr size_t OFF_WO1 = OFF_WV1 + SZ_W1;
static constexpr size_t OFF_WQ2 = OFF_WO1 + SZ_W1;
static constexpr size_t OFF_WO2 = OFF_WQ2 + SZ_W1;
static constexpr size_t OFF_WK2 = OFF_WO2 + SZ_W1;
static constexpr size_t OFF_WV2 = OFF_WK2 + SZ_WK2;
static constexpr size_t OFF_WF1 = OFF_WV2 + SZ_WK2;
static constexpr size_t OFF_WF2 = OFF_WF1 + SZ_WF1;
static constexpr size_t OFF_CTX = OFF_WF2 + SZ_WF2;
static constexpr size_t SZ_S8F  = (size_t)ROWS * CDIM / 4;
static constexpr size_t OFF_LQ8 = OFF_CTX + SZ_CTXB;
static constexpr size_t OFF_LK8 = OFF_LQ8 + SZ_S8F;
static constexpr size_t OFF_LVT = OFF_LK8 + SZ_S8F;
static constexpr size_t TOTAL_SCRATCH = OFF_LVT + SZ_S8F;

__device__ __align__(256) float g_scratch[TOTAL_SCRATCH];

__global__ void init_amax_kernel(unsigned* amax) {
    if (threadIdx.x < 8) amax[threadIdx.x] = 0u;
}

__device__ __forceinline__ float gelu_tanh(float x) {
    float x3 = x * x * x;
    return 0.5f * x * (1.0f + tanhf(0.7978845608028654f * (x + 0.044715f * x3)));
}

__device__ __forceinline__ uint32_t f2tf32(float f) {
    uint32_t r;
    asm("cvt.rna.tf32.f32 %0, %1;" : "=r"(r) : "f"(f));
    return r;
}
__device__ __forceinline__ float tf32r(float f) { return __uint_as_float(f2tf32(f)); }

__device__ __forceinline__ void mma_tf32(float* d, const uint32_t* a, const uint32_t* b) {
    asm volatile("mma.sync.aligned.m16n8k8.row.col.f32.tf32.tf32.f32 "
        "{%0,%1,%2,%3}, {%4,%5,%6,%7}, {%8,%9}, {%0,%1,%2,%3};"
        : "+f"(d[0]), "+f"(d[1]), "+f"(d[2]), "+f"(d[3])
        : "r"(a[0]), "r"(a[1]), "r"(a[2]), "r"(a[3]), "r"(b[0]), "r"(b[1]));
}

__device__ __forceinline__ void mma_s8(int* d, const uint32_t* a, const uint32_t* b) {
    asm volatile("mma.sync.aligned.m16n8k32.row.col.s32.s8.s8.s32 "
        "{%0,%1,%2,%3}, {%4,%5,%6,%7}, {%8,%9}, {%0,%1,%2,%3};"
        : "+r"(d[0]), "+r"(d[1]), "+r"(d[2]), "+r"(d[3])
        : "r"(a[0]), "r"(a[1]), "r"(a[2]), "r"(a[3]), "r"(b[0]), "r"(b[1]));
}

__device__ __forceinline__ void mma_u8s8(int* d, const uint32_t* a, const uint32_t* b) {
    asm volatile("mma.sync.aligned.m16n8k32.row.col.s32.u8.s8.s32 "
        "{%0,%1,%2,%3}, {%4,%5,%6,%7}, {%8,%9}, {%0,%1,%2,%3};"
        : "+r"(d[0]), "+r"(d[1]), "+r"(d[2]), "+r"(d[3])
        : "r"(a[0]), "r"(a[1]), "r"(a[2]), "r"(a[3]), "r"(b[0]), "r"(b[1]));
}

__device__ __forceinline__ void ldsm4(uint32_t& r0, uint32_t& r1, uint32_t& r2, uint32_t& r3,
                                      uint32_t addr) {
    asm volatile("ldmatrix.sync.aligned.m8n8.x4.shared.b16 {%0,%1,%2,%3}, [%4];"
        : "=r"(r0), "=r"(r1), "=r"(r2), "=r"(r3) : "r"(addr));
}

__device__ __forceinline__ void cp_async16(uint32_t dst, const void* src, int srcsize) {
    asm volatile("cp.async.cg.shared.global [%0], [%1], 16, %2;"
                 :: "r"(dst), "l"(src), "r"(srcsize));
}

__device__ __forceinline__ int clamp_i(int v, int lo, int hi) {
    return v < lo ? lo : (v > hi ? hi : v);
}

__device__ __forceinline__ uint32_t pack_s8x4(float4 v, float inv) {
    int a = clamp_i(__float2int_rn(v.x * inv), -128, 127);
    int b = clamp_i(__float2int_rn(v.y * inv), -128, 127);
    int c = clamp_i(__float2int_rn(v.z * inv), -128, 127);
    int d = clamp_i(__float2int_rn(v.w * inv), -128, 127);
    return (a & 255) | ((b & 255) << 8) | ((c & 255) << 16) | ((d & 255) << 24);
}

// -------- tf32 convert (straight copy; used for ctx) --------
__global__ void conv_tf32_kernel(const float* __restrict__ src, float* __restrict__ dst,
                                 long long n4)
{
    long long stride = (long long)gridDim.x * blockDim.x;
    for (long long i = (long long)blockIdx.x * blockDim.x + threadIdx.x; i < n4; i += stride) {
        float4 v = *(const float4*)(src + i * 4);
        v.x = tf32r(v.x); v.y = tf32r(v.y); v.z = tf32r(v.z); v.w = tf32r(v.w);
        *(float4*)(dst + i * 4) = v;
    }
}

// -------- tf32 convert + transpose: src[K][N] -> dst[N][K] --------
__global__ void trans_tf32_kernel(const float* __restrict__ src, float* __restrict__ dst,
                                  int Kn, int Nn)
{
    __shared__ float t[32][33];
    int n0 = blockIdx.x * 32, k0 = blockIdx.y * 32;
    int tx = threadIdx.x & 31, ty0 = threadIdx.x >> 5;   // 256 threads = 32x8
    #pragma unroll
    for (int i = 0; i < 4; i++) {
        int ty = ty0 + i * 8;
        t[ty][tx] = tf32r(src[(size_t)(k0 + ty) * Nn + n0 + tx]);
    }
    __syncthreads();
    #pragma unroll
    for (int i = 0; i < 4; i++) {
        int ty = ty0 + i * 8;
        dst[(size_t)(n0 + ty) * Kn + k0 + tx] = t[tx][ty];
    }
}

// ---------------- LayerNorm (tf32-rounded out) ----------------
__global__ void ln_kernel(const float* __restrict__ x, const float* __restrict__ g,
                          const float* __restrict__ bta, float* __restrict__ out)
{
    __shared__ float sx[CDIM];
    __shared__ float red[8];
    int row = blockIdx.x, tid = threadIdx.x;
    const float* xr = x + (size_t)row * CDIM;
    float s = 0.f;
    for (int i = tid; i < CDIM; i += 256) { float v = xr[i]; sx[i] = v; s += v; }
    #pragma unroll
    for (int o = 16; o; o >>= 1) s += __shfl_xor_sync(0xffffffffu, s, o);
    if ((tid & 31) == 0) red[tid >> 5] = s;
    __syncthreads();
    float tot = 0.f;
    #pragma unroll
    for (int w = 0; w < 8; w++) tot += red[w];
    float mean = tot * (1.0f / (float)CDIM);
    float vs = 0.f;
    for (int i = tid; i < CDIM; i += 256) { float d = sx[i] - mean; vs += d * d; }
    __syncthreads();
    #pragma unroll
    for (int o = 16; o; o >>= 1) vs += __shfl_xor_sync(0xffffffffu, vs, o);
    if ((tid & 31) == 0) red[tid >> 5] = vs;
    __syncthreads();
    float tot2 = 0.f;
    #pragma unroll
    for (int w = 0; w < 8; w++) tot2 += red[w];
    float rstd = rsqrtf(tot2 * (1.0f / (float)CDIM) + 1e-5f);
    for (int i = tid; i < CDIM; i += 256)
        out[(size_t)row * CDIM + i] = tf32r((sx[i] - mean) * rstd * g[i] + bta[i]);
}

// ============ TF32 GEMM: B transposed [N][K]; both operands via ldmatrix ============
// block 128m x 128n, ktile 16, cp.async 3-stage, one barrier per ktile.
template<bool HAS_BIAS, bool HAS_RES, bool DO_AMAX>
__global__ void __launch_bounds__(256, 2) tgemm_kernel(
    const float* __restrict__ A, const float* __restrict__ Bt, float* __restrict__ Cm,
    int Mn, int Nn, int Kn,
    const float* __restrict__ bias, const float* __restrict__ res, unsigned* amax)
{
    constexpr int ST = 3;
    constexpr uint32_t TBYTES = 128 * 20 * 4;   // per stage, each of A and B
    __shared__ __align__(16) uint32_t As[ST][128][20];
    __shared__ __align__(16) uint32_t Bs[ST][128][20];
    __shared__ float reds[8];

    int tid  = threadIdx.x;
    int lane = tid & 31;
    int warp = tid >> 5;
    int wm = warp & 1;   // 2 M groups of 64
    int wn = warp >> 1;  // 4 N groups of 32
    int nBase = blockIdx.x * 128;
    int mBase = blockIdx.y * 128;

    uint32_t asmb = (uint32_t)__cvta_generic_to_shared(&As[0][0][0]);
    uint32_t bsmb = (uint32_t)__cvta_generic_to_shared(&Bs[0][0][0]);

    const int ldR = tid >> 2;          // row 0..63 (+64)
    const int ldC = (tid & 3) << 2;    // word col 0/4/8/12

    int r8 = lane & 7, sel = lane >> 3;
    // A frag addr: m0 rows r8 (+8 if sel&1), words +4 if sel>>1
    uint32_t aoff = asmb + (((wm * 64 + r8 + ((sel & 1) << 3)) * 20 + ((sel >> 1) << 2)) << 2);
    // B frag addr: ntpair rows r8 (+8 if sel&1 -> next ntile), words +4 if sel>>1 (b1)
    uint32_t boff = bsmb + (((wn * 32 + r8 + ((sel & 1) << 3)) * 20 + ((sel >> 1) << 2)) << 2);

    float acc[4][4][4];
    #pragma unroll
    for (int i = 0; i < 4; i++)
        #pragma unroll
        for (int j = 0; j < 4; j++)
            #pragma unroll
            for (int l = 0; l < 4; l++) acc[i][j][l] = 0.f;

    int KT = Kn >> 4;

    auto issue_stage = [&](int s, int k0) {
        #pragma unroll
        for (int i = 0; i < 2; i++) {
            int r = ldR + i * 64;
            int gr = mBase + r;
            int ok = (gr < Mn);
            const float* srcA = A + (size_t)(ok ? gr : 0) * Kn + k0 + ldC;
            cp_async16(asmb + s * TBYTES + ((r * 20 + ldC) << 2), srcA, ok ? 16 : 0);
            const float* srcB = Bt + (size_t)(nBase + r) * Kn + k0 + ldC;
            cp_async16(bsmb + s * TBYTES + ((r * 20 + ldC) << 2), srcB, 16);
        }
        asm volatile("cp.async.commit_group;" ::: "memory");
    };

    issue_stage(0, 0);
    issue_stage(1, 16);

    int lr = lane >> 2, lc = lane & 3;
    for (int kt = 0; kt < KT; ++kt) {
        int buf = kt % ST;
        asm volatile("cp.async.wait_group 1;" ::: "memory");
        __syncthreads();
        if (kt + 2 < KT) issue_stage((kt + 2) % ST, (kt + 2) << 4);
        else asm volatile("cp.async.commit_group;" ::: "memory");

        uint32_t abuf = aoff + buf * TBYTES;
        uint32_t bbuf = boff + buf * TBYTES;
        #pragma unroll
        for (int ks = 0; ks < 2; ks++) {
            uint32_t af[4][4], bf[4][2];
            #pragma unroll
            for (int mt = 0; mt < 4; mt++)
                ldsm4(af[mt][0], af[mt][1], af[mt][2], af[mt][3],
                      abuf + mt * (16 * 20 * 4) + ks * 32);
            #pragma unroll
            for (int np = 0; np < 2; np++)
                ldsm4(bf[np*2][0], bf[np*2+1][0], bf[np*2][1], bf[np*2+1][1],
                      bbuf + np * (16 * 20 * 4) + ks * 32);
            #pragma unroll
            for (int mt = 0; mt < 4; mt++)
                #pragma unroll
                for (int nt = 0; nt < 4; nt++)
                    mma_tf32(acc[mt][nt], af[mt], bf[nt]);
        }
    }

    float amx = 0.f;
    #pragma unroll
    for (int mt = 0; mt < 4; mt++) {
        #pragma unroll
        for (int nt = 0; nt < 4; nt++) {
            int row0 = mBase + wm * 64 + mt * 16 + lr;
            int col0 = nBase + wn * 32 + nt * 8 + lc * 2;
            #pragma unroll
            for (int half = 0; half < 2; half++) {
                int row = row0 + half * 8;
                if (row < Mn) {
                    float c0 = acc[mt][nt][half * 2 + 0];
                    float c1 = acc[mt][nt][half * 2 + 1];
                    if (HAS_BIAS) { c0 += bias[col0]; c1 += bias[col0 + 1]; }
                    if (HAS_RES) {
                        c0 += res[(size_t)row * Nn + col0];
                        c1 += res[(size_t)row * Nn + col0 + 1];
                    }
                    float2 o = {c0, c1};
                    *(float2*)(Cm + (size_t)row * Nn + col0) = o;
                    if (DO_AMAX) amx = fmaxf(amx, fmaxf(fabsf(c0), fabsf(c1)));
                }
            }
        }
    }
    if (DO_AMAX) {
        #pragma unroll
        for (int o = 16; o; o >>= 1) amx = fmaxf(amx, __shfl_xor_sync(0xffffffffu, amx, o));
        if (lane == 0) reds[warp] = amx;
        __syncthreads();
        if (tid == 0) {
            float m = reds[0];
            #pragma unroll
            for (int w = 1; w < 8; w++) m = fmaxf(m, reds[w]);
            atomicMax(amax, __float_as_uint(m));
        }
    }
}

// -------- fp32 fake-quant in place (cross path) --------
__global__ void quant_sym_kernel(float* __restrict__ x, long long n4,
                                 const unsigned* __restrict__ amaxbits)
{
    float delta = fmaxf(__uint_as_float(*amaxbits), 1e-8f) / 127.0f;
    long long stride = (long long)gridDim.x * blockDim.x;
    for (long long i = (long long)blockIdx.x * blockDim.x + threadIdx.x; i < n4; i += stride) {
        float4 v = *(float4*)(x + i * 4);
        float l;
        l = rintf(v.x/delta); l = fminf(fmaxf(l,-128.f),127.f); v.x = l*delta;
        l = rintf(v.y/delta); l = fminf(fmaxf(l,-128.f),127.f); v.y = l*delta;
        l = rintf(v.z/delta); l = fminf(fmaxf(l,-128.f),127.f); v.z = l*delta;
        l = rintf(v.w/delta); l = fminf(fmaxf(l,-128.f),127.f); v.w = l*delta;
        *(float4*)(x + i * 4) = v;
    }
}

// -------- s8 level quant --------
__global__ void quant_s8_kernel(const float* __restrict__ x, int8_t* __restrict__ L,
                                long long n16, const unsigned* __restrict__ amaxbits)
{
    float delta = fmaxf(__uint_as_float(*amaxbits), 1e-8f) / 127.0f;
    float inv = 1.0f / delta;
    long long stride = (long long)gridDim.x * blockDim.x;
    for (long long i = (long long)blockIdx.x * blockDim.x + threadIdx.x; i < n16; i += stride) {
        const float4* p = (const float4*)(x + i * 16);
        uint4 o;
        o.x = pack_s8x4(p[0], inv);
        o.y = pack_s8x4(p[1], inv);
        o.z = pack_s8x4(p[2], inv);
        o.w = pack_s8x4(p[3], inv);
        *(uint4*)(L + i * 16) = o;
    }
}

// -------- V quant + per-head transpose --------
__global__ void __launch_bounds__(256) quant_v_t_kernel(const float* __restrict__ V,
                                                        int8_t* __restrict__ LVT,
                                                        const unsigned* __restrict__ amaxbits)
{
    __shared__ int8_t T[64][80];
    float delta = fmaxf(__uint_as_float(*amaxbits), 1e-8f) / 127.0f;
    float inv = 1.0f / delta;
    int tid = threadIdx.x;
    int bh = blockIdx.y, b = bh / NH, h = bh % NH;
    int m0 = blockIdx.x * 64;
    #pragma unroll
    for (int i = 0; i < 4; i++) {
        int lin = tid + i * 256;
        int r = lin >> 4;
        int c4 = (lin & 15) << 2;
        float4 v = *(const float4*)(V + ((size_t)(b*NSEQ + m0 + r))*CDIM + h*DH + c4);
        T[c4+0][r] = (int8_t)clamp_i(__float2int_rn(v.x*inv), -128, 127);
        T[c4+1][r] = (int8_t)clamp_i(__float2int_rn(v.y*inv), -128, 127);
        T[c4+2][r] = (int8_t)clamp_i(__float2int_rn(v.z*inv), -128, 127);
        T[c4+3][r] = (int8_t)clamp_i(__float2int_rn(v.w*inv), -128, 127);
    }
    __syncthreads();
    int d = tid >> 2, ch = (tid & 3) << 4;
    int4 val = *(int4*)&T[d][ch];
    *(int4*)(LVT + ((size_t)(bh*DH + d))*NSEQ + m0 + ch) = val;
}

// ======== self-attn scores, int8 tensor cores ========
__global__ void __launch_bounds__(256) self_scores_i8_kernel(
    const int8_t* __restrict__ LQ, const int8_t* __restrict__ LK,
    float* __restrict__ S, const unsigned* __restrict__ am)
{
    __shared__ __align__(16) int8_t Qs[128][80];
    __shared__ __align__(16) int8_t Ks[128][80];
    float dq = fmaxf(__uint_as_float(am[0]), 1e-8f) / 127.0f;
    float dk = fmaxf(__uint_as_float(am[1]), 1e-8f) / 127.0f;
    float scale = dq * dk * 0.125f;
    int tid = threadIdx.x, lane = tid & 31, warp = tid >> 5;
    int bh = blockIdx.z, b = bh / NH, h = bh % NH;
    int n0 = blockIdx.x * 128, m0 = blockIdx.y * 128;

    #pragma unroll
    for (int i = 0; i < 2; i++) {
        int lin = tid + i * 256;
        int r = lin >> 2, ch = (lin & 3) << 4;
        *(int4*)&Qs[r][ch] = *(const int4*)(LQ + ((size_t)(b*NSEQ + n0 + r))*CDIM + h*DH + ch);
        *(int4*)&Ks[r][ch] = *(const int4*)(LK + ((size_t)(b*NSEQ + m0 + r))*CDIM + h*DH + ch);
    }
    __syncthreads();

    int wn = warp & 1, wm = warp >> 1;
    int gr = lane >> 2, gc = lane & 3;
    int acc[4][4][4];
    #pragma unroll
    for (int i = 0; i < 4; i++)
        #pragma unroll
        for (int j = 0; j < 4; j++)
            #pragma unroll
            for (int l = 0; l < 4; l++) acc[i][j][l] = 0;

    #pragma unroll
    for (int ks = 0; ks < 2; ks++) {
        uint32_t af[4][4], bf[4][2];
        #pragma unroll
        for (int nt = 0; nt < 4; nt++) {
            int row = wn * 64 + nt * 16 + gr;
            af[nt][0] = *(const uint32_t*)&Qs[row][ks*32 + gc*4];
            af[nt][1] = *(const uint32_t*)&Qs[row + 8][ks*32 + gc*4];
            af[nt][2] = *(const uint32_t*)&Qs[row][ks*32 + 16 + gc*4];
            af[nt][3] = *(const uint32_t*)&Qs[row + 8][ks*32 + 16 + gc*4];
        }
        #pragma unroll
        for (int mt = 0; mt < 4; mt++) {
            int col = wm * 32 + mt * 8 + gr;
            bf[mt][0] = *(const uint32_t*)&Ks[col][ks*32 + gc*4];
            bf[mt][1] = *(const uint32_t*)&Ks[col][ks*32 + 16 + gc*4];
        }
        #pragma unroll
        for (int nt = 0; nt < 4; nt++)
            #pragma unroll
            for (int mt = 0; mt < 4; mt++)
                mma_s8(acc[nt][mt], af[nt], bf[mt]);
    }

    #pragma unroll
    for (int nt = 0; nt < 4; nt++) {
        #pragma unroll
        for (int mt = 0; mt < 4; mt++) {
            int row0 = n0 + wn * 64 + nt * 16 + gr;
            int col0 = m0 + wm * 32 + mt * 8 + gc * 2;
            #pragma unroll
            for (int half = 0; half < 2; half++) {
                int row = row0 + half * 8;
                float2 o = {scale * (float)acc[nt][mt][half*2+0],
                            scale * (float)acc[nt][mt][half*2+1]};
                *(float2*)(S + ((size_t)bh*NSEQ + row)*NSEQ + col0) = o;
            }
        }
    }
}

// -------- softmax row stats --------
__global__ void softmax_stats_kernel(const float* __restrict__ S, float* __restrict__ rowmax,
                                     float* __restrict__ rowz, unsigned* wmax, int cols, int stride)
{
    int row = blockIdx.x, tid = threadIdx.x;
    const float* s = S + (size_t)row * stride;
    __shared__ float red[8];
    float m = -3.4e38f;
    for (int i = tid; i < cols; i += 256) m = fmaxf(m, s[i]);
    #pragma unroll
    for (int o = 16; o; o >>= 1) m = fmaxf(m, __shfl_xor_sync(0xffffffffu, m, o));
    if ((tid & 31) == 0) red[tid >> 5] = m;
    __syncthreads();
    float mm = red[0];
    #pragma unroll
    for (int w = 1; w < 8; w++) mm = fmaxf(mm, red[w]);
    __syncthreads();
    float z = 0.f;
    for (int i = tid; i < cols; i += 256) z += __expf(s[i] - mm);
    #pragma unroll
    for (int o = 16; o; o >>= 1) z += __shfl_xor_sync(0xffffffffu, z, o);
    if ((tid & 31) == 0) red[tid >> 5] = z;
    __syncthreads();
    if (tid == 0) {
        float zz = 0.f;
        #pragma unroll
        for (int w = 0; w < 8; w++) zz += red[w];
        rowmax[row] = mm; rowz[row] = zz;
        atomicMax(wmax, __float_as_uint(1.0f / zz));
    }
}

// ======== self-attn PV, u8 x s8 tensor cores ========
__global__ void __launch_bounds__(256) self_pv_i8_kernel(
    const float* __restrict__ S, const int8_t* __restrict__ LVT,
    const float* __restrict__ RM, const float* __restrict__ RZ,
    const unsigned* __restrict__ am, float* __restrict__ O)
{
    __shared__ __align__(16) uint8_t Lws[128][144];
    __shared__ __align__(16) int8_t  VTs[64][144];
    __shared__ float rmS[128], riS[128];
    float dv = fmaxf(__uint_as_float(am[2]), 1e-8f) / 127.0f;
    float dw = fmaxf(__uint_as_float(am[3]), 1e-8f) / 255.0f;
    float inv_dw = 1.0f / dw;
    float oscale = dw * dv;
    int tid = threadIdx.x, lane = tid & 31, warp = tid >> 5;
    int bh = blockIdx.y, b = bh / NH, h = bh % NH;
    int n0 = blockIdx.x * 128;
    if (tid < 128) {
        rmS[tid] = RM[(size_t)bh*NSEQ + n0 + tid];
        riS[tid] = 1.0f / RZ[(size_t)bh*NSEQ + n0 + tid];
    }
    int wn = warp & 1, wd = warp >> 1;
    int gr = lane >> 2, gc = lane & 3;
    int acc[4][2][4];
    #pragma unroll
    for (int i = 0; i < 4; i++)
        #pragma unroll
        for (int j = 0; j < 2; j++)
            #pragma unroll
            for (int l = 0; l < 4; l++) acc[i][j][l] = 0;

    for (int mc = 0; mc < 8; mc++) {
        __syncthreads();
        #pragma unroll
        for (int i = 0; i < 16; i++) {
            int lin = tid + i * 256;
            int n = lin >> 5, w = lin & 31;
            float4 sv = *(const float4*)(S + ((size_t)bh*NSEQ + n0 + n)*NSEQ + mc*128 + w*4);
            float rm = rmS[n];
            float f = riS[n] * inv_dw;
            int l0 = min(255, __float2int_rn(__expf(sv.x - rm) * f));
            int l1 = min(255, __float2int_rn(__expf(sv.y - rm) * f));
            int l2 = min(255, __float2int_rn(__expf(sv.z - rm) * f));
            int l3 = min(255, __float2int_rn(__expf(sv.w - rm) * f));
            *(uint32_t*)&Lws[n][w*4] = (uint32_t)l0 | ((uint32_t)l1 << 8)
                                     | ((uint32_t)l2 << 16) | ((uint32_t)l3 << 24);
        }
        #pragma unroll
        for (int i = 0; i < 2; i++) {
            int lin = tid + i * 256;
            int d = lin >> 3, ch = (lin & 7) << 4;
            *(int4*)&VTs[d][ch] = *(const int4*)(LVT + ((size_t)(bh*DH + d))*NSEQ + mc*128 + ch);
        }
        __syncthreads();
        #pragma unroll
        for (int ks = 0; ks < 4; ks++) {
            uint32_t af[4][4], bf[2][2];
            #pragma unroll
            for (int nt = 0; nt < 4; nt++) {
                int row = wn * 64 + nt * 16 + gr;
                af[nt][0] = *(const uint32_t*)&Lws[row][ks*32 + gc*4];
                af[nt][1] = *(const uint32_t*)&Lws[row + 8][ks*32 + gc*4];
                af[nt][2] = *(const uint32_t*)&Lws[row][ks*32 + 16 + gc*4];
                af[nt][3] = *(const uint32_t*)&Lws[row + 8][ks*32 + 16 + gc*4];
            }
            #pragma unroll
            for (int dt = 0; dt < 2; dt++) {
                int col = wd * 16 + dt * 8 + gr;
                bf[dt][0] = *(const uint32_t*)&VTs[col][ks*32 + gc*4];
                bf[dt][1] = *(const uint32_t*)&VTs[col][ks*32 + 16 + gc*4];
            }
            #pragma unroll
            for (int nt = 0; nt < 4; nt++)
                #pragma unroll
                for (int dt = 0; dt < 2; dt++)
                    mma_u8s8(acc[nt][dt], af[nt], bf[dt]);
        }
    }
    #pragma unroll
    for (int nt = 0; nt < 4; nt++) {
        #pragma unroll
        for (int dt = 0; dt < 2; dt++) {
            int row0 = n0 + wn * 64 + nt * 16 + gr;
            int col0 = wd * 16 + dt * 8 + gc * 2;
            #pragma unroll
            for (int half = 0; half < 2; half++) {
                int row = row0 + half * 8;
                float2 o = {tf32r(oscale * (float)acc[nt][dt][half*2+0]),
                            tf32r(oscale * (float)acc[nt][dt][half*2+1])};
                *(float2*)(O + ((size_t)(b*NSEQ + row))*CDIM + h*DH + col0) = o;
            }
        }
    }
}

// -------- cross-attn scores (fp32, M=77, stride 80) --------
__global__ void __launch_bounds__(256) cross_scores_kernel(
    const float* __restrict__ q, const float* __restrict__ k, float* __restrict__ S)
{
    __shared__ __align__(16) float Qs[64][68];
    __shared__ __align__(16) float Ks[80][68];
    int tid = threadIdx.x;
    int bh = blockIdx.y, b = bh / NH, h = bh % NH;
    int n0 = blockIdx.x * 64;
    #pragma unroll
    for (int it = 0; it < 4; ++it) {
        int r = (tid >> 4) + it * 16, c = (tid & 15) << 2;
        float4 qv = *(const float4*)(q + ((size_t)(b*NSEQ + n0 + r))*CDIM + h*DH + c);
        Qs[c+0][r]=qv.x; Qs[c+1][r]=qv.y; Qs[c+2][r]=qv.z; Qs[c+3][r]=qv.w;
    }
    #pragma unroll
    for (int it = 0; it < 5; ++it) {
        int lin = tid + it * 256;
        if (lin < 80 * 16) {
            int r = lin >> 4, c = (lin & 15) << 2;
            float4 kv = (r < MCTX) ? *(const float4*)(k + ((size_t)(b*MCTX + r))*CDIM + h*DH + c)
                                   : make_float4(0.f,0.f,0.f,0.f);
            *(float4*)&Ks[r][c] = kv;
        }
    }
    __syncthreads();
    int tx = tid & 15, ty = tid >> 4;
    float acc[4][5];
    #pragma unroll
    for (int i = 0; i < 4; i++)
        #pragma unroll
        for (int j = 0; j < 5; j++) acc[i][j] = 0.f;
    #pragma unroll 4
    for (int d = 0; d < 64; ++d) {
        float4 q4 = *(const float4*)&Qs[d][ty*4];
        float qa[4]={q4.x,q4.y,q4.z,q4.w};
        #pragma unroll
        for (int jj = 0; jj < 5; jj++) {
            float kv = Ks[tx*5+jj][d];
            #pragma unroll
            for (int i = 0; i < 4; i++) acc[i][jj] = fmaf(qa[i], kv, acc[i][jj]);
        }
    }
    #pragma unroll
    for (int i = 0; i < 4; i++)
        #pragma unroll
        for (int jj = 0; jj < 5; jj++) {
            int m = tx * 5 + jj;
            if (m < MCTX)
                S[((size_t)bh*NSEQ + n0 + ty*4 + i)*80 + m] = acc[i][jj] * 0.125f;
        }
}

// -------- cross-attn PV (fp32) --------
__global__ void __launch_bounds__(256) cross_pv_kernel(
    const float* __restrict__ S, const float* __restrict__ v,
    const float* __restrict__ rowmax, const float* __restrict__ rowz,
    const unsigned* __restrict__ wmaxbits, float* __restrict__ O)
{
    __shared__ __align__(16) float Ws[80][68];
    __shared__ __align__(16) float Vs[80][68];
    int tid = threadIdx.x;
    int bh = blockIdx.y, b = bh / NH, h = bh % NH;
    int n0 = blockIdx.x * 64;
    int tx = tid & 15, ty = tid >> 4;
    float delta = fmaxf(__uint_as_float(*wmaxbits), 1e-8f) / 255.0f;
    float inv_delta = 1.0f / delta;
    #pragma unroll
    for (int it = 0; it < 5; ++it) {
        int lin = tid + it * 256;
        if (lin < MCTX * 16) {
            int r = lin >> 4, c = (lin & 15) << 2;
            *(float4*)&Vs[r][c] = *(const float4*)(v + ((size_t)(b*MCTX + r))*CDIM + h*DH + c);
        }
    }
    #pragma unroll
    for (int it = 0; it < 4; ++it) {
        int r = (tid >> 4) + it * 16;
        float rm = rowmax[(size_t)bh*NSEQ + n0 + r];
        float ri = 1.0f / rowz[(size_t)bh*NSEQ + n0 + r];
        #pragma unroll
        for (int jj = 0; jj < 5; jj++) {
            int m = (tid & 15) * 5 + jj;
            float w = 0.f;
            if (m < MCTX) {
                float s = S[((size_t)bh*NSEQ + n0 + r)*80 + m];
                float p = __expf(s - rm);
                float l = rintf(p * ri * inv_delta);
                l = fminf(fmaxf(l, 0.f), 255.f);
                w = l * delta;
            }
            Ws[m][r] = w;
        }
    }
    __syncthreads();
    float acc[4][4];
    #pragma unroll
    for (int i = 0; i < 4; i++)
        #pragma unroll
        for (int j = 0; j < 4; j++) acc[i][j] = 0.f;
    for (int m = 0; m < MCTX; m++) {
        float4 w4 = *(const float4*)&Ws[m][ty*4];
        float4 v4 = *(const float4*)&Vs[m][tx*4];
        float wa[4]={w4.x,w4.y,w4.z,w4.w}, va[4]={v4.x,v4.y,v4.z,v4.w};
        #pragma unroll
        for (int i = 0; i < 4; i++)
            #pragma unroll
            for (int j = 0; j < 4; j++) acc[i][j] = fmaf(wa[i], va[j], acc[i][j]);
    }
    #pragma unroll
    for (int i = 0; i < 4; i++) {
        float4 o = {tf32r(acc[i][0]), tf32r(acc[i][1]), tf32r(acc[i][2]), tf32r(acc[i][3])};
        *(float4*)(O + ((size_t)(b*NSEQ + n0 + ty*4 + i))*CDIM + h*DH + tx*4) = o;
    }
}

// -------- GEGLU (tf32-rounded out) --------
__global__ void geglu_kernel(const float* __restrict__ Hh, float* __restrict__ G)
{
    size_t n4 = (size_t)ROWS * FFD / 4;
    size_t stride = (size_t)gridDim.x * blockDim.x;
    for (size_t i = (size_t)blockIdx.x * blockDim.x + threadIdx.x; i < n4; i += stride) {
        size_t col4 = i % (FFD / 4), row = i / (FFD / 4);
        float4 a4 = *(const float4*)(Hh + row * FF2D + col4 * 4);
        float4 g4 = *(const float4*)(Hh + row * FF2D + FFD + col4 * 4);
        float4 o;
        o.x = tf32r(a4.x * gelu_tanh(g4.x)); o.y = tf32r(a4.y * gelu_tanh(g4.y));
        o.z = tf32r(a4.z * gelu_tanh(g4.z)); o.w = tf32r(a4.w * gelu_tanh(g4.w));
        *(float4*)(G + i * 4) = o;
    }
}

extern "C" void kernel_launch(void* const* d_in, const int* in_sizes, int n_in,
                              void* d_out, int out_size)
{
    const float* x    = (const float*)d_in[0];
    const float* ctx  = (const float*)d_in[1];
    const float* ln1g = (const float*)d_in[2];
    const float* ln1b = (const float*)d_in[3];
    const float* ln2g = (const float*)d_in[4];
    const float* ln2b = (const float*)d_in[5];
    const float* ln3g = (const float*)d_in[6];
    const float* ln3b = (const float*)d_in[7];
    const float* Wq1  = (const float*)d_in[8];
    const float* Wk1  = (const float*)d_in[9];
    const float* Wv1  = (const float*)d_in[10];
    const float* Wo1  = (const float*)d_in[11];
    const float* bo1  = (const float*)d_in[12];
    const float* Wq2  = (const float*)d_in[13];
    const float* Wk2  = (const float*)d_in[14];
    const float* Wv2  = (const float*)d_in[15];
    const float* Wo2  = (const float*)d_in[16];
    const float* bo2  = (const float*)d_in[17];
    const float* Wff1 = (const float*)d_in[18];
    const float* bff1 = (const float*)d_in[19];
    const float* Wff2 = (const float*)d_in[20];
    const float* bff2 = (const float*)d_in[21];
    float* out = (float*)d_out;

    float* sc = nullptr;
    cudaGetSymbolAddress((void**)&sc, g_scratch);
    float* XN = sc + OFF_XN;  float* Q  = sc + OFF_Q;
    float* K  = sc + OFF_K;   float* V  = sc + OFF_V;
    float* O  = sc + OFF_O;   float* X1 = sc + OFF_X1;
    float* S  = sc + OFF_S;   float* Hb = sc + OFF_H;
    float* G  = sc + OFF_G;   float* RM = sc + OFF_RM;
    float* RZ = sc + OFF_RZ;
    unsigned* AM = (unsigned*)(sc + OFF_AM);
    float* cWq1 = sc + OFF_WQ1; float* cWk1 = sc + OFF_WK1;
    float* cWv1 = sc + OFF_WV1; float* cWo1 = sc + OFF_WO1;
    float* cWq2 = sc + OFF_WQ2; float* cWo2 = sc + OFF_WO2;
    float* cWk2 = sc + OFF_WK2; float* cWv2 = sc + OFF_WV2;
    float* cWf1 = sc + OFF_WF1; float* cWf2 = sc + OFF_WF2;
    float* cCtx = sc + OFF_CTX;
    int8_t* LQ8 = (int8_t*)(sc + OFF_LQ8);
    int8_t* LK8 = (int8_t*)(sc + OFF_LK8);
    int8_t* LVT = (int8_t*)(sc + OFF_LVT);

    dim3 g1280(CDIM / 128, ROWS / 128);
    dim3 gcross(CDIM / 128, (CROSSROWS + 127) / 128);
    dim3 gff1(FF2D / 128, ROWS / 128);
    long long n4  = (long long)ROWS * CDIM / 4;
    long long n16 = (long long)ROWS * CDIM / 16;
    long long n4c = (long long)CROSSROWS * CDIM / 4;

    init_amax_kernel<<<1, 32>>>(AM);

    // ---- pre-convert: weights -> tf32 TRANSPOSED [N][K]; ctx -> tf32 copy ----
    dim3 t1280(CDIM/32, CDIM/32);
    trans_tf32_kernel<<<t1280,256>>>(Wq1,  cWq1, CDIM, CDIM);
    trans_tf32_kernel<<<t1280,256>>>(Wk1,  cWk1, CDIM, CDIM);
    trans_tf32_kernel<<<t1280,256>>>(Wv1,  cWv1, CDIM, CDIM);
    trans_tf32_kernel<<<t1280,256>>>(Wo1,  cWo1, CDIM, CDIM);
    trans_tf32_kernel<<<t1280,256>>>(Wq2,  cWq2, CDIM, CDIM);
    trans_tf32_kernel<<<t1280,256>>>(Wo2,  cWo2, CDIM, CDIM);
    trans_tf32_kernel<<<dim3(CDIM/32, CTXC/32),256>>>(Wk2, cWk2, CTXC, CDIM);
    trans_tf32_kernel<<<dim3(CDIM/32, CTXC/32),256>>>(Wv2, cWv2, CTXC, CDIM);
    trans_tf32_kernel<<<dim3(FF2D/32, CDIM/32),256>>>(Wff1, cWf1, CDIM, FF2D);
    trans_tf32_kernel<<<dim3(CDIM/32, FFD/32),256>>>(Wff2, cWf2, FFD, CDIM);
    conv_tf32_kernel<<<512,256>>>(ctx, cCtx, (long long)SZ_CTXB/4);

    // ---- block 1: self attention (int8 tensor-core path) ----
    ln_kernel<<<ROWS, 256>>>(x, ln1g, ln1b, XN);
    tgemm_kernel<false,false,true><<<g1280,256>>>(XN, cWq1, Q, ROWS, CDIM, CDIM, nullptr, nullptr, AM+0);
    tgemm_kernel<false,false,true><<<g1280,256>>>(XN, cWk1, K, ROWS, CDIM, CDIM, nullptr, nullptr, AM+1);
    tgemm_kernel<false,false,true><<<g1280,256>>>(XN, cWv1, V, ROWS, CDIM, CDIM, nullptr, nullptr, AM+2);
    quant_s8_kernel<<<1024,256>>>(Q, LQ8, n16, AM+0);
    quant_s8_kernel<<<1024,256>>>(K, LK8, n16, AM+1);
    quant_v_t_kernel<<<dim3(NSEQ/64, BHD),256>>>(V, LVT, AM+2);
    self_scores_i8_kernel<<<dim3(8,8,BHD),256>>>(LQ8, LK8, S, AM);
    softmax_stats_kernel<<<BHD*NSEQ,256>>>(S, RM, RZ, AM+3, NSEQ, NSEQ);
    self_pv_i8_kernel<<<dim3(8,BHD),256>>>(S, LVT, RM, RZ, AM, O);
    tgemm_kernel<true,true,false><<<g1280,256>>>(O, cWo1, X1, ROWS, CDIM, CDIM, bo1, x, nullptr);

    // ---- block 2: cross attention (fp32 path, small) ----
    ln_kernel<<<ROWS,256>>>(X1, ln2g, ln2b, XN);
    tgemm_kernel<false,false,true><<<g1280,256>>>(XN, cWq2, Q, ROWS, CDIM, CDIM, nullptr, nullptr, AM+4);
    tgemm_kernel<false,false,true><<<gcross,256>>>(cCtx, cWk2, K, CROSSROWS, CDIM, CTXC, nullptr, nullptr, AM+5);
    tgemm_kernel<false,false,true><<<gcross,256>>>(cCtx, cWv2, V, CROSSROWS, CDIM, CTXC, nullptr, nullptr, AM+6);
    quant_sym_kernel<<<2048,256>>>(Q, n4, AM+4);
    quant_sym_kernel<<<512,256>>>(K, n4c, AM+5);
    quant_sym_kernel<<<512,256>>>(V, n4c, AM+6);
    cross_scores_kernel<<<dim3(16,BHD),256>>>(Q, K, S);
    softmax_stats_kernel<<<BHD*NSEQ,256>>>(S, RM, RZ, AM+7, MCTX, 80);
    cross_pv_kernel<<<dim3(16,BHD),256>>>(S, V, RM, RZ, AM+7, O);
    tgemm_kernel<true,true,false><<<g1280,256>>>(O, cWo2, X1, ROWS, CDIM, CDIM, bo2, X1, nullptr);

    // ---- block 3: GEGLU FF ----
    ln_kernel<<<ROWS,256>>>(X1, ln3g, ln3b, XN);
    tgemm_kernel<true,false,false><<<gff1,256>>>(XN, cWf1, Hb, ROWS, FF2D, CDIM, bff1, nullptr, nullptr);
    geglu_kernel<<<4096,256>>>(Hb, G);
    tgemm_kernel<true,true,false><<<g1280,256>>>(G, cWf2, out, ROWS, CDIM, FFD, bff2, X1, nullptr);
}

// round 9
// speedup vs baseline: 1.1755x; 1.1755x over previous
#include <cuda_runtime.h>
#include <cstdint>

#define NB 8
#define NSEQ 1024
#define CDIM 1280
#define NH 20
#define DH 64
#define MCTX 77
#define CTXC 768
#define FFD 5120
#define FF2D 10240
#define ROWS (NB*NSEQ)
#define BHD (NB*NH)
#define CROSSROWS (NB*MCTX)
#define QKVN 3840
#define KV2N 2560

static constexpr size_t SZ_XC = (size_t)ROWS * CDIM;
static constexpr size_t OFF_XN = 0;
static constexpr size_t OFF_Q  = OFF_XN + SZ_XC;     // QKV fused buffer [ROWS][3840] (3*SZ_XC)
static constexpr size_t OFF_K  = OFF_Q + SZ_XC;      // cross-phase reuse: KV2 [616][2560]
static constexpr size_t OFF_V  = OFF_K + SZ_XC;
static constexpr size_t OFF_O  = OFF_V + SZ_XC;
static constexpr size_t OFF_X1 = OFF_O + SZ_XC;
static constexpr size_t OFF_S  = OFF_X1 + SZ_XC;
static constexpr size_t SZ_S   = (size_t)BHD * NSEQ * NSEQ;
static constexpr size_t OFF_H  = OFF_S + SZ_S;
static constexpr size_t SZ_H   = (size_t)ROWS * FF2D;
static constexpr size_t OFF_G  = OFF_H + SZ_H;
static constexpr size_t SZ_G   = (size_t)ROWS * FFD;
static constexpr size_t OFF_RM = OFF_G + SZ_G;
static constexpr size_t OFF_RZ = OFF_RM + (size_t)BHD * NSEQ;
static constexpr size_t OFF_AM = OFF_RZ + (size_t)BHD * NSEQ;
static constexpr size_t SZ_W1  = (size_t)CDIM * CDIM;
static constexpr size_t SZ_WK2 = (size_t)CTXC * CDIM;
static constexpr size_t SZ_WF1 = (size_t)CDIM * FF2D;
static constexpr size_t SZ_WF2 = (size_t)FFD * CDIM;
static constexpr size_t SZ_CTXB = (size_t)CROSSROWS * CTXC;
static constexpr size_t OFF_WQKV = OFF_AM + 8;                 // [1280][3840]
static constexpr size_t OFF_WO1  = OFF_WQKV + 3 * SZ_W1;
static constexpr size_t OFF_WQ2  = OFF_WO1 + SZ_W1;
static constexpr size_t OFF_WO2  = OFF_WQ2 + SZ_W1;
static constexpr size_t OFF_WKV2 = OFF_WO2 + SZ_W1;            // [768][2560]
static constexpr size_t OFF_WF1  = OFF_WKV2 + 2 * SZ_WK2;
static constexpr size_t OFF_WF2  = OFF_WF1 + SZ_WF1;
static constexpr size_t OFF_CTX  = OFF_WF2 + SZ_WF2;
static constexpr size_t SZ_S8F   = (size_t)ROWS * CDIM / 4;
static constexpr size_t OFF_LQ8  = OFF_CTX + SZ_CTXB;
static constexpr size_t OFF_LK8  = OFF_LQ8 + SZ_S8F;
static constexpr size_t OFF_LVT  = OFF_LK8 + SZ_S8F;
static constexpr size_t TOTAL_SCRATCH = OFF_LVT + SZ_S8F;

__device__ __align__(256) float g_scratch[TOTAL_SCRATCH];

__global__ void init_amax_kernel(unsigned* amax) {
    if (threadIdx.x < 8) amax[threadIdx.x] = 0u;
}

__device__ __forceinline__ float gelu_tanh(float x) {
    float x3 = x * x * x;
    return 0.5f * x * (1.0f + tanhf(0.7978845608028654f * (x + 0.044715f * x3)));
}

__device__ __forceinline__ uint32_t f2tf32(float f) {
    uint32_t r;
    asm("cvt.rna.tf32.f32 %0, %1;" : "=r"(r) : "f"(f));
    return r;
}
__device__ __forceinline__ float tf32r(float f) { return __uint_as_float(f2tf32(f)); }

__device__ __forceinline__ void mma_tf32(float* d, const uint32_t* a, const uint32_t* b) {
    asm volatile("mma.sync.aligned.m16n8k8.row.col.f32.tf32.tf32.f32 "
        "{%0,%1,%2,%3}, {%4,%5,%6,%7}, {%8,%9}, {%0,%1,%2,%3};"
        : "+f"(d[0]), "+f"(d[1]), "+f"(d[2]), "+f"(d[3])
        : "r"(a[0]), "r"(a[1]), "r"(a[2]), "r"(a[3]), "r"(b[0]), "r"(b[1]));
}

__device__ __forceinline__ void mma_s8(int* d, const uint32_t* a, const uint32_t* b) {
    asm volatile("mma.sync.aligned.m16n8k32.row.col.s32.s8.s8.s32 "
        "{%0,%1,%2,%3}, {%4,%5,%6,%7}, {%8,%9}, {%0,%1,%2,%3};"
        : "+r"(d[0]), "+r"(d[1]), "+r"(d[2]), "+r"(d[3])
        : "r"(a[0]), "r"(a[1]), "r"(a[2]), "r"(a[3]), "r"(b[0]), "r"(b[1]));
}

__device__ __forceinline__ void mma_u8s8(int* d, const uint32_t* a, const uint32_t* b) {
    asm volatile("mma.sync.aligned.m16n8k32.row.col.s32.u8.s8.s32 "
        "{%0,%1,%2,%3}, {%4,%5,%6,%7}, {%8,%9}, {%0,%1,%2,%3};"
        : "+r"(d[0]), "+r"(d[1]), "+r"(d[2]), "+r"(d[3])
        : "r"(a[0]), "r"(a[1]), "r"(a[2]), "r"(a[3]), "r"(b[0]), "r"(b[1]));
}

__device__ __forceinline__ void ldsm4(uint32_t& r0, uint32_t& r1, uint32_t& r2, uint32_t& r3,
                                      uint32_t addr) {
    asm volatile("ldmatrix.sync.aligned.m8n8.x4.shared.b16 {%0,%1,%2,%3}, [%4];"
        : "=r"(r0), "=r"(r1), "=r"(r2), "=r"(r3) : "r"(addr));
}

__device__ __forceinline__ void cp_async16(uint32_t dst, const void* src, int srcsize) {
    asm volatile("cp.async.cg.shared.global [%0], [%1], 16, %2;"
                 :: "r"(dst), "l"(src), "r"(srcsize));
}

__device__ __forceinline__ int clamp_i(int v, int lo, int hi) {
    return v < lo ? lo : (v > hi ? hi : v);
}

__device__ __forceinline__ uint32_t pack_s8x4(float4 v, float inv) {
    int a = clamp_i(__float2int_rn(v.x * inv), -128, 127);
    int b = clamp_i(__float2int_rn(v.y * inv), -128, 127);
    int c = clamp_i(__float2int_rn(v.z * inv), -128, 127);
    int d = clamp_i(__float2int_rn(v.w * inv), -128, 127);
    return (a & 255) | ((b & 255) << 8) | ((c & 255) << 16) | ((d & 255) << 24);
}

// -------- tf32 convert (contiguous) --------
__global__ void conv_tf32_kernel(const float* __restrict__ src, float* __restrict__ dst,
                                 long long n4)
{
    long long stride = (long long)gridDim.x * blockDim.x;
    for (long long i = (long long)blockIdx.x * blockDim.x + threadIdx.x; i < n4; i += stride) {
        float4 v = *(const float4*)(src + i * 4);
        v.x = tf32r(v.x); v.y = tf32r(v.y); v.z = tf32r(v.z); v.w = tf32r(v.w);
        *(float4*)(dst + i * 4) = v;
    }
}

// -------- tf32 convert + column-pack: src[K][N] -> dst[K][dstStride] at col offset --------
__global__ void conv_pack_kernel(const float* __restrict__ src, float* __restrict__ dst,
                                 int Kn, int Nn, int dstStride)
{
    long long n4 = (long long)Kn * Nn / 4;
    long long stride = (long long)gridDim.x * blockDim.x;
    for (long long i = (long long)blockIdx.x * blockDim.x + threadIdx.x; i < n4; i += stride) {
        long long e = i * 4;
        int row = (int)(e / Nn), col = (int)(e % Nn);
        float4 v = *(const float4*)(src + e);
        v.x = tf32r(v.x); v.y = tf32r(v.y); v.z = tf32r(v.z); v.w = tf32r(v.w);
        *(float4*)(dst + (size_t)row * dstStride + col) = v;
    }
}

// ---------------- LayerNorm (tf32-rounded out) ----------------
__global__ void ln_kernel(const float* __restrict__ x, const float* __restrict__ g,
                          const float* __restrict__ bta, float* __restrict__ out)
{
    __shared__ float sx[CDIM];
    __shared__ float red[8];
    int row = blockIdx.x, tid = threadIdx.x;
    const float* xr = x + (size_t)row * CDIM;
    float s = 0.f;
    for (int i = tid; i < CDIM; i += 256) { float v = xr[i]; sx[i] = v; s += v; }
    #pragma unroll
    for (int o = 16; o; o >>= 1) s += __shfl_xor_sync(0xffffffffu, s, o);
    if ((tid & 31) == 0) red[tid >> 5] = s;
    __syncthreads();
    float tot = 0.f;
    #pragma unroll
    for (int w = 0; w < 8; w++) tot += red[w];
    float mean = tot * (1.0f / (float)CDIM);
    float vs = 0.f;
    for (int i = tid; i < CDIM; i += 256) { float d = sx[i] - mean; vs += d * d; }
    __syncthreads();
    #pragma unroll
    for (int o = 16; o; o >>= 1) vs += __shfl_xor_sync(0xffffffffu, vs, o);
    if ((tid & 31) == 0) red[tid >> 5] = vs;
    __syncthreads();
    float tot2 = 0.f;
    #pragma unroll
    for (int w = 0; w < 8; w++) tot2 += red[w];
    float rstd = rsqrtf(tot2 * (1.0f / (float)CDIM) + 1e-5f);
    for (int i = tid; i < CDIM; i += 256)
        out[(size_t)row * CDIM + i] = tf32r((sx[i] - mean) * rstd * g[i] + bta[i]);
}

// ============ TF32 GEMM (R7-proven): B [K][N], cp.async 3-stage, 1 barrier/ktile ============
// SEG: amax slot selected per 1280-col segment (for fused QKV / KV GEMMs).
template<bool HAS_BIAS, bool HAS_RES, bool DO_AMAX, bool SEG>
__global__ void __launch_bounds__(256, 2) tgemm_kernel(
    const float* __restrict__ A, const float* __restrict__ Bm, float* __restrict__ Cm,
    int Mn, int Nn, int Kn,
    const float* __restrict__ bias, const float* __restrict__ res, unsigned* amax)
{
    constexpr int ST = 3;
    constexpr uint32_t ABYTES = 128 * 20 * 4;
    constexpr uint32_t BBYTES = 16 * 136 * 4;
    __shared__ __align__(16) uint32_t As[ST][128][20];
    __shared__ __align__(16) float    Bs[ST][16][136];
    __shared__ float reds[8];

    int tid  = threadIdx.x;
    int lane = tid & 31;
    int warp = tid >> 5;
    int wm = warp & 1;
    int wn = warp >> 1;
    int nBase = blockIdx.x * 128;
    int mBase = blockIdx.y * 128;

    uint32_t asmb = (uint32_t)__cvta_generic_to_shared(&As[0][0][0]);
    uint32_t bsmb = (uint32_t)__cvta_generic_to_shared(&Bs[0][0][0]);

    const int aR0 = tid >> 2;
    const int aC  = (tid & 3) << 2;
    const int bK0 = tid >> 5;
    const int bN  = (tid & 31) << 2;

    int r8 = lane & 7, sel = lane >> 3;
    uint32_t aoff = asmb + (((wm * 64 + r8 + ((sel & 1) << 3)) * 20 + ((sel >> 1) << 2)) << 2);

    float acc[4][4][4];
    #pragma unroll
    for (int i = 0; i < 4; i++)
        #pragma unroll
        for (int j = 0; j < 4; j++)
            #pragma unroll
            for (int l = 0; l < 4; l++) acc[i][j][l] = 0.f;

    int KT = Kn >> 4;

    auto issue_stage = [&](int s, int k0) {
        #pragma unroll
        for (int i = 0; i < 2; i++) {
            int r = aR0 + i * 64;
            int gr = mBase + r;
            int ok = (gr < Mn);
            const float* src = A + (size_t)(ok ? gr : 0) * Kn + k0 + aC;
            cp_async16(asmb + s * ABYTES + ((r * 20 + aC) << 2), src, ok ? 16 : 0);
        }
        #pragma unroll
        for (int i = 0; i < 2; i++) {
            int kr = bK0 + i * 8;
            const float* src = Bm + (size_t)(k0 + kr) * Nn + nBase + bN;
            cp_async16(bsmb + s * BBYTES + ((kr * 136 + bN) << 2), src, 16);
        }
        asm volatile("cp.async.commit_group;" ::: "memory");
    };

    issue_stage(0, 0);
    issue_stage(1, 16);

    int lr = lane >> 2, lc = lane & 3;
    for (int kt = 0; kt < KT; ++kt) {
        int buf = kt % ST;
        asm volatile("cp.async.wait_group 1;" ::: "memory");
        __syncthreads();
        if (kt + 2 < KT) issue_stage((kt + 2) % ST, (kt + 2) << 4);
        else asm volatile("cp.async.commit_group;" ::: "memory");

        uint32_t abuf = aoff + buf * ABYTES;
        #pragma unroll
        for (int ks = 0; ks < 2; ks++) {
            uint32_t af[4][4], bf[4][2];
            #pragma unroll
            for (int mt = 0; mt < 4; mt++)
                ldsm4(af[mt][0], af[mt][1], af[mt][2], af[mt][3],
                      abuf + mt * (16 * 20 * 4) + ks * 32);
            #pragma unroll
            for (int nt = 0; nt < 4; nt++) {
                int col = wn * 32 + nt * 8 + lr;
                bf[nt][0] = __float_as_uint(Bs[buf][ks * 8 + lc][col]);
                bf[nt][1] = __float_as_uint(Bs[buf][ks * 8 + lc + 4][col]);
            }
            #pragma unroll
            for (int mt = 0; mt < 4; mt++)
                #pragma unroll
                for (int nt = 0; nt < 4; nt++)
                    mma_tf32(acc[mt][nt], af[mt], bf[nt]);
        }
    }

    float amx = 0.f;
    #pragma unroll
    for (int mt = 0; mt < 4; mt++) {
        #pragma unroll
        for (int nt = 0; nt < 4; nt++) {
            int row0 = mBase + wm * 64 + mt * 16 + lr;
            int col0 = nBase + wn * 32 + nt * 8 + lc * 2;
            #pragma unroll
            for (int half = 0; half < 2; half++) {
                int row = row0 + half * 8;
                if (row < Mn) {
                    float c0 = acc[mt][nt][half * 2 + 0];
                    float c1 = acc[mt][nt][half * 2 + 1];
                    if (HAS_BIAS) { c0 += bias[col0]; c1 += bias[col0 + 1]; }
                    if (HAS_RES) {
                        c0 += res[(size_t)row * Nn + col0];
                        c1 += res[(size_t)row * Nn + col0 + 1];
                    }
                    float2 o = {c0, c1};
                    *(float2*)(Cm + (size_t)row * Nn + col0) = o;
                    if (DO_AMAX) amx = fmaxf(amx, fmaxf(fabsf(c0), fabsf(c1)));
                }
            }
        }
    }
    if (DO_AMAX) {
        #pragma unroll
        for (int o = 16; o; o >>= 1) amx = fmaxf(amx, __shfl_xor_sync(0xffffffffu, amx, o));
        if (lane == 0) reds[warp] = amx;
        __syncthreads();
        if (tid == 0) {
            float m = reds[0];
            #pragma unroll
            for (int w = 1; w < 8; w++) m = fmaxf(m, reds[w]);
            unsigned* tgt = amax + (SEG ? (nBase / 1280) : 0);
            atomicMax(tgt, __float_as_uint(m));
        }
    }
}

// -------- fp32 fake-quant in place (contiguous; cross Q) --------
__global__ void quant_sym_kernel(float* __restrict__ x, long long n4,
                                 const unsigned* __restrict__ amaxbits)
{
    float delta = fmaxf(__uint_as_float(*amaxbits), 1e-8f) / 127.0f;
    long long stride = (long long)gridDim.x * blockDim.x;
    for (long long i = (long long)blockIdx.x * blockDim.x + threadIdx.x; i < n4; i += stride) {
        float4 v = *(float4*)(x + i * 4);
        float l;
        l = rintf(v.x/delta); l = fminf(fmaxf(l,-128.f),127.f); v.x = l*delta;
        l = rintf(v.y/delta); l = fminf(fmaxf(l,-128.f),127.f); v.y = l*delta;
        l = rintf(v.z/delta); l = fminf(fmaxf(l,-128.f),127.f); v.z = l*delta;
        l = rintf(v.w/delta); l = fminf(fmaxf(l,-128.f),127.f); v.w = l*delta;
        *(float4*)(x + i * 4) = v;
    }
}

// -------- fp32 fake-quant in place, two column segments (cross K|V fused) --------
__global__ void quant_kv2_kernel(float* __restrict__ x, const unsigned* __restrict__ am)
{
    float d0 = fmaxf(__uint_as_float(am[0]), 1e-8f) / 127.0f;
    float d1 = fmaxf(__uint_as_float(am[1]), 1e-8f) / 127.0f;
    long long n4 = (long long)CROSSROWS * KV2N / 4;
    long long stride = (long long)gridDim.x * blockDim.x;
    for (long long i = (long long)blockIdx.x * blockDim.x + threadIdx.x; i < n4; i += stride) {
        int col = (int)((i * 4) % KV2N);
        float delta = (col < CDIM) ? d0 : d1;
        float4 v = *(float4*)(x + i * 4);
        float l;
        l = rintf(v.x/delta); l = fminf(fmaxf(l,-128.f),127.f); v.x = l*delta;
        l = rintf(v.y/delta); l = fminf(fmaxf(l,-128.f),127.f); v.y = l*delta;
        l = rintf(v.z/delta); l = fminf(fmaxf(l,-128.f),127.f); v.z = l*delta;
        l = rintf(v.w/delta); l = fminf(fmaxf(l,-128.f),127.f); v.w = l*delta;
        *(float4*)(x + i * 4) = v;
    }
}

// -------- s8 level quant from strided source (QKV fused buffer) --------
__global__ void quant_s8_strided(const float* __restrict__ x, int8_t* __restrict__ L,
                                 const unsigned* __restrict__ amaxbits)
{
    float delta = fmaxf(__uint_as_float(*amaxbits), 1e-8f) / 127.0f;
    float inv = 1.0f / delta;
    long long n16 = (long long)ROWS * (CDIM / 16);
    long long stride = (long long)gridDim.x * blockDim.x;
    for (long long i = (long long)blockIdx.x * blockDim.x + threadIdx.x; i < n16; i += stride) {
        int row = (int)(i / (CDIM / 16));
        int c16 = (int)(i % (CDIM / 16));
        const float4* p = (const float4*)(x + (size_t)row * QKVN + c16 * 16);
        uint4 o;
        o.x = pack_s8x4(p[0], inv);
        o.y = pack_s8x4(p[1], inv);
        o.z = pack_s8x4(p[2], inv);
        o.w = pack_s8x4(p[3], inv);
        *(uint4*)(L + i * 16) = o;
    }
}

// -------- V quant + per-head transpose (strided source) --------
__global__ void __launch_bounds__(256) quant_v_t_kernel(const float* __restrict__ V,
                                                        int8_t* __restrict__ LVT,
                                                        const unsigned* __restrict__ amaxbits)
{
    __shared__ int8_t T[64][80];
    float delta = fmaxf(__uint_as_float(*amaxbits), 1e-8f) / 127.0f;
    float inv = 1.0f / delta;
    int tid = threadIdx.x;
    int bh = blockIdx.y, b = bh / NH, h = bh % NH;
    int m0 = blockIdx.x * 64;
    #pragma unroll
    for (int i = 0; i < 4; i++) {
        int lin = tid + i * 256;
        int r = lin >> 4;
        int c4 = (lin & 15) << 2;
        float4 v = *(const float4*)(V + ((size_t)(b*NSEQ + m0 + r))*QKVN + h*DH + c4);
        T[c4+0][r] = (int8_t)clamp_i(__float2int_rn(v.x*inv), -128, 127);
        T[c4+1][r] = (int8_t)clamp_i(__float2int_rn(v.y*inv), -128, 127);
        T[c4+2][r] = (int8_t)clamp_i(__float2int_rn(v.z*inv), -128, 127);
        T[c4+3][r] = (int8_t)clamp_i(__float2int_rn(v.w*inv), -128, 127);
    }
    __syncthreads();
    int d = tid >> 2, ch = (tid & 3) << 4;
    int4 val = *(int4*)&T[d][ch];
    *(int4*)(LVT + ((size_t)(bh*DH + d))*NSEQ + m0 + ch) = val;
}

// ======== self-attn scores, int8 tensor cores ========
__global__ void __launch_bounds__(256) self_scores_i8_kernel(
    const int8_t* __restrict__ LQ, const int8_t* __restrict__ LK,
    float* __restrict__ S, const unsigned* __restrict__ am)
{
    __shared__ __align__(16) int8_t Qs[128][80];
    __shared__ __align__(16) int8_t Ks[128][80];
    float dq = fmaxf(__uint_as_float(am[0]), 1e-8f) / 127.0f;
    float dk = fmaxf(__uint_as_float(am[1]), 1e-8f) / 127.0f;
    float scale = dq * dk * 0.125f;
    int tid = threadIdx.x, lane = tid & 31, warp = tid >> 5;
    int bh = blockIdx.z, b = bh / NH, h = bh % NH;
    int n0 = blockIdx.x * 128, m0 = blockIdx.y * 128;

    #pragma unroll
    for (int i = 0; i < 2; i++) {
        int lin = tid + i * 256;
        int r = lin >> 2, ch = (lin & 3) << 4;
        *(int4*)&Qs[r][ch] = *(const int4*)(LQ + ((size_t)(b*NSEQ + n0 + r))*CDIM + h*DH + ch);
        *(int4*)&Ks[r][ch] = *(const int4*)(LK + ((size_t)(b*NSEQ + m0 + r))*CDIM + h*DH + ch);
    }
    __syncthreads();

    int wn = warp & 1, wm = warp >> 1;
    int gr = lane >> 2, gc = lane & 3;
    int acc[4][4][4];
    #pragma unroll
    for (int i = 0; i < 4; i++)
        #pragma unroll
        for (int j = 0; j < 4; j++)
            #pragma unroll
            for (int l = 0; l < 4; l++) acc[i][j][l] = 0;

    #pragma unroll
    for (int ks = 0; ks < 2; ks++) {
        uint32_t af[4][4], bf[4][2];
        #pragma unroll
        for (int nt = 0; nt < 4; nt++) {
            int row = wn * 64 + nt * 16 + gr;
            af[nt][0] = *(const uint32_t*)&Qs[row][ks*32 + gc*4];
            af[nt][1] = *(const uint32_t*)&Qs[row + 8][ks*32 + gc*4];
            af[nt][2] = *(const uint32_t*)&Qs[row][ks*32 + 16 + gc*4];
            af[nt][3] = *(const uint32_t*)&Qs[row + 8][ks*32 + 16 + gc*4];
        }
        #pragma unroll
        for (int mt = 0; mt < 4; mt++) {
            int col = wm * 32 + mt * 8 + gr;
            bf[mt][0] = *(const uint32_t*)&Ks[col][ks*32 + gc*4];
            bf[mt][1] = *(const uint32_t*)&Ks[col][ks*32 + 16 + gc*4];
        }
        #pragma unroll
        for (int nt = 0; nt < 4; nt++)
            #pragma unroll
            for (int mt = 0; mt < 4; mt++)
                mma_s8(acc[nt][mt], af[nt], bf[mt]);
    }

    #pragma unroll
    for (int nt = 0; nt < 4; nt++) {
        #pragma unroll
        for (int mt = 0; mt < 4; mt++) {
            int row0 = n0 + wn * 64 + nt * 16 + gr;
            int col0 = m0 + wm * 32 + mt * 8 + gc * 2;
            #pragma unroll
            for (int half = 0; half < 2; half++) {
                int row = row0 + half * 8;
                float2 o = {scale * (float)acc[nt][mt][half*2+0],
                            scale * (float)acc[nt][mt][half*2+1]};
                *(float2*)(S + ((size_t)bh*NSEQ + row)*NSEQ + col0) = o;
            }
        }
    }
}

// -------- softmax row stats --------
__global__ void softmax_stats_kernel(const float* __restrict__ S, float* __restrict__ rowmax,
                                     float* __restrict__ rowz, unsigned* wmax, int cols, int stride)
{
    int row = blockIdx.x, tid = threadIdx.x;
    const float* s = S + (size_t)row * stride;
    __shared__ float red[8];
    float m = -3.4e38f;
    for (int i = tid; i < cols; i += 256) m = fmaxf(m, s[i]);
    #pragma unroll
    for (int o = 16; o; o >>= 1) m = fmaxf(m, __shfl_xor_sync(0xffffffffu, m, o));
    if ((tid & 31) == 0) red[tid >> 5] = m;
    __syncthreads();
    float mm = red[0];
    #pragma unroll
    for (int w = 1; w < 8; w++) mm = fmaxf(mm, red[w]);
    __syncthreads();
    float z = 0.f;
    for (int i = tid; i < cols; i += 256) z += __expf(s[i] - mm);
    #pragma unroll
    for (int o = 16; o; o >>= 1) z += __shfl_xor_sync(0xffffffffu, z, o);
    if ((tid & 31) == 0) red[tid >> 5] = z;
    __syncthreads();
    if (tid == 0) {
        float zz = 0.f;
        #pragma unroll
        for (int w = 0; w < 8; w++) zz += red[w];
        rowmax[row] = mm; rowz[row] = zz;
        atomicMax(wmax, __float_as_uint(1.0f / zz));
    }
}

// ======== self-attn PV, u8 x s8 tensor cores ========
__global__ void __launch_bounds__(256) self_pv_i8_kernel(
    const float* __restrict__ S, const int8_t* __restrict__ LVT,
    const float* __restrict__ RM, const float* __restrict__ RZ,
    const unsigned* __restrict__ am, float* __restrict__ O)
{
    __shared__ __align__(16) uint8_t Lws[128][144];
    __shared__ __align__(16) int8_t  VTs[64][144];
    __shared__ float rmS[128], riS[128];
    float dv = fmaxf(__uint_as_float(am[2]), 1e-8f) / 127.0f;
    float dw = fmaxf(__uint_as_float(am[3]), 1e-8f) / 255.0f;
    float inv_dw = 1.0f / dw;
    float oscale = dw * dv;
    int tid = threadIdx.x, lane = tid & 31, warp = tid >> 5;
    int bh = blockIdx.y, b = bh / NH, h = bh % NH;
    int n0 = blockIdx.x * 128;
    if (tid < 128) {
        rmS[tid] = RM[(size_t)bh*NSEQ + n0 + tid];
        riS[tid] = 1.0f / RZ[(size_t)bh*NSEQ + n0 + tid];
    }
    int wn = warp & 1, wd = warp >> 1;
    int gr = lane >> 2, gc = lane & 3;
    int acc[4][2][4];
    #pragma unroll
    for (int i = 0; i < 4; i++)
        #pragma unroll
        for (int j = 0; j < 2; j++)
            #pragma unroll
            for (int l = 0; l < 4; l++) acc[i][j][l] = 0;

    for (int mc = 0; mc < 8; mc++) {
        __syncthreads();
        #pragma unroll
        for (int i = 0; i < 16; i++) {
            int lin = tid + i * 256;
            int n = lin >> 5, w = lin & 31;
            float4 sv = *(const float4*)(S + ((size_t)bh*NSEQ + n0 + n)*NSEQ + mc*128 + w*4);
            float rm = rmS[n];
            float f = riS[n] * inv_dw;
            int l0 = min(255, __float2int_rn(__expf(sv.x - rm) * f));
            int l1 = min(255, __float2int_rn(__expf(sv.y - rm) * f));
            int l2 = min(255, __float2int_rn(__expf(sv.z - rm) * f));
            int l3 = min(255, __float2int_rn(__expf(sv.w - rm) * f));
            *(uint32_t*)&Lws[n][w*4] = (uint32_t)l0 | ((uint32_t)l1 << 8)
                                     | ((uint32_t)l2 << 16) | ((uint32_t)l3 << 24);
        }
        #pragma unroll
        for (int i = 0; i < 2; i++) {
            int lin = tid + i * 256;
            int d = lin >> 3, ch = (lin & 7) << 4;
            *(int4*)&VTs[d][ch] = *(const int4*)(LVT + ((size_t)(bh*DH + d))*NSEQ + mc*128 + ch);
        }
        __syncthreads();
        #pragma unroll
        for (int ks = 0; ks < 4; ks++) {
            uint32_t af[4][4], bf[2][2];
            #pragma unroll
            for (int nt = 0; nt < 4; nt++) {
                int row = wn * 64 + nt * 16 + gr;
                af[nt][0] = *(const uint32_t*)&Lws[row][ks*32 + gc*4];
                af[nt][1] = *(const uint32_t*)&Lws[row + 8][ks*32 + gc*4];
                af[nt][2] = *(const uint32_t*)&Lws[row][ks*32 + 16 + gc*4];
                af[nt][3] = *(const uint32_t*)&Lws[row + 8][ks*32 + 16 + gc*4];
            }
            #pragma unroll
            for (int dt = 0; dt < 2; dt++) {
                int col = wd * 16 + dt * 8 + gr;
                bf[dt][0] = *(const uint32_t*)&VTs[col][ks*32 + gc*4];
                bf[dt][1] = *(const uint32_t*)&VTs[col][ks*32 + 16 + gc*4];
            }
            #pragma unroll
            for (int nt = 0; nt < 4; nt++)
                #pragma unroll
                for (int dt = 0; dt < 2; dt++)
                    mma_u8s8(acc[nt][dt], af[nt], bf[dt]);
        }
    }
    #pragma unroll
    for (int nt = 0; nt < 4; nt++) {
        #pragma unroll
        for (int dt = 0; dt < 2; dt++) {
            int row0 = n0 + wn * 64 + nt * 16 + gr;
            int col0 = wd * 16 + dt * 8 + gc * 2;
            #pragma unroll
            for (int half = 0; half < 2; half++) {
                int row = row0 + half * 8;
                float2 o = {tf32r(oscale * (float)acc[nt][dt][half*2+0]),
                            tf32r(oscale * (float)acc[nt][dt][half*2+1])};
                *(float2*)(O + ((size_t)(b*NSEQ + row))*CDIM + h*DH + col0) = o;
            }
        }
    }
}

// -------- cross-attn scores (fp32, M=77, stride 80; K source strided) --------
__global__ void __launch_bounds__(256) cross_scores_kernel(
    const float* __restrict__ q, const float* __restrict__ k, int kstride,
    float* __restrict__ S)
{
    __shared__ __align__(16) float Qs[64][68];
    __shared__ __align__(16) float Ks[80][68];
    int tid = threadIdx.x;
    int bh = blockIdx.y, b = bh / NH, h = bh % NH;
    int n0 = blockIdx.x * 64;
    #pragma unroll
    for (int it = 0; it < 4; ++it) {
        int r = (tid >> 4) + it * 16, c = (tid & 15) << 2;
        float4 qv = *(const float4*)(q + ((size_t)(b*NSEQ + n0 + r))*CDIM + h*DH + c);
        Qs[c+0][r]=qv.x; Qs[c+1][r]=qv.y; Qs[c+2][r]=qv.z; Qs[c+3][r]=qv.w;
    }
    #pragma unroll
    for (int it = 0; it < 5; ++it) {
        int lin = tid + it * 256;
        if (lin < 80 * 16) {
            int r = lin >> 4, c = (lin & 15) << 2;
            float4 kv = (r < MCTX) ? *(const float4*)(k + ((size_t)(b*MCTX + r))*kstride + h*DH + c)
                                   : make_float4(0.f,0.f,0.f,0.f);
            *(float4*)&Ks[r][c] = kv;
        }
    }
    __syncthreads();
    int tx = tid & 15, ty = tid >> 4;
    float acc[4][5];
    #pragma unroll
    for (int i = 0; i < 4; i++)
        #pragma unroll
        for (int j = 0; j < 5; j++) acc[i][j] = 0.f;
    #pragma unroll 4
    for (int d = 0; d < 64; ++d) {
        float4 q4 = *(const float4*)&Qs[d][ty*4];
        float qa[4]={q4.x,q4.y,q4.z,q4.w};
        #pragma unroll
        for (int jj = 0; jj < 5; jj++) {
            float kv = Ks[tx*5+jj][d];
            #pragma unroll
            for (int i = 0; i < 4; i++) acc[i][jj] = fmaf(qa[i], kv, acc[i][jj]);
        }
    }
    #pragma unroll
    for (int i = 0; i < 4; i++)
        #pragma unroll
        for (int jj = 0; jj < 5; jj++) {
            int m = tx * 5 + jj;
            if (m < MCTX)
                S[((size_t)bh*NSEQ + n0 + ty*4 + i)*80 + m] = acc[i][jj] * 0.125f;
        }
}

// -------- cross-attn PV (fp32; V source strided) --------
__global__ void __launch_bounds__(256) cross_pv_kernel(
    const float* __restrict__ S, const float* __restrict__ v, int vstride,
    const float* __restrict__ rowmax, const float* __restrict__ rowz,
    const unsigned* __restrict__ wmaxbits, float* __restrict__ O)
{
    __shared__ __align__(16) float Ws[80][68];
    __shared__ __align__(16) float Vs[80][68];
    int tid = threadIdx.x;
    int bh = blockIdx.y, b = bh / NH, h = bh % NH;
    int n0 = blockIdx.x * 64;
    int tx = tid & 15, ty = tid >> 4;
    float delta = fmaxf(__uint_as_float(*wmaxbits), 1e-8f) / 255.0f;
    float inv_delta = 1.0f / delta;
    #pragma unroll
    for (int it = 0; it < 5; ++it) {
        int lin = tid + it * 256;
        if (lin < MCTX * 16) {
            int r = lin >> 4, c = (lin & 15) << 2;
            *(float4*)&Vs[r][c] = *(const float4*)(v + ((size_t)(b*MCTX + r))*vstride + h*DH + c);
        }
    }
    #pragma unroll
    for (int it = 0; it < 4; ++it) {
        int r = (tid >> 4) + it * 16;
        float rm = rowmax[(size_t)bh*NSEQ + n0 + r];
        float ri = 1.0f / rowz[(size_t)bh*NSEQ + n0 + r];
        #pragma unroll
        for (int jj = 0; jj < 5; jj++) {
            int m = (tid & 15) * 5 + jj;
            float w = 0.f;
            if (m < MCTX) {
                float s = S[((size_t)bh*NSEQ + n0 + r)*80 + m];
                float p = __expf(s - rm);
                float l = rintf(p * ri * inv_delta);
                l = fminf(fmaxf(l, 0.f), 255.f);
                w = l * delta;
            }
            Ws[m][r] = w;
        }
    }
    __syncthreads();
    float acc[4][4];
    #pragma unroll
    for (int i = 0; i < 4; i++)
        #pragma unroll
        for (int j = 0; j < 4; j++) acc[i][j] = 0.f;
    for (int m = 0; m < MCTX; m++) {
        float4 w4 = *(const float4*)&Ws[m][ty*4];
        float4 v4 = *(const float4*)&Vs[m][tx*4];
        float wa[4]={w4.x,w4.y,w4.z,w4.w}, va[4]={v4.x,v4.y,v4.z,v4.w};
        #pragma unroll
        for (int i = 0; i < 4; i++)
            #pragma unroll
            for (int j = 0; j < 4; j++) acc[i][j] = fmaf(wa[i], va[j], acc[i][j]);
    }
    #pragma unroll
    for (int i = 0; i < 4; i++) {
        float4 o = {tf32r(acc[i][0]), tf32r(acc[i][1]), tf32r(acc[i][2]), tf32r(acc[i][3])};
        *(float4*)(O + ((size_t)(b*NSEQ + n0 + ty*4 + i))*CDIM + h*DH + tx*4) = o;
    }
}

// -------- GEGLU (tf32-rounded out) --------
__global__ void geglu_kernel(const float* __restrict__ Hh, float* __restrict__ G)
{
    size_t n4 = (size_t)ROWS * FFD / 4;
    size_t stride = (size_t)gridDim.x * blockDim.x;
    for (size_t i = (size_t)blockIdx.x * blockDim.x + threadIdx.x; i < n4; i += stride) {
        size_t col4 = i % (FFD / 4), row = i / (FFD / 4);
        float4 a4 = *(const float4*)(Hh + row * FF2D + col4 * 4);
        float4 g4 = *(const float4*)(Hh + row * FF2D + FFD + col4 * 4);
        float4 o;
        o.x = tf32r(a4.x * gelu_tanh(g4.x)); o.y = tf32r(a4.y * gelu_tanh(g4.y));
        o.z = tf32r(a4.z * gelu_tanh(g4.z)); o.w = tf32r(a4.w * gelu_tanh(g4.w));
        *(float4*)(G + i * 4) = o;
    }
}

extern "C" void kernel_launch(void* const* d_in, const int* in_sizes, int n_in,
                              void* d_out, int out_size)
{
    const float* x    = (const float*)d_in[0];
    const float* ctx  = (const float*)d_in[1];
    const float* ln1g = (const float*)d_in[2];
    const float* ln1b = (const float*)d_in[3];
    const float* ln2g = (const float*)d_in[4];
    const float* ln2b = (const float*)d_in[5];
    const float* ln3g = (const float*)d_in[6];
    const float* ln3b = (const float*)d_in[7];
    const float* Wq1  = (const float*)d_in[8];
    const float* Wk1  = (const float*)d_in[9];
    const float* Wv1  = (const float*)d_in[10];
    const float* Wo1  = (const float*)d_in[11];
    const float* bo1  = (const float*)d_in[12];
    const float* Wq2  = (const float*)d_in[13];
    const float* Wk2  = (const float*)d_in[14];
    const float* Wv2  = (const float*)d_in[15];
    const float* Wo2  = (const float*)d_in[16];
    const float* bo2  = (const float*)d_in[17];
    const float* Wff1 = (const float*)d_in[18];
    const float* bff1 = (const float*)d_in[19];
    const float* Wff2 = (const float*)d_in[20];
    const float* bff2 = (const float*)d_in[21];
    float* out = (float*)d_out;

    float* sc = nullptr;
    cudaGetSymbolAddress((void**)&sc, g_scratch);
    float* XN  = sc + OFF_XN;
    float* QKV = sc + OFF_Q;              // [ROWS][3840]
    float* Qc  = sc + OFF_Q;              // cross-phase: Q [ROWS][1280]
    float* KV2 = sc + OFF_K;              // cross-phase: K|V [616][2560]
    float* O   = sc + OFF_O;
    float* X1  = sc + OFF_X1;
    float* S   = sc + OFF_S;
    float* Hb  = sc + OFF_H;
    float* G   = sc + OFF_G;
    float* RM  = sc + OFF_RM;
    float* RZ  = sc + OFF_RZ;
    unsigned* AM = (unsigned*)(sc + OFF_AM);
    float* cWqkv = sc + OFF_WQKV;
    float* cWo1  = sc + OFF_WO1;
    float* cWq2  = sc + OFF_WQ2;
    float* cWo2  = sc + OFF_WO2;
    float* cWkv2 = sc + OFF_WKV2;
    float* cWf1  = sc + OFF_WF1;
    float* cWf2  = sc + OFF_WF2;
    float* cCtx  = sc + OFF_CTX;
    int8_t* LQ8 = (int8_t*)(sc + OFF_LQ8);
    int8_t* LK8 = (int8_t*)(sc + OFF_LK8);
    int8_t* LVT = (int8_t*)(sc + OFF_LVT);

    dim3 g1280(CDIM / 128, ROWS / 128);     // (10, 64)
    dim3 gqkv(QKVN / 128, ROWS / 128);      // (30, 64)
    dim3 gkv2(KV2N / 128, (CROSSROWS + 127) / 128);  // (20, 5)
    dim3 gff1(FF2D / 128, ROWS / 128);      // (80, 64)
    long long n4 = (long long)ROWS * CDIM / 4;

    init_amax_kernel<<<1, 32>>>(AM);

    // ---- pre-convert: pack QKV + cross-KV weights; plain conv for the rest ----
    conv_pack_kernel<<<512,256>>>(Wq1, cWqkv + 0,      CDIM, CDIM, QKVN);
    conv_pack_kernel<<<512,256>>>(Wk1, cWqkv + CDIM,   CDIM, CDIM, QKVN);
    conv_pack_kernel<<<512,256>>>(Wv1, cWqkv + 2*CDIM, CDIM, CDIM, QKVN);
    conv_pack_kernel<<<512,256>>>(Wk2, cWkv2 + 0,    CTXC, CDIM, KV2N);
    conv_pack_kernel<<<512,256>>>(Wv2, cWkv2 + CDIM, CTXC, CDIM, KV2N);
    conv_tf32_kernel<<<1024,256>>>(Wo1,  cWo1, (long long)SZ_W1/4);
    conv_tf32_kernel<<<1024,256>>>(Wq2,  cWq2, (long long)SZ_W1/4);
    conv_tf32_kernel<<<1024,256>>>(Wo2,  cWo2, (long long)SZ_W1/4);
    conv_tf32_kernel<<<2048,256>>>(Wff1, cWf1, (long long)SZ_WF1/4);
    conv_tf32_kernel<<<2048,256>>>(Wff2, cWf2, (long long)SZ_WF2/4);
    conv_tf32_kernel<<<512,256>>>(ctx,   cCtx, (long long)SZ_CTXB/4);

    // ---- block 1: self attention ----
    ln_kernel<<<ROWS, 256>>>(x, ln1g, ln1b, XN);
    tgemm_kernel<false,false,true,true><<<gqkv,256>>>(XN, cWqkv, QKV, ROWS, QKVN, CDIM, nullptr, nullptr, AM+0);
    quant_s8_strided<<<1024,256>>>(QKV + 0,      LQ8, AM+0);
    quant_s8_strided<<<1024,256>>>(QKV + CDIM,   LK8, AM+1);
    quant_v_t_kernel<<<dim3(NSEQ/64, BHD),256>>>(QKV + 2*CDIM, LVT, AM+2);
    self_scores_i8_kernel<<<dim3(8,8,BHD),256>>>(LQ8, LK8, S, AM);
    softmax_stats_kernel<<<BHD*NSEQ,256>>>(S, RM, RZ, AM+3, NSEQ, NSEQ);
    self_pv_i8_kernel<<<dim3(8,BHD),256>>>(S, LVT, RM, RZ, AM, O);
    tgemm_kernel<true,true,false,false><<<g1280,256>>>(O, cWo1, X1, ROWS, CDIM, CDIM, bo1, x, nullptr);

    // ---- block 2: cross attention ----
    ln_kernel<<<ROWS,256>>>(X1, ln2g, ln2b, XN);
    tgemm_kernel<false,false,true,false><<<g1280,256>>>(XN, cWq2, Qc, ROWS, CDIM, CDIM, nullptr, nullptr, AM+4);
    tgemm_kernel<false,false,true,true><<<gkv2,256>>>(cCtx, cWkv2, KV2, CROSSROWS, KV2N, CTXC, nullptr, nullptr, AM+5);
    quant_sym_kernel<<<2048,256>>>(Qc, n4, AM+4);
    quant_kv2_kernel<<<1024,256>>>(KV2, AM+5);
    cross_scores_kernel<<<dim3(16,BHD),256>>>(Qc, KV2, KV2N, S);
    softmax_stats_kernel<<<BHD*NSEQ,256>>>(S, RM, RZ, AM+7, MCTX, 80);
    cross_pv_kernel<<<dim3(16,BHD),256>>>(S, KV2 + CDIM, KV2N, RM, RZ, AM+7, O);
    tgemm_kernel<true,true,false,false><<<g1280,256>>>(O, cWo2, X1, ROWS, CDIM, CDIM, bo2, X1, nullptr);

    // ---- block 3: GEGLU FF ----
    ln_kernel<<<ROWS,256>>>(X1, ln3g, ln3b, XN);
    tgemm_kernel<true,false,false,false><<<gff1,256>>>(XN, cWf1, Hb, ROWS, FF2D, CDIM, bff1, nullptr, nullptr);
    geglu_kernel<<<4096,256>>>(Hb, G);
    tgemm_kernel<true,true,false,false><<<g1280,256>>>(G, cWf2, out, ROWS, CDIM, FFD, bff2, X1, nullptr);
}

// round 10
// speedup vs baseline: 1.2000x; 1.0209x over previous
#include <cuda_runtime.h>
#include <cstdint>

#define NB 8
#define NSEQ 1024
#define CDIM 1280
#define NH 20
#define DH 64
#define MCTX 77
#define CTXC 768
#define FFD 5120
#define FF2D 10240
#define ROWS (NB*NSEQ)
#define BHD (NB*NH)
#define CROSSROWS (NB*MCTX)
#define QKVN 3840
#define KV2N 2560

static constexpr size_t SZ_XC = (size_t)ROWS * CDIM;
static constexpr size_t OFF_XN = 0;
static constexpr size_t OFF_Q  = OFF_XN + SZ_XC;     // QKV fused buffer [ROWS][3840]
static constexpr size_t OFF_K  = OFF_Q + SZ_XC;      // cross-phase: KV2 [616][2560]
static constexpr size_t OFF_V  = OFF_K + SZ_XC;
static constexpr size_t OFF_O  = OFF_V + SZ_XC;
static constexpr size_t OFF_X1 = OFF_O + SZ_XC;
static constexpr size_t OFF_S  = OFF_X1 + SZ_XC;     // cross scores only now
static constexpr size_t SZ_S   = (size_t)BHD * NSEQ * 80;
static constexpr size_t OFF_H  = OFF_S + SZ_S;
static constexpr size_t SZ_H   = (size_t)ROWS * FF2D;
static constexpr size_t OFF_G  = OFF_H + SZ_H;
static constexpr size_t SZ_G   = (size_t)ROWS * FFD;
static constexpr size_t OFF_RM = OFF_G + SZ_G;
static constexpr size_t OFF_RZ = OFF_RM + (size_t)BHD * NSEQ;
static constexpr size_t OFF_AM = OFF_RZ + (size_t)BHD * NSEQ;
static constexpr size_t SZ_W1  = (size_t)CDIM * CDIM;
static constexpr size_t SZ_WK2 = (size_t)CTXC * CDIM;
static constexpr size_t SZ_WF1 = (size_t)CDIM * FF2D;
static constexpr size_t SZ_WF2 = (size_t)FFD * CDIM;
static constexpr size_t SZ_CTXB = (size_t)CROSSROWS * CTXC;
static constexpr size_t OFF_WQKV = OFF_AM + 8;
static constexpr size_t OFF_WO1  = OFF_WQKV + 3 * SZ_W1;
static constexpr size_t OFF_WQ2  = OFF_WO1 + SZ_W1;
static constexpr size_t OFF_WO2  = OFF_WQ2 + SZ_W1;
static constexpr size_t OFF_WKV2 = OFF_WO2 + SZ_W1;
static constexpr size_t OFF_WF1  = OFF_WKV2 + 2 * SZ_WK2;
static constexpr size_t OFF_WF2  = OFF_WF1 + SZ_WF1;
static constexpr size_t OFF_CTX  = OFF_WF2 + SZ_WF2;
static constexpr size_t SZ_S8F   = (size_t)ROWS * CDIM / 4;
static constexpr size_t OFF_LQ8  = OFF_CTX + SZ_CTXB;
static constexpr size_t OFF_LK8  = OFF_LQ8 + SZ_S8F;
static constexpr size_t OFF_LVT  = OFF_LK8 + SZ_S8F;
static constexpr size_t TOTAL_SCRATCH = OFF_LVT + SZ_S8F;

__device__ __align__(256) float g_scratch[TOTAL_SCRATCH];

__global__ void init_amax_kernel(unsigned* amax) {
    if (threadIdx.x < 8) amax[threadIdx.x] = 0u;
}

__device__ __forceinline__ float gelu_tanh(float x) {
    float x3 = x * x * x;
    return 0.5f * x * (1.0f + tanhf(0.7978845608028654f * (x + 0.044715f * x3)));
}

__device__ __forceinline__ uint32_t f2tf32(float f) {
    uint32_t r;
    asm("cvt.rna.tf32.f32 %0, %1;" : "=r"(r) : "f"(f));
    return r;
}
__device__ __forceinline__ float tf32r(float f) { return __uint_as_float(f2tf32(f)); }

__device__ __forceinline__ void mma_tf32(float* d, const uint32_t* a, const uint32_t* b) {
    asm volatile("mma.sync.aligned.m16n8k8.row.col.f32.tf32.tf32.f32 "
        "{%0,%1,%2,%3}, {%4,%5,%6,%7}, {%8,%9}, {%0,%1,%2,%3};"
        : "+f"(d[0]), "+f"(d[1]), "+f"(d[2]), "+f"(d[3])
        : "r"(a[0]), "r"(a[1]), "r"(a[2]), "r"(a[3]), "r"(b[0]), "r"(b[1]));
}

__device__ __forceinline__ void mma_s8(int* d, const uint32_t* a, const uint32_t* b) {
    asm volatile("mma.sync.aligned.m16n8k32.row.col.s32.s8.s8.s32 "
        "{%0,%1,%2,%3}, {%4,%5,%6,%7}, {%8,%9}, {%0,%1,%2,%3};"
        : "+r"(d[0]), "+r"(d[1]), "+r"(d[2]), "+r"(d[3])
        : "r"(a[0]), "r"(a[1]), "r"(a[2]), "r"(a[3]), "r"(b[0]), "r"(b[1]));
}

__device__ __forceinline__ void mma_u8s8(int* d, const uint32_t* a, const uint32_t* b) {
    asm volatile("mma.sync.aligned.m16n8k32.row.col.s32.u8.s8.s32 "
        "{%0,%1,%2,%3}, {%4,%5,%6,%7}, {%8,%9}, {%0,%1,%2,%3};"
        : "+r"(d[0]), "+r"(d[1]), "+r"(d[2]), "+r"(d[3])
        : "r"(a[0]), "r"(a[1]), "r"(a[2]), "r"(a[3]), "r"(b[0]), "r"(b[1]));
}

__device__ __forceinline__ void ldsm4(uint32_t& r0, uint32_t& r1, uint32_t& r2, uint32_t& r3,
                                      uint32_t addr) {
    asm volatile("ldmatrix.sync.aligned.m8n8.x4.shared.b16 {%0,%1,%2,%3}, [%4];"
        : "=r"(r0), "=r"(r1), "=r"(r2), "=r"(r3) : "r"(addr));
}

__device__ __forceinline__ void cp_async16(uint32_t dst, const void* src, int srcsize) {
    asm volatile("cp.async.cg.shared.global [%0], [%1], 16, %2;"
                 :: "r"(dst), "l"(src), "r"(srcsize));
}

__device__ __forceinline__ int clamp_i(int v, int lo, int hi) {
    return v < lo ? lo : (v > hi ? hi : v);
}

__device__ __forceinline__ uint32_t pack_s8x4(float4 v, float inv) {
    int a = clamp_i(__float2int_rn(v.x * inv), -128, 127);
    int b = clamp_i(__float2int_rn(v.y * inv), -128, 127);
    int c = clamp_i(__float2int_rn(v.z * inv), -128, 127);
    int d = clamp_i(__float2int_rn(v.w * inv), -128, 127);
    return (a & 255) | ((b & 255) << 8) | ((c & 255) << 16) | ((d & 255) << 24);
}

// -------- tf32 convert (contiguous) --------
__global__ void conv_tf32_kernel(const float* __restrict__ src, float* __restrict__ dst,
                                 long long n4)
{
    long long stride = (long long)gridDim.x * blockDim.x;
    for (long long i = (long long)blockIdx.x * blockDim.x + threadIdx.x; i < n4; i += stride) {
        float4 v = *(const float4*)(src + i * 4);
        v.x = tf32r(v.x); v.y = tf32r(v.y); v.z = tf32r(v.z); v.w = tf32r(v.w);
        *(float4*)(dst + i * 4) = v;
    }
}

// -------- tf32 convert + column-pack --------
__global__ void conv_pack_kernel(const float* __restrict__ src, float* __restrict__ dst,
                                 int Kn, int Nn, int dstStride)
{
    long long n4 = (long long)Kn * Nn / 4;
    long long stride = (long long)gridDim.x * blockDim.x;
    for (long long i = (long long)blockIdx.x * blockDim.x + threadIdx.x; i < n4; i += stride) {
        long long e = i * 4;
        int row = (int)(e / Nn), col = (int)(e % Nn);
        float4 v = *(const float4*)(src + e);
        v.x = tf32r(v.x); v.y = tf32r(v.y); v.z = tf32r(v.z); v.w = tf32r(v.w);
        *(float4*)(dst + (size_t)row * dstStride + col) = v;
    }
}

// ---------------- LayerNorm (tf32-rounded out) ----------------
__global__ void ln_kernel(const float* __restrict__ x, const float* __restrict__ g,
                          const float* __restrict__ bta, float* __restrict__ out)
{
    __shared__ float sx[CDIM];
    __shared__ float red[8];
    int row = blockIdx.x, tid = threadIdx.x;
    const float* xr = x + (size_t)row * CDIM;
    float s = 0.f;
    for (int i = tid; i < CDIM; i += 256) { float v = xr[i]; sx[i] = v; s += v; }
    #pragma unroll
    for (int o = 16; o; o >>= 1) s += __shfl_xor_sync(0xffffffffu, s, o);
    if ((tid & 31) == 0) red[tid >> 5] = s;
    __syncthreads();
    float tot = 0.f;
    #pragma unroll
    for (int w = 0; w < 8; w++) tot += red[w];
    float mean = tot * (1.0f / (float)CDIM);
    float vs = 0.f;
    for (int i = tid; i < CDIM; i += 256) { float d = sx[i] - mean; vs += d * d; }
    __syncthreads();
    #pragma unroll
    for (int o = 16; o; o >>= 1) vs += __shfl_xor_sync(0xffffffffu, vs, o);
    if ((tid & 31) == 0) red[tid >> 5] = vs;
    __syncthreads();
    float tot2 = 0.f;
    #pragma unroll
    for (int w = 0; w < 8; w++) tot2 += red[w];
    float rstd = rsqrtf(tot2 * (1.0f / (float)CDIM) + 1e-5f);
    for (int i = tid; i < CDIM; i += 256)
        out[(size_t)row * CDIM + i] = tf32r((sx[i] - mean) * rstd * g[i] + bta[i]);
}

// ============ TF32 GEMM (R7-proven) ============
template<bool HAS_BIAS, bool HAS_RES, bool DO_AMAX, bool SEG>
__global__ void __launch_bounds__(256, 2) tgemm_kernel(
    const float* __restrict__ A, const float* __restrict__ Bm, float* __restrict__ Cm,
    int Mn, int Nn, int Kn,
    const float* __restrict__ bias, const float* __restrict__ res, unsigned* amax)
{
    constexpr int ST = 3;
    constexpr uint32_t ABYTES = 128 * 20 * 4;
    constexpr uint32_t BBYTES = 16 * 136 * 4;
    __shared__ __align__(16) uint32_t As[ST][128][20];
    __shared__ __align__(16) float    Bs[ST][16][136];
    __shared__ float reds[8];

    int tid  = threadIdx.x;
    int lane = tid & 31;
    int warp = tid >> 5;
    int wm = warp & 1;
    int wn = warp >> 1;
    int nBase = blockIdx.x * 128;
    int mBase = blockIdx.y * 128;

    uint32_t asmb = (uint32_t)__cvta_generic_to_shared(&As[0][0][0]);
    uint32_t bsmb = (uint32_t)__cvta_generic_to_shared(&Bs[0][0][0]);

    const int aR0 = tid >> 2;
    const int aC  = (tid & 3) << 2;
    const int bK0 = tid >> 5;
    const int bN  = (tid & 31) << 2;

    int r8 = lane & 7, sel = lane >> 3;
    uint32_t aoff = asmb + (((wm * 64 + r8 + ((sel & 1) << 3)) * 20 + ((sel >> 1) << 2)) << 2);

    float acc[4][4][4];
    #pragma unroll
    for (int i = 0; i < 4; i++)
        #pragma unroll
        for (int j = 0; j < 4; j++)
            #pragma unroll
            for (int l = 0; l < 4; l++) acc[i][j][l] = 0.f;

    int KT = Kn >> 4;

    auto issue_stage = [&](int s, int k0) {
        #pragma unroll
        for (int i = 0; i < 2; i++) {
            int r = aR0 + i * 64;
            int gr = mBase + r;
            int ok = (gr < Mn);
            const float* src = A + (size_t)(ok ? gr : 0) * Kn + k0 + aC;
            cp_async16(asmb + s * ABYTES + ((r * 20 + aC) << 2), src, ok ? 16 : 0);
        }
        #pragma unroll
        for (int i = 0; i < 2; i++) {
            int kr = bK0 + i * 8;
            const float* src = Bm + (size_t)(k0 + kr) * Nn + nBase + bN;
            cp_async16(bsmb + s * BBYTES + ((kr * 136 + bN) << 2), src, 16);
        }
        asm volatile("cp.async.commit_group;" ::: "memory");
    };

    issue_stage(0, 0);
    issue_stage(1, 16);

    int lr = lane >> 2, lc = lane & 3;
    for (int kt = 0; kt < KT; ++kt) {
        int buf = kt % ST;
        asm volatile("cp.async.wait_group 1;" ::: "memory");
        __syncthreads();
        if (kt + 2 < KT) issue_stage((kt + 2) % ST, (kt + 2) << 4);
        else asm volatile("cp.async.commit_group;" ::: "memory");

        uint32_t abuf = aoff + buf * ABYTES;
        #pragma unroll
        for (int ks = 0; ks < 2; ks++) {
            uint32_t af[4][4], bf[4][2];
            #pragma unroll
            for (int mt = 0; mt < 4; mt++)
                ldsm4(af[mt][0], af[mt][1], af[mt][2], af[mt][3],
                      abuf + mt * (16 * 20 * 4) + ks * 32);
            #pragma unroll
            for (int nt = 0; nt < 4; nt++) {
                int col = wn * 32 + nt * 8 + lr;
                bf[nt][0] = __float_as_uint(Bs[buf][ks * 8 + lc][col]);
                bf[nt][1] = __float_as_uint(Bs[buf][ks * 8 + lc + 4][col]);
            }
            #pragma unroll
            for (int mt = 0; mt < 4; mt++)
                #pragma unroll
                for (int nt = 0; nt < 4; nt++)
                    mma_tf32(acc[mt][nt], af[mt], bf[nt]);
        }
    }

    float amx = 0.f;
    #pragma unroll
    for (int mt = 0; mt < 4; mt++) {
        #pragma unroll
        for (int nt = 0; nt < 4; nt++) {
            int row0 = mBase + wm * 64 + mt * 16 + lr;
            int col0 = nBase + wn * 32 + nt * 8 + lc * 2;
            #pragma unroll
            for (int half = 0; half < 2; half++) {
                int row = row0 + half * 8;
                if (row < Mn) {
                    float c0 = acc[mt][nt][half * 2 + 0];
                    float c1 = acc[mt][nt][half * 2 + 1];
                    if (HAS_BIAS) { c0 += bias[col0]; c1 += bias[col0 + 1]; }
                    if (HAS_RES) {
                        c0 += res[(size_t)row * Nn + col0];
                        c1 += res[(size_t)row * Nn + col0 + 1];
                    }
                    float2 o = {c0, c1};
                    *(float2*)(Cm + (size_t)row * Nn + col0) = o;
                    if (DO_AMAX) amx = fmaxf(amx, fmaxf(fabsf(c0), fabsf(c1)));
                }
            }
        }
    }
    if (DO_AMAX) {
        #pragma unroll
        for (int o = 16; o; o >>= 1) amx = fmaxf(amx, __shfl_xor_sync(0xffffffffu, amx, o));
        if (lane == 0) reds[warp] = amx;
        __syncthreads();
        if (tid == 0) {
            float m = reds[0];
            #pragma unroll
            for (int w = 1; w < 8; w++) m = fmaxf(m, reds[w]);
            unsigned* tgt = amax + (SEG ? (nBase / 1280) : 0);
            atomicMax(tgt, __float_as_uint(m));
        }
    }
}

// -------- fp32 fake-quant in place (contiguous; cross Q) --------
__global__ void quant_sym_kernel(float* __restrict__ x, long long n4,
                                 const unsigned* __restrict__ amaxbits)
{
    float delta = fmaxf(__uint_as_float(*amaxbits), 1e-8f) / 127.0f;
    long long stride = (long long)gridDim.x * blockDim.x;
    for (long long i = (long long)blockIdx.x * blockDim.x + threadIdx.x; i < n4; i += stride) {
        float4 v = *(float4*)(x + i * 4);
        float l;
        l = rintf(v.x/delta); l = fminf(fmaxf(l,-128.f),127.f); v.x = l*delta;
        l = rintf(v.y/delta); l = fminf(fmaxf(l,-128.f),127.f); v.y = l*delta;
        l = rintf(v.z/delta); l = fminf(fmaxf(l,-128.f),127.f); v.z = l*delta;
        l = rintf(v.w/delta); l = fminf(fmaxf(l,-128.f),127.f); v.w = l*delta;
        *(float4*)(x + i * 4) = v;
    }
}

// -------- fp32 fake-quant, two column segments (cross K|V fused) --------
__global__ void quant_kv2_kernel(float* __restrict__ x, const unsigned* __restrict__ am)
{
    float d0 = fmaxf(__uint_as_float(am[0]), 1e-8f) / 127.0f;
    float d1 = fmaxf(__uint_as_float(am[1]), 1e-8f) / 127.0f;
    long long n4 = (long long)CROSSROWS * KV2N / 4;
    long long stride = (long long)gridDim.x * blockDim.x;
    for (long long i = (long long)blockIdx.x * blockDim.x + threadIdx.x; i < n4; i += stride) {
        int col = (int)((i * 4) % KV2N);
        float delta = (col < CDIM) ? d0 : d1;
        float4 v = *(float4*)(x + i * 4);
        float l;
        l = rintf(v.x/delta); l = fminf(fmaxf(l,-128.f),127.f); v.x = l*delta;
        l = rintf(v.y/delta); l = fminf(fmaxf(l,-128.f),127.f); v.y = l*delta;
        l = rintf(v.z/delta); l = fminf(fmaxf(l,-128.f),127.f); v.z = l*delta;
        l = rintf(v.w/delta); l = fminf(fmaxf(l,-128.f),127.f); v.w = l*delta;
        *(float4*)(x + i * 4) = v;
    }
}

// -------- s8 level quant from strided source --------
__global__ void quant_s8_strided(const float* __restrict__ x, int8_t* __restrict__ L,
                                 const unsigned* __restrict__ amaxbits)
{
    float delta = fmaxf(__uint_as_float(*amaxbits), 1e-8f) / 127.0f;
    float inv = 1.0f / delta;
    long long n16 = (long long)ROWS * (CDIM / 16);
    long long stride = (long long)gridDim.x * blockDim.x;
    for (long long i = (long long)blockIdx.x * blockDim.x + threadIdx.x; i < n16; i += stride) {
        int row = (int)(i / (CDIM / 16));
        int c16 = (int)(i % (CDIM / 16));
        const float4* p = (const float4*)(x + (size_t)row * QKVN + c16 * 16);
        uint4 o;
        o.x = pack_s8x4(p[0], inv);
        o.y = pack_s8x4(p[1], inv);
        o.z = pack_s8x4(p[2], inv);
        o.w = pack_s8x4(p[3], inv);
        *(uint4*)(L + i * 16) = o;
    }
}

// -------- V quant + per-head transpose (strided source) --------
__global__ void __launch_bounds__(256) quant_v_t_kernel(const float* __restrict__ V,
                                                        int8_t* __restrict__ LVT,
                                                        const unsigned* __restrict__ amaxbits)
{
    __shared__ int8_t T[64][80];
    float delta = fmaxf(__uint_as_float(*amaxbits), 1e-8f) / 127.0f;
    float inv = 1.0f / delta;
    int tid = threadIdx.x;
    int bh = blockIdx.y, b = bh / NH, h = bh % NH;
    int m0 = blockIdx.x * 64;
    #pragma unroll
    for (int i = 0; i < 4; i++) {
        int lin = tid + i * 256;
        int r = lin >> 4;
        int c4 = (lin & 15) << 2;
        float4 v = *(const float4*)(V + ((size_t)(b*NSEQ + m0 + r))*QKVN + h*DH + c4);
        T[c4+0][r] = (int8_t)clamp_i(__float2int_rn(v.x*inv), -128, 127);
        T[c4+1][r] = (int8_t)clamp_i(__float2int_rn(v.y*inv), -128, 127);
        T[c4+2][r] = (int8_t)clamp_i(__float2int_rn(v.z*inv), -128, 127);
        T[c4+3][r] = (int8_t)clamp_i(__float2int_rn(v.w*inv), -128, 127);
    }
    __syncthreads();
    int d = tid >> 2, ch = (tid & 3) << 4;
    int4 val = *(int4*)&T[d][ch];
    *(int4*)(LVT + ((size_t)(bh*DH + d))*NSEQ + m0 + ch) = val;
}

// ======== FUSED self-attn stats: recompute scores, online softmax, no S tensor ========
__global__ void __launch_bounds__(256) self_stats_i8_kernel(
    const int8_t* __restrict__ LQ, const int8_t* __restrict__ LK,
    float* __restrict__ RM, float* __restrict__ RZ, unsigned* __restrict__ am)
{
    __shared__ __align__(16) int8_t Qs[128][80];
    __shared__ __align__(16) int8_t Ks[128][80];
    __shared__ float red[128][4];
    __shared__ float tmaxS[128];
    __shared__ float rowmS[128], rowzS[128];
    __shared__ float wred[8];
    float dq = fmaxf(__uint_as_float(am[0]), 1e-8f) / 127.0f;
    float dk = fmaxf(__uint_as_float(am[1]), 1e-8f) / 127.0f;
    float scale = dq * dk * 0.125f;
    int tid = threadIdx.x, lane = tid & 31, warp = tid >> 5;
    int bh = blockIdx.y, b = bh / NH, h = bh % NH;
    int n0 = blockIdx.x * 128;
    int wn = warp & 1, wm = warp >> 1;
    int gr = lane >> 2, gc = lane & 3;

    #pragma unroll
    for (int i = 0; i < 2; i++) {
        int lin = tid + i * 256;
        int r = lin >> 2, ch = (lin & 3) << 4;
        *(int4*)&Qs[r][ch] = *(const int4*)(LQ + ((size_t)(b*NSEQ + n0 + r))*CDIM + h*DH + ch);
    }
    if (tid < 128) { rowmS[tid] = -3.4e38f; rowzS[tid] = 0.f; }

    int rows[8];
    #pragma unroll
    for (int nt = 0; nt < 4; nt++)
        #pragma unroll
        for (int half = 0; half < 2; half++)
            rows[nt*2+half] = wn*64 + nt*16 + gr + half*8;

    for (int mc = 0; mc < 8; mc++) {
        __syncthreads();
        #pragma unroll
        for (int i = 0; i < 2; i++) {
            int lin = tid + i * 256;
            int r = lin >> 2, ch = (lin & 3) << 4;
            *(int4*)&Ks[r][ch] = *(const int4*)(LK + ((size_t)(b*NSEQ + mc*128 + r))*CDIM + h*DH + ch);
        }
        __syncthreads();

        int acc[4][4][4];
        #pragma unroll
        for (int i = 0; i < 4; i++)
            #pragma unroll
            for (int j = 0; j < 4; j++)
                #pragma unroll
                for (int l = 0; l < 4; l++) acc[i][j][l] = 0;
        #pragma unroll
        for (int ks = 0; ks < 2; ks++) {
            uint32_t af[4][4], bf[4][2];
            #pragma unroll
            for (int nt = 0; nt < 4; nt++) {
                int row = wn * 64 + nt * 16 + gr;
                af[nt][0] = *(const uint32_t*)&Qs[row][ks*32 + gc*4];
                af[nt][1] = *(const uint32_t*)&Qs[row + 8][ks*32 + gc*4];
                af[nt][2] = *(const uint32_t*)&Qs[row][ks*32 + 16 + gc*4];
                af[nt][3] = *(const uint32_t*)&Qs[row + 8][ks*32 + 16 + gc*4];
            }
            #pragma unroll
            for (int mt = 0; mt < 4; mt++) {
                int col = wm * 32 + mt * 8 + gr;
                bf[mt][0] = *(const uint32_t*)&Ks[col][ks*32 + gc*4];
                bf[mt][1] = *(const uint32_t*)&Ks[col][ks*32 + 16 + gc*4];
            }
            #pragma unroll
            for (int nt = 0; nt < 4; nt++)
                #pragma unroll
                for (int mt = 0; mt < 4; mt++)
                    mma_s8(acc[nt][mt], af[nt], bf[mt]);
        }

        // per-row tile max
        float lmax[8];
        #pragma unroll
        for (int j = 0; j < 8; j++) lmax[j] = -3.4e38f;
        #pragma unroll
        for (int nt = 0; nt < 4; nt++)
            #pragma unroll
            for (int mt = 0; mt < 4; mt++)
                #pragma unroll
                for (int c = 0; c < 4; c++)
                    lmax[nt*2 + (c>>1)] = fmaxf(lmax[nt*2 + (c>>1)], scale*(float)acc[nt][mt][c]);
        #pragma unroll
        for (int j = 0; j < 8; j++) {
            lmax[j] = fmaxf(lmax[j], __shfl_xor_sync(0xffffffffu, lmax[j], 1));
            lmax[j] = fmaxf(lmax[j], __shfl_xor_sync(0xffffffffu, lmax[j], 2));
        }
        if (gc == 0) {
            #pragma unroll
            for (int j = 0; j < 8; j++) red[rows[j]][wm] = lmax[j];
        }
        __syncthreads();
        if (tid < 128)
            tmaxS[tid] = fmaxf(fmaxf(red[tid][0], red[tid][1]), fmaxf(red[tid][2], red[tid][3]));
        __syncthreads();

        // per-row tile exp-sum
        float lsum[8];
        #pragma unroll
        for (int j = 0; j < 8; j++) lsum[j] = 0.f;
        #pragma unroll
        for (int nt = 0; nt < 4; nt++) {
            float tm0 = tmaxS[rows[nt*2]];
            float tm1 = tmaxS[rows[nt*2+1]];
            #pragma unroll
            for (int mt = 0; mt < 4; mt++) {
                lsum[nt*2]   += __expf(scale*(float)acc[nt][mt][0] - tm0)
                              + __expf(scale*(float)acc[nt][mt][1] - tm0);
                lsum[nt*2+1] += __expf(scale*(float)acc[nt][mt][2] - tm1)
                              + __expf(scale*(float)acc[nt][mt][3] - tm1);
            }
        }
        #pragma unroll
        for (int j = 0; j < 8; j++) {
            lsum[j] += __shfl_xor_sync(0xffffffffu, lsum[j], 1);
            lsum[j] += __shfl_xor_sync(0xffffffffu, lsum[j], 2);
        }
        if (gc == 0) {
            #pragma unroll
            for (int j = 0; j < 8; j++) red[rows[j]][wm] = lsum[j];
        }
        __syncthreads();
        if (tid < 128) {
            float ts = red[tid][0] + red[tid][1] + red[tid][2] + red[tid][3];
            float tm = tmaxS[tid];
            float om = rowmS[tid];
            float nm = fmaxf(om, tm);
            rowzS[tid] = rowzS[tid] * __expf(om - nm) + ts * __expf(tm - nm);
            rowmS[tid] = nm;
        }
    }
    __syncthreads();
    float invz = -3.4e38f;
    if (tid < 128) {
        float z = rowzS[tid];
        RM[(size_t)bh*NSEQ + n0 + tid] = rowmS[tid];
        RZ[(size_t)bh*NSEQ + n0 + tid] = z;
        invz = 1.0f / z;
    }
    #pragma unroll
    for (int o = 16; o; o >>= 1) invz = fmaxf(invz, __shfl_xor_sync(0xffffffffu, invz, o));
    if (lane == 0) wred[warp] = invz;
    __syncthreads();
    if (tid == 0) {
        float m = wred[0];
        #pragma unroll
        for (int w = 1; w < 8; w++) m = fmaxf(m, wred[w]);
        atomicMax(am + 3, __float_as_uint(m));
    }
}

// ======== FUSED self-attn PV: recompute scores, fq_zero, u8xs8 PV — no S tensor ========
__global__ void __launch_bounds__(256) self_pv_i8_kernel(
    const int8_t* __restrict__ LQ, const int8_t* __restrict__ LK,
    const int8_t* __restrict__ LVT,
    const float* __restrict__ RM, const float* __restrict__ RZ,
    const unsigned* __restrict__ am, float* __restrict__ O)
{
    __shared__ __align__(16) int8_t  Qs[128][80];
    __shared__ __align__(16) int8_t  Ks[128][80];
    __shared__ __align__(16) uint8_t Lws[128][144];
    __shared__ __align__(16) int8_t  VTs[64][144];
    __shared__ float rmS[128], riS[128];
    float dq = fmaxf(__uint_as_float(am[0]), 1e-8f) / 127.0f;
    float dk = fmaxf(__uint_as_float(am[1]), 1e-8f) / 127.0f;
    float scale = dq * dk * 0.125f;
    float dv = fmaxf(__uint_as_float(am[2]), 1e-8f) / 127.0f;
    float dw = fmaxf(__uint_as_float(am[3]), 1e-8f) / 255.0f;
    float inv_dw = 1.0f / dw;
    float oscale = dw * dv;
    int tid = threadIdx.x, lane = tid & 31, warp = tid >> 5;
    int bh = blockIdx.y, b = bh / NH, h = bh % NH;
    int n0 = blockIdx.x * 128;
    int wn = warp & 1, wm = warp >> 1, wd = warp >> 1;
    int gr = lane >> 2, gc = lane & 3;

    #pragma unroll
    for (int i = 0; i < 2; i++) {
        int lin = tid + i * 256;
        int r = lin >> 2, ch = (lin & 3) << 4;
        *(int4*)&Qs[r][ch] = *(const int4*)(LQ + ((size_t)(b*NSEQ + n0 + r))*CDIM + h*DH + ch);
    }
    if (tid < 128) {
        rmS[tid] = RM[(size_t)bh*NSEQ + n0 + tid];
        riS[tid] = 1.0f / RZ[(size_t)bh*NSEQ + n0 + tid];
    }

    int acc[4][2][4];
    #pragma unroll
    for (int i = 0; i < 4; i++)
        #pragma unroll
        for (int j = 0; j < 2; j++)
            #pragma unroll
            for (int l = 0; l < 4; l++) acc[i][j][l] = 0;

    for (int mc = 0; mc < 8; mc++) {
        __syncthreads();
        #pragma unroll
        for (int i = 0; i < 2; i++) {
            int lin = tid + i * 256;
            int r = lin >> 2, ch = (lin & 3) << 4;
            *(int4*)&Ks[r][ch] = *(const int4*)(LK + ((size_t)(b*NSEQ + mc*128 + r))*CDIM + h*DH + ch);
        }
        #pragma unroll
        for (int i = 0; i < 2; i++) {
            int lin = tid + i * 256;
            int d = lin >> 3, ch = (lin & 7) << 4;
            *(int4*)&VTs[d][ch] = *(const int4*)(LVT + ((size_t)(bh*DH + d))*NSEQ + mc*128 + ch);
        }
        __syncthreads();

        // recompute score tile
        int sacc[4][4][4];
        #pragma unroll
        for (int i = 0; i < 4; i++)
            #pragma unroll
            for (int j = 0; j < 4; j++)
                #pragma unroll
                for (int l = 0; l < 4; l++) sacc[i][j][l] = 0;
        #pragma unroll
        for (int ks = 0; ks < 2; ks++) {
            uint32_t af[4][4], bf[4][2];
            #pragma unroll
            for (int nt = 0; nt < 4; nt++) {
                int row = wn * 64 + nt * 16 + gr;
                af[nt][0] = *(const uint32_t*)&Qs[row][ks*32 + gc*4];
                af[nt][1] = *(const uint32_t*)&Qs[row + 8][ks*32 + gc*4];
                af[nt][2] = *(const uint32_t*)&Qs[row][ks*32 + 16 + gc*4];
                af[nt][3] = *(const uint32_t*)&Qs[row + 8][ks*32 + 16 + gc*4];
            }
            #pragma unroll
            for (int mt = 0; mt < 4; mt++) {
                int col = wm * 32 + mt * 8 + gr;
                bf[mt][0] = *(const uint32_t*)&Ks[col][ks*32 + gc*4];
                bf[mt][1] = *(const uint32_t*)&Ks[col][ks*32 + 16 + gc*4];
            }
            #pragma unroll
            for (int nt = 0; nt < 4; nt++)
                #pragma unroll
                for (int mt = 0; mt < 4; mt++)
                    mma_s8(sacc[nt][mt], af[nt], bf[mt]);
        }
        // exp + fq_zero -> Lws (u16-packed u8 pairs)
        #pragma unroll
        for (int nt = 0; nt < 4; nt++) {
            #pragma unroll
            for (int half = 0; half < 2; half++) {
                int row = wn*64 + nt*16 + gr + half*8;
                float rm = rmS[row];
                float f = riS[row] * inv_dw;
                #pragma unroll
                for (int mt = 0; mt < 4; mt++) {
                    int col = wm*32 + mt*8 + gc*2;
                    int l0 = min(255, __float2int_rn(__expf(scale*(float)sacc[nt][mt][half*2+0] - rm) * f));
                    int l1 = min(255, __float2int_rn(__expf(scale*(float)sacc[nt][mt][half*2+1] - rm) * f));
                    *(uint16_t*)&Lws[row][col] = (uint16_t)(l0 | (l1 << 8));
                }
            }
        }
        __syncthreads();

        // PV mma
        #pragma unroll
        for (int ks = 0; ks < 4; ks++) {
            uint32_t af[4][4], bf[2][2];
            #pragma unroll
            for (int nt = 0; nt < 4; nt++) {
                int row = wn * 64 + nt * 16 + gr;
                af[nt][0] = *(const uint32_t*)&Lws[row][ks*32 + gc*4];
                af[nt][1] = *(const uint32_t*)&Lws[row + 8][ks*32 + gc*4];
                af[nt][2] = *(const uint32_t*)&Lws[row][ks*32 + 16 + gc*4];
                af[nt][3] = *(const uint32_t*)&Lws[row + 8][ks*32 + 16 + gc*4];
            }
            #pragma unroll
            for (int dt = 0; dt < 2; dt++) {
                int col = wd * 16 + dt * 8 + gr;
                bf[dt][0] = *(const uint32_t*)&VTs[col][ks*32 + gc*4];
                bf[dt][1] = *(const uint32_t*)&VTs[col][ks*32 + 16 + gc*4];
            }
            #pragma unroll
            for (int nt = 0; nt < 4; nt++)
                #pragma unroll
                for (int dt = 0; dt < 2; dt++)
                    mma_u8s8(acc[nt][dt], af[nt], bf[dt]);
        }
    }
    #pragma unroll
    for (int nt = 0; nt < 4; nt++) {
        #pragma unroll
        for (int dt = 0; dt < 2; dt++) {
            int row0 = n0 + wn * 64 + nt * 16 + gr;
            int col0 = wd * 16 + dt * 8 + gc * 2;
            #pragma unroll
            for (int half = 0; half < 2; half++) {
                int row = row0 + half * 8;
                float2 o = {tf32r(oscale * (float)acc[nt][dt][half*2+0]),
                            tf32r(oscale * (float)acc[nt][dt][half*2+1])};
                *(float2*)(O + ((size_t)(b*NSEQ + row))*CDIM + h*DH + col0) = o;
            }
        }
    }
}

// -------- softmax row stats (cross path) --------
__global__ void softmax_stats_kernel(const float* __restrict__ S, float* __restrict__ rowmax,
                                     float* __restrict__ rowz, unsigned* wmax, int cols, int stride)
{
    int row = blockIdx.x, tid = threadIdx.x;
    const float* s = S + (size_t)row * stride;
    __shared__ float red[8];
    float m = -3.4e38f;
    for (int i = tid; i < cols; i += 256) m = fmaxf(m, s[i]);
    #pragma unroll
    for (int o = 16; o; o >>= 1) m = fmaxf(m, __shfl_xor_sync(0xffffffffu, m, o));
    if ((tid & 31) == 0) red[tid >> 5] = m;
    __syncthreads();
    float mm = red[0];
    #pragma unroll
    for (int w = 1; w < 8; w++) mm = fmaxf(mm, red[w]);
    __syncthreads();
    float z = 0.f;
    for (int i = tid; i < cols; i += 256) z += __expf(s[i] - mm);
    #pragma unroll
    for (int o = 16; o; o >>= 1) z += __shfl_xor_sync(0xffffffffu, z, o);
    if ((tid & 31) == 0) red[tid >> 5] = z;
    __syncthreads();
    if (tid == 0) {
        float zz = 0.f;
        #pragma unroll
        for (int w = 0; w < 8; w++) zz += red[w];
        rowmax[row] = mm; rowz[row] = zz;
        atomicMax(wmax, __float_as_uint(1.0f / zz));
    }
}

// -------- cross-attn scores (fp32, M=77, stride 80; K source strided) --------
__global__ void __launch_bounds__(256) cross_scores_kernel(
    const float* __restrict__ q, const float* __restrict__ k, int kstride,
    float* __restrict__ S)
{
    __shared__ __align__(16) float Qs[64][68];
    __shared__ __align__(16) float Ks[80][68];
    int tid = threadIdx.x;
    int bh = blockIdx.y, b = bh / NH, h = bh % NH;
    int n0 = blockIdx.x * 64;
    #pragma unroll
    for (int it = 0; it < 4; ++it) {
        int r = (tid >> 4) + it * 16, c = (tid & 15) << 2;
        float4 qv = *(const float4*)(q + ((size_t)(b*NSEQ + n0 + r))*CDIM + h*DH + c);
        Qs[c+0][r]=qv.x; Qs[c+1][r]=qv.y; Qs[c+2][r]=qv.z; Qs[c+3][r]=qv.w;
    }
    #pragma unroll
    for (int it = 0; it < 5; ++it) {
        int lin = tid + it * 256;
        if (lin < 80 * 16) {
            int r = lin >> 4, c = (lin & 15) << 2;
            float4 kv = (r < MCTX) ? *(const float4*)(k + ((size_t)(b*MCTX + r))*kstride + h*DH + c)
                                   : make_float4(0.f,0.f,0.f,0.f);
            *(float4*)&Ks[r][c] = kv;
        }
    }
    __syncthreads();
    int tx = tid & 15, ty = tid >> 4;
    float acc[4][5];
    #pragma unroll
    for (int i = 0; i < 4; i++)
        #pragma unroll
        for (int j = 0; j < 5; j++) acc[i][j] = 0.f;
    #pragma unroll 4
    for (int d = 0; d < 64; ++d) {
        float4 q4 = *(const float4*)&Qs[d][ty*4];
        float qa[4]={q4.x,q4.y,q4.z,q4.w};
        #pragma unroll
        for (int jj = 0; jj < 5; jj++) {
            float kv = Ks[tx*5+jj][d];
            #pragma unroll
            for (int i = 0; i < 4; i++) acc[i][jj] = fmaf(qa[i], kv, acc[i][jj]);
        }
    }
    #pragma unroll
    for (int i = 0; i < 4; i++)
        #pragma unroll
        for (int jj = 0; jj < 5; jj++) {
            int m = tx * 5 + jj;
            if (m < MCTX)
                S[((size_t)bh*NSEQ + n0 + ty*4 + i)*80 + m] = acc[i][jj] * 0.125f;
        }
}

// -------- cross-attn PV (fp32; V source strided) --------
__global__ void __launch_bounds__(256) cross_pv_kernel(
    const float* __restrict__ S, const float* __restrict__ v, int vstride,
    const float* __restrict__ rowmax, const float* __restrict__ rowz,
    const unsigned* __restrict__ wmaxbits, float* __restrict__ O)
{
    __shared__ __align__(16) float Ws[80][68];
    __shared__ __align__(16) float Vs[80][68];
    int tid = threadIdx.x;
    int bh = blockIdx.y, b = bh / NH, h = bh % NH;
    int n0 = blockIdx.x * 64;
    int tx = tid & 15, ty = tid >> 4;
    float delta = fmaxf(__uint_as_float(*wmaxbits), 1e-8f) / 255.0f;
    float inv_delta = 1.0f / delta;
    #pragma unroll
    for (int it = 0; it < 5; ++it) {
        int lin = tid + it * 256;
        if (lin < MCTX * 16) {
            int r = lin >> 4, c = (lin & 15) << 2;
            *(float4*)&Vs[r][c] = *(const float4*)(v + ((size_t)(b*MCTX + r))*vstride + h*DH + c);
        }
    }
    #pragma unroll
    for (int it = 0; it < 4; ++it) {
        int r = (tid >> 4) + it * 16;
        float rm = rowmax[(size_t)bh*NSEQ + n0 + r];
        float ri = 1.0f / rowz[(size_t)bh*NSEQ + n0 + r];
        #pragma unroll
        for (int jj = 0; jj < 5; jj++) {
            int m = (tid & 15) * 5 + jj;
            float w = 0.f;
            if (m < MCTX) {
                float s = S[((size_t)bh*NSEQ + n0 + r)*80 + m];
                float p = __expf(s - rm);
                float l = rintf(p * ri * inv_delta);
                l = fminf(fmaxf(l, 0.f), 255.f);
                w = l * delta;
            }
            Ws[m][r] = w;
        }
    }
    __syncthreads();
    float acc[4][4];
    #pragma unroll
    for (int i = 0; i < 4; i++)
        #pragma unroll
        for (int j = 0; j < 4; j++) acc[i][j] = 0.f;
    for (int m = 0; m < MCTX; m++) {
        float4 w4 = *(const float4*)&Ws[m][ty*4];
        float4 v4 = *(const float4*)&Vs[m][tx*4];
        float wa[4]={w4.x,w4.y,w4.z,w4.w}, va[4]={v4.x,v4.y,v4.z,v4.w};
        #pragma unroll
        for (int i = 0; i < 4; i++)
            #pragma unroll
            for (int j = 0; j < 4; j++) acc[i][j] = fmaf(wa[i], va[j], acc[i][j]);
    }
    #pragma unroll
    for (int i = 0; i < 4; i++) {
        float4 o = {tf32r(acc[i][0]), tf32r(acc[i][1]), tf32r(acc[i][2]), tf32r(acc[i][3])};
        *(float4*)(O + ((size_t)(b*NSEQ + n0 + ty*4 + i))*CDIM + h*DH + tx*4) = o;
    }
}

// -------- GEGLU (tf32-rounded out) --------
__global__ void geglu_kernel(const float* __restrict__ Hh, float* __restrict__ G)
{
    size_t n4 = (size_t)ROWS * FFD / 4;
    size_t stride = (size_t)gridDim.x * blockDim.x;
    for (size_t i = (size_t)blockIdx.x * blockDim.x + threadIdx.x; i < n4; i += stride) {
        size_t col4 = i % (FFD / 4), row = i / (FFD / 4);
        float4 a4 = *(const float4*)(Hh + row * FF2D + col4 * 4);
        float4 g4 = *(const float4*)(Hh + row * FF2D + FFD + col4 * 4);
        float4 o;
        o.x = tf32r(a4.x * gelu_tanh(g4.x)); o.y = tf32r(a4.y * gelu_tanh(g4.y));
        o.z = tf32r(a4.z * gelu_tanh(g4.z)); o.w = tf32r(a4.w * gelu_tanh(g4.w));
        *(float4*)(G + i * 4) = o;
    }
}

extern "C" void kernel_launch(void* const* d_in, const int* in_sizes, int n_in,
                              void* d_out, int out_size)
{
    const float* x    = (const float*)d_in[0];
    const float* ctx  = (const float*)d_in[1];
    const float* ln1g = (const float*)d_in[2];
    const float* ln1b = (const float*)d_in[3];
    const float* ln2g = (const float*)d_in[4];
    const float* ln2b = (const float*)d_in[5];
    const float* ln3g = (const float*)d_in[6];
    const float* ln3b = (const float*)d_in[7];
    const float* Wq1  = (const float*)d_in[8];
    const float* Wk1  = (const float*)d_in[9];
    const float* Wv1  = (const float*)d_in[10];
    const float* Wo1  = (const float*)d_in[11];
    const float* bo1  = (const float*)d_in[12];
    const float* Wq2  = (const float*)d_in[13];
    const float* Wk2  = (const float*)d_in[14];
    const float* Wv2  = (const float*)d_in[15];
    const float* Wo2  = (const float*)d_in[16];
    const float* bo2  = (const float*)d_in[17];
    const float* Wff1 = (const float*)d_in[18];
    const float* bff1 = (const float*)d_in[19];
    const float* Wff2 = (const float*)d_in[20];
    const float* bff2 = (const float*)d_in[21];
    float* out = (float*)d_out;

    float* sc = nullptr;
    cudaGetSymbolAddress((void**)&sc, g_scratch);
    float* XN  = sc + OFF_XN;
    float* QKV = sc + OFF_Q;
    float* Qc  = sc + OFF_Q;
    float* KV2 = sc + OFF_K;
    float* O   = sc + OFF_O;
    float* X1  = sc + OFF_X1;
    float* S   = sc + OFF_S;
    float* Hb  = sc + OFF_H;
    float* G   = sc + OFF_G;
    float* RM  = sc + OFF_RM;
    float* RZ  = sc + OFF_RZ;
    unsigned* AM = (unsigned*)(sc + OFF_AM);
    float* cWqkv = sc + OFF_WQKV;
    float* cWo1  = sc + OFF_WO1;
    float* cWq2  = sc + OFF_WQ2;
    float* cWo2  = sc + OFF_WO2;
    float* cWkv2 = sc + OFF_WKV2;
    float* cWf1  = sc + OFF_WF1;
    float* cWf2  = sc + OFF_WF2;
    float* cCtx  = sc + OFF_CTX;
    int8_t* LQ8 = (int8_t*)(sc + OFF_LQ8);
    int8_t* LK8 = (int8_t*)(sc + OFF_LK8);
    int8_t* LVT = (int8_t*)(sc + OFF_LVT);

    dim3 g1280(CDIM / 128, ROWS / 128);
    dim3 gqkv(QKVN / 128, ROWS / 128);
    dim3 gkv2(KV2N / 128, (CROSSROWS + 127) / 128);
    dim3 gff1(FF2D / 128, ROWS / 128);
    long long n4 = (long long)ROWS * CDIM / 4;

    init_amax_kernel<<<1, 32>>>(AM);

    conv_pack_kernel<<<512,256>>>(Wq1, cWqkv + 0,      CDIM, CDIM, QKVN);
    conv_pack_kernel<<<512,256>>>(Wk1, cWqkv + CDIM,   CDIM, CDIM, QKVN);
    conv_pack_kernel<<<512,256>>>(Wv1, cWqkv + 2*CDIM, CDIM, CDIM, QKVN);
    conv_pack_kernel<<<512,256>>>(Wk2, cWkv2 + 0,    CTXC, CDIM, KV2N);
    conv_pack_kernel<<<512,256>>>(Wv2, cWkv2 + CDIM, CTXC, CDIM, KV2N);
    conv_tf32_kernel<<<1024,256>>>(Wo1,  cWo1, (long long)SZ_W1/4);
    conv_tf32_kernel<<<1024,256>>>(Wq2,  cWq2, (long long)SZ_W1/4);
    conv_tf32_kernel<<<1024,256>>>(Wo2,  cWo2, (long long)SZ_W1/4);
    conv_tf32_kernel<<<2048,256>>>(Wff1, cWf1, (long long)SZ_WF1/4);
    conv_tf32_kernel<<<2048,256>>>(Wff2, cWf2, (long long)SZ_WF2/4);
    conv_tf32_kernel<<<512,256>>>(ctx,   cCtx, (long long)SZ_CTXB/4);

    // ---- block 1: self attention (fused flash-style int8 path, no S tensor) ----
    ln_kernel<<<ROWS, 256>>>(x, ln1g, ln1b, XN);
    tgemm_kernel<false,false,true,true><<<gqkv,256>>>(XN, cWqkv, QKV, ROWS, QKVN, CDIM, nullptr, nullptr, AM+0);
    quant_s8_strided<<<1024,256>>>(QKV + 0,    LQ8, AM+0);
    quant_s8_strided<<<1024,256>>>(QKV + CDIM, LK8, AM+1);
    quant_v_t_kernel<<<dim3(NSEQ/64, BHD),256>>>(QKV + 2*CDIM, LVT, AM+2);
    self_stats_i8_kernel<<<dim3(8,BHD),256>>>(LQ8, LK8, RM, RZ, AM);
    self_pv_i8_kernel<<<dim3(8,BHD),256>>>(LQ8, LK8, LVT, RM, RZ, AM, O);
    tgemm_kernel<true,true,false,false><<<g1280,256>>>(O, cWo1, X1, ROWS, CDIM, CDIM, bo1, x, nullptr);

    // ---- block 2: cross attention ----
    ln_kernel<<<ROWS,256>>>(X1, ln2g, ln2b, XN);
    tgemm_kernel<false,false,true,false><<<g1280,256>>>(XN, cWq2, Qc, ROWS, CDIM, CDIM, nullptr, nullptr, AM+4);
    tgemm_kernel<false,false,true,true><<<gkv2,256>>>(cCtx, cWkv2, KV2, CROSSROWS, KV2N, CTXC, nullptr, nullptr, AM+5);
    quant_sym_kernel<<<2048,256>>>(Qc, n4, AM+4);
    quant_kv2_kernel<<<1024,256>>>(KV2, AM+5);
    cross_scores_kernel<<<dim3(16,BHD),256>>>(Qc, KV2, KV2N, S);
    softmax_stats_kernel<<<BHD*NSEQ,256>>>(S, RM, RZ, AM+7, MCTX, 80);
    cross_pv_kernel<<<dim3(16,BHD),256>>>(S, KV2 + CDIM, KV2N, RM, RZ, AM+7, O);
    tgemm_kernel<true,true,false,false><<<g1280,256>>>(O, cWo2, X1, ROWS, CDIM, CDIM, bo2, X1, nullptr);

    // ---- block 3: GEGLU FF ----
    ln_kernel<<<ROWS,256>>>(X1, ln3g, ln3b, XN);
    tgemm_kernel<true,false,false,false><<<gff1,256>>>(XN, cWf1, Hb, ROWS, FF2D, CDIM, bff1, nullptr, nullptr);
    geglu_kernel<<<4096,256>>>(Hb, G);
    tgemm_kernel<true,true,false,false><<<g1280,256>>>(G, cWf2, out, ROWS, CDIM, FFD, bff2, X1, nullptr);
}

// round 11
// speedup vs baseline: 1.2258x; 1.0215x over previous
#include <cuda_runtime.h>
#include <cstdint>

#define NB 8
#define NSEQ 1024
#define CDIM 1280
#define NH 20
#define DH 64
#define MCTX 77
#define CTXC 768
#define FFD 5120
#define FF2D 10240
#define ROWS (NB*NSEQ)
#define BHD (NB*NH)
#define CROSSROWS (NB*MCTX)
#define QKVN 3840
#define KV2N 2560

static constexpr size_t SZ_XC = (size_t)ROWS * CDIM;
static constexpr size_t OFF_XN = 0;
static constexpr size_t OFF_Q  = OFF_XN + SZ_XC;     // QKV fused buffer [ROWS][3840]
static constexpr size_t OFF_K  = OFF_Q + SZ_XC;      // cross-phase: KV2 [616][2560]
static constexpr size_t OFF_V  = OFF_K + SZ_XC;
static constexpr size_t OFF_O  = OFF_V + SZ_XC;
static constexpr size_t OFF_X1 = OFF_O + SZ_XC;
static constexpr size_t OFF_S  = OFF_X1 + SZ_XC;     // cross scores only
static constexpr size_t SZ_S   = (size_t)BHD * NSEQ * 80;
static constexpr size_t OFF_H  = OFF_S + SZ_S;
static constexpr size_t SZ_H   = (size_t)ROWS * FF2D;
static constexpr size_t OFF_G  = OFF_H + SZ_H;
static constexpr size_t SZ_G   = (size_t)ROWS * FFD;
static constexpr size_t OFF_RM = OFF_G + SZ_G;
static constexpr size_t OFF_RZ = OFF_RM + (size_t)BHD * NSEQ;
static constexpr size_t OFF_AM = OFF_RZ + (size_t)BHD * NSEQ;
static constexpr size_t SZ_W1  = (size_t)CDIM * CDIM;
static constexpr size_t SZ_WK2 = (size_t)CTXC * CDIM;
static constexpr size_t SZ_WF1 = (size_t)CDIM * FF2D;
static constexpr size_t SZ_WF2 = (size_t)FFD * CDIM;
static constexpr size_t SZ_CTXB = (size_t)CROSSROWS * CTXC;
static constexpr size_t OFF_WQKV = OFF_AM + 8;
static constexpr size_t OFF_WO1  = OFF_WQKV + 3 * SZ_W1;
static constexpr size_t OFF_WQ2  = OFF_WO1 + SZ_W1;
static constexpr size_t OFF_WO2  = OFF_WQ2 + SZ_W1;
static constexpr size_t OFF_WKV2 = OFF_WO2 + SZ_W1;
static constexpr size_t OFF_WF1  = OFF_WKV2 + 2 * SZ_WK2;
static constexpr size_t OFF_WF2  = OFF_WF1 + SZ_WF1;
static constexpr size_t OFF_CTX  = OFF_WF2 + SZ_WF2;
static constexpr size_t SZ_S8F   = (size_t)ROWS * CDIM / 4;
static constexpr size_t OFF_LQ8  = OFF_CTX + SZ_CTXB;
static constexpr size_t OFF_LK8  = OFF_LQ8 + SZ_S8F;
static constexpr size_t OFF_LVT  = OFF_LK8 + SZ_S8F;
static constexpr size_t TOTAL_SCRATCH = OFF_LVT + SZ_S8F;

__device__ __align__(256) float g_scratch[TOTAL_SCRATCH];

__global__ void init_amax_kernel(unsigned* amax) {
    if (threadIdx.x < 8) amax[threadIdx.x] = 0u;
}

__device__ __forceinline__ float gelu_tanh(float x) {
    float x3 = x * x * x;
    return 0.5f * x * (1.0f + tanhf(0.7978845608028654f * (x + 0.044715f * x3)));
}

__device__ __forceinline__ uint32_t f2tf32(float f) {
    uint32_t r;
    asm("cvt.rna.tf32.f32 %0, %1;" : "=r"(r) : "f"(f));
    return r;
}
__device__ __forceinline__ float tf32r(float f) { return __uint_as_float(f2tf32(f)); }

__device__ __forceinline__ void mma_tf32(float* d, const uint32_t* a, const uint32_t* b) {
    asm volatile("mma.sync.aligned.m16n8k8.row.col.f32.tf32.tf32.f32 "
        "{%0,%1,%2,%3}, {%4,%5,%6,%7}, {%8,%9}, {%0,%1,%2,%3};"
        : "+f"(d[0]), "+f"(d[1]), "+f"(d[2]), "+f"(d[3])
        : "r"(a[0]), "r"(a[1]), "r"(a[2]), "r"(a[3]), "r"(b[0]), "r"(b[1]));
}

__device__ __forceinline__ void mma_s8(int* d, const uint32_t* a, const uint32_t* b) {
    asm volatile("mma.sync.aligned.m16n8k32.row.col.s32.s8.s8.s32 "
        "{%0,%1,%2,%3}, {%4,%5,%6,%7}, {%8,%9}, {%0,%1,%2,%3};"
        : "+r"(d[0]), "+r"(d[1]), "+r"(d[2]), "+r"(d[3])
        : "r"(a[0]), "r"(a[1]), "r"(a[2]), "r"(a[3]), "r"(b[0]), "r"(b[1]));
}

__device__ __forceinline__ void mma_u8s8(int* d, const uint32_t* a, const uint32_t* b) {
    asm volatile("mma.sync.aligned.m16n8k32.row.col.s32.u8.s8.s32 "
        "{%0,%1,%2,%3}, {%4,%5,%6,%7}, {%8,%9}, {%0,%1,%2,%3};"
        : "+r"(d[0]), "+r"(d[1]), "+r"(d[2]), "+r"(d[3])
        : "r"(a[0]), "r"(a[1]), "r"(a[2]), "r"(a[3]), "r"(b[0]), "r"(b[1]));
}

__device__ __forceinline__ void ldsm4(uint32_t& r0, uint32_t& r1, uint32_t& r2, uint32_t& r3,
                                      uint32_t addr) {
    asm volatile("ldmatrix.sync.aligned.m8n8.x4.shared.b16 {%0,%1,%2,%3}, [%4];"
        : "=r"(r0), "=r"(r1), "=r"(r2), "=r"(r3) : "r"(addr));
}

__device__ __forceinline__ void cp_async16(uint32_t dst, const void* src, int srcsize) {
    asm volatile("cp.async.cg.shared.global [%0], [%1], 16, %2;"
                 :: "r"(dst), "l"(src), "r"(srcsize));
}

__device__ __forceinline__ int clamp_i(int v, int lo, int hi) {
    return v < lo ? lo : (v > hi ? hi : v);
}

__device__ __forceinline__ uint32_t pack_s8x4(float4 v, float inv) {
    int a = clamp_i(__float2int_rn(v.x * inv), -128, 127);
    int b = clamp_i(__float2int_rn(v.y * inv), -128, 127);
    int c = clamp_i(__float2int_rn(v.z * inv), -128, 127);
    int d = clamp_i(__float2int_rn(v.w * inv), -128, 127);
    return (a & 255) | ((b & 255) << 8) | ((c & 255) << 16) | ((d & 255) << 24);
}

// -------- tf32 convert (contiguous) --------
__global__ void conv_tf32_kernel(const float* __restrict__ src, float* __restrict__ dst,
                                 long long n4)
{
    long long stride = (long long)gridDim.x * blockDim.x;
    for (long long i = (long long)blockIdx.x * blockDim.x + threadIdx.x; i < n4; i += stride) {
        float4 v = *(const float4*)(src + i * 4);
        v.x = tf32r(v.x); v.y = tf32r(v.y); v.z = tf32r(v.z); v.w = tf32r(v.w);
        *(float4*)(dst + i * 4) = v;
    }
}

// -------- tf32 convert + column-pack --------
__global__ void conv_pack_kernel(const float* __restrict__ src, float* __restrict__ dst,
                                 int Kn, int Nn, int dstStride)
{
    long long n4 = (long long)Kn * Nn / 4;
    long long stride = (long long)gridDim.x * blockDim.x;
    for (long long i = (long long)blockIdx.x * blockDim.x + threadIdx.x; i < n4; i += stride) {
        long long e = i * 4;
        int row = (int)(e / Nn), col = (int)(e % Nn);
        float4 v = *(const float4*)(src + e);
        v.x = tf32r(v.x); v.y = tf32r(v.y); v.z = tf32r(v.z); v.w = tf32r(v.w);
        *(float4*)(dst + (size_t)row * dstStride + col) = v;
    }
}

// ---------------- LayerNorm (tf32-rounded out) ----------------
__global__ void ln_kernel(const float* __restrict__ x, const float* __restrict__ g,
                          const float* __restrict__ bta, float* __restrict__ out)
{
    __shared__ float sx[CDIM];
    __shared__ float red[8];
    int row = blockIdx.x, tid = threadIdx.x;
    const float* xr = x + (size_t)row * CDIM;
    float s = 0.f;
    for (int i = tid; i < CDIM; i += 256) { float v = xr[i]; sx[i] = v; s += v; }
    #pragma unroll
    for (int o = 16; o; o >>= 1) s += __shfl_xor_sync(0xffffffffu, s, o);
    if ((tid & 31) == 0) red[tid >> 5] = s;
    __syncthreads();
    float tot = 0.f;
    #pragma unroll
    for (int w = 0; w < 8; w++) tot += red[w];
    float mean = tot * (1.0f / (float)CDIM);
    float vs = 0.f;
    for (int i = tid; i < CDIM; i += 256) { float d = sx[i] - mean; vs += d * d; }
    __syncthreads();
    #pragma unroll
    for (int o = 16; o; o >>= 1) vs += __shfl_xor_sync(0xffffffffu, vs, o);
    if ((tid & 31) == 0) red[tid >> 5] = vs;
    __syncthreads();
    float tot2 = 0.f;
    #pragma unroll
    for (int w = 0; w < 8; w++) tot2 += red[w];
    float rstd = rsqrtf(tot2 * (1.0f / (float)CDIM) + 1e-5f);
    for (int i = tid; i < CDIM; i += 256)
        out[(size_t)row * CDIM + i] = tf32r((sx[i] - mean) * rstd * g[i] + bta[i]);
}

// ============ TF32 GEMM: 4-stage cp.async, ONE barrier per TWO ktiles ============
template<bool HAS_BIAS, bool HAS_RES, bool DO_AMAX, bool SEG>
__global__ void __launch_bounds__(256, 2) tgemm_kernel(
    const float* __restrict__ A, const float* __restrict__ Bm, float* __restrict__ Cm,
    int Mn, int Nn, int Kn,
    const float* __restrict__ bias, const float* __restrict__ res, unsigned* amax)
{
    constexpr int ST = 4;
    constexpr uint32_t ABYTES = 128 * 20 * 4;
    constexpr uint32_t BBYTES = 16 * 136 * 4;
    __shared__ __align__(16) uint32_t As[ST][128][20];
    __shared__ __align__(16) float    Bs[ST][16][136];
    __shared__ float reds[8];

    int tid  = threadIdx.x;
    int lane = tid & 31;
    int warp = tid >> 5;
    int wm = warp & 1;
    int wn = warp >> 1;
    int nBase = blockIdx.x * 128;
    int mBase = blockIdx.y * 128;

    uint32_t asmb = (uint32_t)__cvta_generic_to_shared(&As[0][0][0]);
    uint32_t bsmb = (uint32_t)__cvta_generic_to_shared(&Bs[0][0][0]);

    const int aR0 = tid >> 2;
    const int aC  = (tid & 3) << 2;
    const int bK0 = tid >> 5;
    const int bN  = (tid & 31) << 2;

    int r8 = lane & 7, sel = lane >> 3;
    uint32_t aoff = asmb + (((wm * 64 + r8 + ((sel & 1) << 3)) * 20 + ((sel >> 1) << 2)) << 2);

    float acc[4][4][4];
    #pragma unroll
    for (int i = 0; i < 4; i++)
        #pragma unroll
        for (int j = 0; j < 4; j++)
            #pragma unroll
            for (int l = 0; l < 4; l++) acc[i][j][l] = 0.f;

    int KT = Kn >> 4;   // even for all shapes used (80, 48, 320)

    auto issue_stage = [&](int s, int k0) {
        #pragma unroll
        for (int i = 0; i < 2; i++) {
            int r = aR0 + i * 64;
            int gr = mBase + r;
            int ok = (gr < Mn);
            const float* src = A + (size_t)(ok ? gr : 0) * Kn + k0 + aC;
            cp_async16(asmb + s * ABYTES + ((r * 20 + aC) << 2), src, ok ? 16 : 0);
        }
        #pragma unroll
        for (int i = 0; i < 2; i++) {
            int kr = bK0 + i * 8;
            const float* src = Bm + (size_t)(k0 + kr) * Nn + nBase + bN;
            cp_async16(bsmb + s * BBYTES + ((kr * 136 + bN) << 2), src, 16);
        }
        asm volatile("cp.async.commit_group;" ::: "memory");
    };

    issue_stage(0, 0);
    issue_stage(1, 16);

    int lr = lane >> 2, lc = lane & 3;
    for (int kt = 0; kt < KT; kt += 2) {
        asm volatile("cp.async.wait_group 0;" ::: "memory");
        __syncthreads();
        // buffers (kt+2)&3, (kt+3)&3 were computed BEFORE this barrier -> safe to refill
        if (kt + 2 < KT) {
            issue_stage((kt + 2) & 3, (kt + 2) << 4);
            issue_stage((kt + 3) & 3, (kt + 3) << 4);
        }
        #pragma unroll
        for (int sub = 0; sub < 2; sub++) {
            int buf = (kt + sub) & 3;
            uint32_t abuf = aoff + buf * ABYTES;
            #pragma unroll
            for (int ks = 0; ks < 2; ks++) {
                uint32_t af[4][4], bf[4][2];
                #pragma unroll
                for (int mt = 0; mt < 4; mt++)
                    ldsm4(af[mt][0], af[mt][1], af[mt][2], af[mt][3],
                          abuf + mt * (16 * 20 * 4) + ks * 32);
                #pragma unroll
                for (int nt = 0; nt < 4; nt++) {
                    int col = wn * 32 + nt * 8 + lr;
                    bf[nt][0] = __float_as_uint(Bs[buf][ks * 8 + lc][col]);
                    bf[nt][1] = __float_as_uint(Bs[buf][ks * 8 + lc + 4][col]);
                }
                #pragma unroll
                for (int mt = 0; mt < 4; mt++)
                    #pragma unroll
                    for (int nt = 0; nt < 4; nt++)
                        mma_tf32(acc[mt][nt], af[mt], bf[nt]);
            }
        }
    }

    float amx = 0.f;
    #pragma unroll
    for (int mt = 0; mt < 4; mt++) {
        #pragma unroll
        for (int nt = 0; nt < 4; nt++) {
            int row0 = mBase + wm * 64 + mt * 16 + lr;
            int col0 = nBase + wn * 32 + nt * 8 + lc * 2;
            #pragma unroll
            for (int half = 0; half < 2; half++) {
                int row = row0 + half * 8;
                if (row < Mn) {
                    float c0 = acc[mt][nt][half * 2 + 0];
                    float c1 = acc[mt][nt][half * 2 + 1];
                    if (HAS_BIAS) { c0 += bias[col0]; c1 += bias[col0 + 1]; }
                    if (HAS_RES) {
                        c0 += res[(size_t)row * Nn + col0];
                        c1 += res[(size_t)row * Nn + col0 + 1];
                    }
                    float2 o = {c0, c1};
                    *(float2*)(Cm + (size_t)row * Nn + col0) = o;
                    if (DO_AMAX) amx = fmaxf(amx, fmaxf(fabsf(c0), fabsf(c1)));
                }
            }
        }
    }
    if (DO_AMAX) {
        #pragma unroll
        for (int o = 16; o; o >>= 1) amx = fmaxf(amx, __shfl_xor_sync(0xffffffffu, amx, o));
        if (lane == 0) reds[warp] = amx;
        __syncthreads();
        if (tid == 0) {
            float m = reds[0];
            #pragma unroll
            for (int w = 1; w < 8; w++) m = fmaxf(m, reds[w]);
            unsigned* tgt = amax + (SEG ? (nBase / 1280) : 0);
            atomicMax(tgt, __float_as_uint(m));
        }
    }
}

// -------- fp32 fake-quant in place (contiguous; cross Q) --------
__global__ void quant_sym_kernel(float* __restrict__ x, long long n4,
                                 const unsigned* __restrict__ amaxbits)
{
    float delta = fmaxf(__uint_as_float(*amaxbits), 1e-8f) / 127.0f;
    long long stride = (long long)gridDim.x * blockDim.x;
    for (long long i = (long long)blockIdx.x * blockDim.x + threadIdx.x; i < n4; i += stride) {
        float4 v = *(float4*)(x + i * 4);
        float l;
        l = rintf(v.x/delta); l = fminf(fmaxf(l,-128.f),127.f); v.x = l*delta;
        l = rintf(v.y/delta); l = fminf(fmaxf(l,-128.f),127.f); v.y = l*delta;
        l = rintf(v.z/delta); l = fminf(fmaxf(l,-128.f),127.f); v.z = l*delta;
        l = rintf(v.w/delta); l = fminf(fmaxf(l,-128.f),127.f); v.w = l*delta;
        *(float4*)(x + i * 4) = v;
    }
}

// -------- fp32 fake-quant, two column segments (cross K|V fused) --------
__global__ void quant_kv2_kernel(float* __restrict__ x, const unsigned* __restrict__ am)
{
    float d0 = fmaxf(__uint_as_float(am[0]), 1e-8f) / 127.0f;
    float d1 = fmaxf(__uint_as_float(am[1]), 1e-8f) / 127.0f;
    long long n4 = (long long)CROSSROWS * KV2N / 4;
    long long stride = (long long)gridDim.x * blockDim.x;
    for (long long i = (long long)blockIdx.x * blockDim.x + threadIdx.x; i < n4; i += stride) {
        int col = (int)((i * 4) % KV2N);
        float delta = (col < CDIM) ? d0 : d1;
        float4 v = *(float4*)(x + i * 4);
        float l;
        l = rintf(v.x/delta); l = fminf(fmaxf(l,-128.f),127.f); v.x = l*delta;
        l = rintf(v.y/delta); l = fminf(fmaxf(l,-128.f),127.f); v.y = l*delta;
        l = rintf(v.z/delta); l = fminf(fmaxf(l,-128.f),127.f); v.z = l*delta;
        l = rintf(v.w/delta); l = fminf(fmaxf(l,-128.f),127.f); v.w = l*delta;
        *(float4*)(x + i * 4) = v;
    }
}

// -------- s8 level quant from strided source --------
__global__ void quant_s8_strided(const float* __restrict__ x, int8_t* __restrict__ L,
                                 const unsigned* __restrict__ amaxbits)
{
    float delta = fmaxf(__uint_as_float(*amaxbits), 1e-8f) / 127.0f;
    float inv = 1.0f / delta;
    long long n16 = (long long)ROWS * (CDIM / 16);
    long long stride = (long long)gridDim.x * blockDim.x;
    for (long long i = (long long)blockIdx.x * blockDim.x + threadIdx.x; i < n16; i += stride) {
        int row = (int)(i / (CDIM / 16));
        int c16 = (int)(i % (CDIM / 16));
        const float4* p = (const float4*)(x + (size_t)row * QKVN + c16 * 16);
        uint4 o;
        o.x = pack_s8x4(p[0], inv);
        o.y = pack_s8x4(p[1], inv);
        o.z = pack_s8x4(p[2], inv);
        o.w = pack_s8x4(p[3], inv);
        *(uint4*)(L + i * 16) = o;
    }
}

// -------- V quant + per-head transpose (strided source) --------
__global__ void __launch_bounds__(256) quant_v_t_kernel(const float* __restrict__ V,
                                                        int8_t* __restrict__ LVT,
                                                        const unsigned* __restrict__ amaxbits)
{
    __shared__ int8_t T[64][80];
    float delta = fmaxf(__uint_as_float(*amaxbits), 1e-8f) / 127.0f;
    float inv = 1.0f / delta;
    int tid = threadIdx.x;
    int bh = blockIdx.y, b = bh / NH, h = bh % NH;
    int m0 = blockIdx.x * 64;
    #pragma unroll
    for (int i = 0; i < 4; i++) {
        int lin = tid + i * 256;
        int r = lin >> 4;
        int c4 = (lin & 15) << 2;
        float4 v = *(const float4*)(V + ((size_t)(b*NSEQ + m0 + r))*QKVN + h*DH + c4);
        T[c4+0][r] = (int8_t)clamp_i(__float2int_rn(v.x*inv), -128, 127);
        T[c4+1][r] = (int8_t)clamp_i(__float2int_rn(v.y*inv), -128, 127);
        T[c4+2][r] = (int8_t)clamp_i(__float2int_rn(v.z*inv), -128, 127);
        T[c4+3][r] = (int8_t)clamp_i(__float2int_rn(v.w*inv), -128, 127);
    }
    __syncthreads();
    int d = tid >> 2, ch = (tid & 3) << 4;
    int4 val = *(int4*)&T[d][ch];
    *(int4*)(LVT + ((size_t)(bh*DH + d))*NSEQ + m0 + ch) = val;
}

// ======== FUSED self-attn stats: recompute scores, online softmax ========
__global__ void __launch_bounds__(256) self_stats_i8_kernel(
    const int8_t* __restrict__ LQ, const int8_t* __restrict__ LK,
    float* __restrict__ RM, float* __restrict__ RZ, unsigned* __restrict__ am)
{
    __shared__ __align__(16) int8_t Qs[128][80];
    __shared__ __align__(16) int8_t Ks[128][80];
    __shared__ float red[128][4];
    __shared__ float tmaxS[128];
    __shared__ float rowmS[128], rowzS[128];
    __shared__ float wred[8];
    float dq = fmaxf(__uint_as_float(am[0]), 1e-8f) / 127.0f;
    float dk = fmaxf(__uint_as_float(am[1]), 1e-8f) / 127.0f;
    float scale = dq * dk * 0.125f;
    int tid = threadIdx.x, lane = tid & 31, warp = tid >> 5;
    int bh = blockIdx.y, b = bh / NH, h = bh % NH;
    int n0 = blockIdx.x * 128;
    int wn = warp & 1, wm = warp >> 1;
    int gr = lane >> 2, gc = lane & 3;

    #pragma unroll
    for (int i = 0; i < 2; i++) {
        int lin = tid + i * 256;
        int r = lin >> 2, ch = (lin & 3) << 4;
        *(int4*)&Qs[r][ch] = *(const int4*)(LQ + ((size_t)(b*NSEQ + n0 + r))*CDIM + h*DH + ch);
    }
    if (tid < 128) { rowmS[tid] = -3.4e38f; rowzS[tid] = 0.f; }

    int rows[8];
    #pragma unroll
    for (int nt = 0; nt < 4; nt++)
        #pragma unroll
        for (int half = 0; half < 2; half++)
            rows[nt*2+half] = wn*64 + nt*16 + gr + half*8;

    for (int mc = 0; mc < 8; mc++) {
        __syncthreads();
        #pragma unroll
        for (int i = 0; i < 2; i++) {
            int lin = tid + i * 256;
            int r = lin >> 2, ch = (lin & 3) << 4;
            *(int4*)&Ks[r][ch] = *(const int4*)(LK + ((size_t)(b*NSEQ + mc*128 + r))*CDIM + h*DH + ch);
        }
        __syncthreads();

        int acc[4][4][4];
        #pragma unroll
        for (int i = 0; i < 4; i++)
            #pragma unroll
            for (int j = 0; j < 4; j++)
                #pragma unroll
                for (int l = 0; l < 4; l++) acc[i][j][l] = 0;
        #pragma unroll
        for (int ks = 0; ks < 2; ks++) {
            uint32_t af[4][4], bf[4][2];
            #pragma unroll
            for (int nt = 0; nt < 4; nt++) {
                int row = wn * 64 + nt * 16 + gr;
                af[nt][0] = *(const uint32_t*)&Qs[row][ks*32 + gc*4];
                af[nt][1] = *(const uint32_t*)&Qs[row + 8][ks*32 + gc*4];
                af[nt][2] = *(const uint32_t*)&Qs[row][ks*32 + 16 + gc*4];
                af[nt][3] = *(const uint32_t*)&Qs[row + 8][ks*32 + 16 + gc*4];
            }
            #pragma unroll
            for (int mt = 0; mt < 4; mt++) {
                int col = wm * 32 + mt * 8 + gr;
                bf[mt][0] = *(const uint32_t*)&Ks[col][ks*32 + gc*4];
                bf[mt][1] = *(const uint32_t*)&Ks[col][ks*32 + 16 + gc*4];
            }
            #pragma unroll
            for (int nt = 0; nt < 4; nt++)
                #pragma unroll
                for (int mt = 0; mt < 4; mt++)
                    mma_s8(acc[nt][mt], af[nt], bf[mt]);
        }

        float lmax[8];
        #pragma unroll
        for (int j = 0; j < 8; j++) lmax[j] = -3.4e38f;
        #pragma unroll
        for (int nt = 0; nt < 4; nt++)
            #pragma unroll
            for (int mt = 0; mt < 4; mt++)
                #pragma unroll
                for (int c = 0; c < 4; c++)
                    lmax[nt*2 + (c>>1)] = fmaxf(lmax[nt*2 + (c>>1)], scale*(float)acc[nt][mt][c]);
        #pragma unroll
        for (int j = 0; j < 8; j++) {
            lmax[j] = fmaxf(lmax[j], __shfl_xor_sync(0xffffffffu, lmax[j], 1));
            lmax[j] = fmaxf(lmax[j], __shfl_xor_sync(0xffffffffu, lmax[j], 2));
        }
        if (gc == 0) {
            #pragma unroll
            for (int j = 0; j < 8; j++) red[rows[j]][wm] = lmax[j];
        }
        __syncthreads();
        if (tid < 128)
            tmaxS[tid] = fmaxf(fmaxf(red[tid][0], red[tid][1]), fmaxf(red[tid][2], red[tid][3]));
        __syncthreads();

        float lsum[8];
        #pragma unroll
        for (int j = 0; j < 8; j++) lsum[j] = 0.f;
        #pragma unroll
        for (int nt = 0; nt < 4; nt++) {
            float tm0 = tmaxS[rows[nt*2]];
            float tm1 = tmaxS[rows[nt*2+1]];
            #pragma unroll
            for (int mt = 0; mt < 4; mt++) {
                lsum[nt*2]   += __expf(scale*(float)acc[nt][mt][0] - tm0)
                              + __expf(scale*(float)acc[nt][mt][1] - tm0);
                lsum[nt*2+1] += __expf(scale*(float)acc[nt][mt][2] - tm1)
                              + __expf(scale*(float)acc[nt][mt][3] - tm1);
            }
        }
        #pragma unroll
        for (int j = 0; j < 8; j++) {
            lsum[j] += __shfl_xor_sync(0xffffffffu, lsum[j], 1);
            lsum[j] += __shfl_xor_sync(0xffffffffu, lsum[j], 2);
        }
        if (gc == 0) {
            #pragma unroll
            for (int j = 0; j < 8; j++) red[rows[j]][wm] = lsum[j];
        }
        __syncthreads();
        if (tid < 128) {
            float ts = red[tid][0] + red[tid][1] + red[tid][2] + red[tid][3];
            float tm = tmaxS[tid];
            float om = rowmS[tid];
            float nm = fmaxf(om, tm);
            rowzS[tid] = rowzS[tid] * __expf(om - nm) + ts * __expf(tm - nm);
            rowmS[tid] = nm;
        }
    }
    __syncthreads();
    float invz = -3.4e38f;
    if (tid < 128) {
        float z = rowzS[tid];
        RM[(size_t)bh*NSEQ + n0 + tid] = rowmS[tid];
        RZ[(size_t)bh*NSEQ + n0 + tid] = z;
        invz = 1.0f / z;
    }
    #pragma unroll
    for (int o = 16; o; o >>= 1) invz = fmaxf(invz, __shfl_xor_sync(0xffffffffu, invz, o));
    if (lane == 0) wred[warp] = invz;
    __syncthreads();
    if (tid == 0) {
        float m = wred[0];
        #pragma unroll
        for (int w = 1; w < 8; w++) m = fmaxf(m, wred[w]);
        atomicMax(am + 3, __float_as_uint(m));
    }
}

// ======== FUSED self-attn PV: recompute scores, fq_zero, u8xs8 PV ========
__global__ void __launch_bounds__(256) self_pv_i8_kernel(
    const int8_t* __restrict__ LQ, const int8_t* __restrict__ LK,
    const int8_t* __restrict__ LVT,
    const float* __restrict__ RM, const float* __restrict__ RZ,
    const unsigned* __restrict__ am, float* __restrict__ O)
{
    __shared__ __align__(16) int8_t  Qs[128][80];
    __shared__ __align__(16) int8_t  Ks[128][80];
    __shared__ __align__(16) uint8_t Lws[128][144];
    __shared__ __align__(16) int8_t  VTs[64][144];
    __shared__ float rmS[128], riS[128];
    float dq = fmaxf(__uint_as_float(am[0]), 1e-8f) / 127.0f;
    float dk = fmaxf(__uint_as_float(am[1]), 1e-8f) / 127.0f;
    float scale = dq * dk * 0.125f;
    float dv = fmaxf(__uint_as_float(am[2]), 1e-8f) / 127.0f;
    float dw = fmaxf(__uint_as_float(am[3]), 1e-8f) / 255.0f;
    float inv_dw = 1.0f / dw;
    float oscale = dw * dv;
    int tid = threadIdx.x, lane = tid & 31, warp = tid >> 5;
    int bh = blockIdx.y, b = bh / NH, h = bh % NH;
    int n0 = blockIdx.x * 128;
    int wn = warp & 1, wm = warp >> 1, wd = warp >> 1;
    int gr = lane >> 2, gc = lane & 3;

    #pragma unroll
    for (int i = 0; i < 2; i++) {
        int lin = tid + i * 256;
        int r = lin >> 2, ch = (lin & 3) << 4;
        *(int4*)&Qs[r][ch] = *(const int4*)(LQ + ((size_t)(b*NSEQ + n0 + r))*CDIM + h*DH + ch);
    }
    if (tid < 128) {
        rmS[tid] = RM[(size_t)bh*NSEQ + n0 + tid];
        riS[tid] = 1.0f / RZ[(size_t)bh*NSEQ + n0 + tid];
    }

    int acc[4][2][4];
    #pragma unroll
    for (int i = 0; i < 4; i++)
        #pragma unroll
        for (int j = 0; j < 2; j++)
            #pragma unroll
            for (int l = 0; l < 4; l++) acc[i][j][l] = 0;

    for (int mc = 0; mc < 8; mc++) {
        __syncthreads();
        #pragma unroll
        for (int i = 0; i < 2; i++) {
            int lin = tid + i * 256;
            int r = lin >> 2, ch = (lin & 3) << 4;
            *(int4*)&Ks[r][ch] = *(const int4*)(LK + ((size_t)(b*NSEQ + mc*128 + r))*CDIM + h*DH + ch);
        }
        #pragma unroll
        for (int i = 0; i < 2; i++) {
            int lin = tid + i * 256;
            int d = lin >> 3, ch = (lin & 7) << 4;
            *(int4*)&VTs[d][ch] = *(const int4*)(LVT + ((size_t)(bh*DH + d))*NSEQ + mc*128 + ch);
        }
        __syncthreads();

        int sacc[4][4][4];
        #pragma unroll
        for (int i = 0; i < 4; i++)
            #pragma unroll
            for (int j = 0; j < 4; j++)
                #pragma unroll
                for (int l = 0; l < 4; l++) sacc[i][j][l] = 0;
        #pragma unroll
        for (int ks = 0; ks < 2; ks++) {
            uint32_t af[4][4], bf[4][2];
            #pragma unroll
            for (int nt = 0; nt < 4; nt++) {
                int row = wn * 64 + nt * 16 + gr;
                af[nt][0] = *(const uint32_t*)&Qs[row][ks*32 + gc*4];
                af[nt][1] = *(const uint32_t*)&Qs[row + 8][ks*32 + gc*4];
                af[nt][2] = *(const uint32_t*)&Qs[row][ks*32 + 16 + gc*4];
                af[nt][3] = *(const uint32_t*)&Qs[row + 8][ks*32 + 16 + gc*4];
            }
            #pragma unroll
            for (int mt = 0; mt < 4; mt++) {
                int col = wm * 32 + mt * 8 + gr;
                bf[mt][0] = *(const uint32_t*)&Ks[col][ks*32 + gc*4];
                bf[mt][1] = *(const uint32_t*)&Ks[col][ks*32 + 16 + gc*4];
            }
            #pragma unroll
            for (int nt = 0; nt < 4; nt++)
                #pragma unroll
                for (int mt = 0; mt < 4; mt++)
                    mma_s8(sacc[nt][mt], af[nt], bf[mt]);
        }
        #pragma unroll
        for (int nt = 0; nt < 4; nt++) {
            #pragma unroll
            for (int half = 0; half < 2; half++) {
                int row = wn*64 + nt*16 + gr + half*8;
                float rm = rmS[row];
                float f = riS[row] * inv_dw;
                #pragma unroll
                for (int mt = 0; mt < 4; mt++) {
                    int col = wm*32 + mt*8 + gc*2;
                    int l0 = min(255, __float2int_rn(__expf(scale*(float)sacc[nt][mt][half*2+0] - rm) * f));
                    int l1 = min(255, __float2int_rn(__expf(scale*(float)sacc[nt][mt][half*2+1] - rm) * f));
                    *(uint16_t*)&Lws[row][col] = (uint16_t)(l0 | (l1 << 8));
                }
            }
        }
        __syncthreads();

        #pragma unroll
        for (int ks = 0; ks < 4; ks++) {
            uint32_t af[4][4], bf[2][2];
            #pragma unroll
            for (int nt = 0; nt < 4; nt++) {
                int row = wn * 64 + nt * 16 + gr;
                af[nt][0] = *(const uint32_t*)&Lws[row][ks*32 + gc*4];
                af[nt][1] = *(const uint32_t*)&Lws[row + 8][ks*32 + gc*4];
                af[nt][2] = *(const uint32_t*)&Lws[row][ks*32 + 16 + gc*4];
                af[nt][3] = *(const uint32_t*)&Lws[row + 8][ks*32 + 16 + gc*4];
            }
            #pragma unroll
            for (int dt = 0; dt < 2; dt++) {
                int col = wd * 16 + dt * 8 + gr;
                bf[dt][0] = *(const uint32_t*)&VTs[col][ks*32 + gc*4];
                bf[dt][1] = *(const uint32_t*)&VTs[col][ks*32 + 16 + gc*4];
            }
            #pragma unroll
            for (int nt = 0; nt < 4; nt++)
                #pragma unroll
                for (int dt = 0; dt < 2; dt++)
                    mma_u8s8(acc[nt][dt], af[nt], bf[dt]);
        }
    }
    #pragma unroll
    for (int nt = 0; nt < 4; nt++) {
        #pragma unroll
        for (int dt = 0; dt < 2; dt++) {
            int row0 = n0 + wn * 64 + nt * 16 + gr;
            int col0 = wd * 16 + dt * 8 + gc * 2;
            #pragma unroll
            for (int half = 0; half < 2; half++) {
                int row = row0 + half * 8;
                float2 o = {tf32r(oscale * (float)acc[nt][dt][half*2+0]),
                            tf32r(oscale * (float)acc[nt][dt][half*2+1])};
                *(float2*)(O + ((size_t)(b*NSEQ + row))*CDIM + h*DH + col0) = o;
            }
        }
    }
}

// -------- softmax row stats (cross path) --------
__global__ void softmax_stats_kernel(const float* __restrict__ S, float* __restrict__ rowmax,
                                     float* __restrict__ rowz, unsigned* wmax, int cols, int stride)
{
    int row = blockIdx.x, tid = threadIdx.x;
    const float* s = S + (size_t)row * stride;
    __shared__ float red[8];
    float m = -3.4e38f;
    for (int i = tid; i < cols; i += 256) m = fmaxf(m, s[i]);
    #pragma unroll
    for (int o = 16; o; o >>= 1) m = fmaxf(m, __shfl_xor_sync(0xffffffffu, m, o));
    if ((tid & 31) == 0) red[tid >> 5] = m;
    __syncthreads();
    float mm = red[0];
    #pragma unroll
    for (int w = 1; w < 8; w++) mm = fmaxf(mm, red[w]);
    __syncthreads();
    float z = 0.f;
    for (int i = tid; i < cols; i += 256) z += __expf(s[i] - mm);
    #pragma unroll
    for (int o = 16; o; o >>= 1) z += __shfl_xor_sync(0xffffffffu, z, o);
    if ((tid & 31) == 0) red[tid >> 5] = z;
    __syncthreads();
    if (tid == 0) {
        float zz = 0.f;
        #pragma unroll
        for (int w = 0; w < 8; w++) zz += red[w];
        rowmax[row] = mm; rowz[row] = zz;
        atomicMax(wmax, __float_as_uint(1.0f / zz));
    }
}

// -------- cross-attn scores (fp32, M=77, stride 80; K source strided) --------
__global__ void __launch_bounds__(256) cross_scores_kernel(
    const float* __restrict__ q, const float* __restrict__ k, int kstride,
    float* __restrict__ S)
{
    __shared__ __align__(16) float Qs[64][68];
    __shared__ __align__(16) float Ks[80][68];
    int tid = threadIdx.x;
    int bh = blockIdx.y, b = bh / NH, h = bh % NH;
    int n0 = blockIdx.x * 64;
    #pragma unroll
    for (int it = 0; it < 4; ++it) {
        int r = (tid >> 4) + it * 16, c = (tid & 15) << 2;
        float4 qv = *(const float4*)(q + ((size_t)(b*NSEQ + n0 + r))*CDIM + h*DH + c);
        Qs[c+0][r]=qv.x; Qs[c+1][r]=qv.y; Qs[c+2][r]=qv.z; Qs[c+3][r]=qv.w;
    }
    #pragma unroll
    for (int it = 0; it < 5; ++it) {
        int lin = tid + it * 256;
        if (lin < 80 * 16) {
            int r = lin >> 4, c = (lin & 15) << 2;
            float4 kv = (r < MCTX) ? *(const float4*)(k + ((size_t)(b*MCTX + r))*kstride + h*DH + c)
                                   : make_float4(0.f,0.f,0.f,0.f);
            *(float4*)&Ks[r][c] = kv;
        }
    }
    __syncthreads();
    int tx = tid & 15, ty = tid >> 4;
    float acc[4][5];
    #pragma unroll
    for (int i = 0; i < 4; i++)
        #pragma unroll
        for (int j = 0; j < 5; j++) acc[i][j] = 0.f;
    #pragma unroll 4
    for (int d = 0; d < 64; ++d) {
        float4 q4 = *(const float4*)&Qs[d][ty*4];
        float qa[4]={q4.x,q4.y,q4.z,q4.w};
        #pragma unroll
        for (int jj = 0; jj < 5; jj++) {
            float kv = Ks[tx*5+jj][d];
            #pragma unroll
            for (int i = 0; i < 4; i++) acc[i][jj] = fmaf(qa[i], kv, acc[i][jj]);
        }
    }
    #pragma unroll
    for (int i = 0; i < 4; i++)
        #pragma unroll
        for (int jj = 0; jj < 5; jj++) {
            int m = tx * 5 + jj;
            if (m < MCTX)
                S[((size_t)bh*NSEQ + n0 + ty*4 + i)*80 + m] = acc[i][jj] * 0.125f;
        }
}

// -------- cross-attn PV (fp32; V source strided) --------
__global__ void __launch_bounds__(256) cross_pv_kernel(
    const float* __restrict__ S, const float* __restrict__ v, int vstride,
    const float* __restrict__ rowmax, const float* __restrict__ rowz,
    const unsigned* __restrict__ wmaxbits, float* __restrict__ O)
{
    __shared__ __align__(16) float Ws[80][68];
    __shared__ __align__(16) float Vs[80][68];
    int tid = threadIdx.x;
    int bh = blockIdx.y, b = bh / NH, h = bh % NH;
    int n0 = blockIdx.x * 64;
    int tx = tid & 15, ty = tid >> 4;
    float delta = fmaxf(__uint_as_float(*wmaxbits), 1e-8f) / 255.0f;
    float inv_delta = 1.0f / delta;
    #pragma unroll
    for (int it = 0; it < 5; ++it) {
        int lin = tid + it * 256;
        if (lin < MCTX * 16) {
            int r = lin >> 4, c = (lin & 15) << 2;
            *(float4*)&Vs[r][c] = *(const float4*)(v + ((size_t)(b*MCTX + r))*vstride + h*DH + c);
        }
    }
    #pragma unroll
    for (int it = 0; it < 4; ++it) {
        int r = (tid >> 4) + it * 16;
        float rm = rowmax[(size_t)bh*NSEQ + n0 + r];
        float ri = 1.0f / rowz[(size_t)bh*NSEQ + n0 + r];
        #pragma unroll
        for (int jj = 0; jj < 5; jj++) {
            int m = (tid & 15) * 5 + jj;
            float w = 0.f;
            if (m < MCTX) {
                float s = S[((size_t)bh*NSEQ + n0 + r)*80 + m];
                float p = __expf(s - rm);
                float l = rintf(p * ri * inv_delta);
                l = fminf(fmaxf(l, 0.f), 255.f);
                w = l * delta;
            }
            Ws[m][r] = w;
        }
    }
    __syncthreads();
    float acc[4][4];
    #pragma unroll
    for (int i = 0; i < 4; i++)
        #pragma unroll
        for (int j = 0; j < 4; j++) acc[i][j] = 0.f;
    for (int m = 0; m < MCTX; m++) {
        float4 w4 = *(const float4*)&Ws[m][ty*4];
        float4 v4 = *(const float4*)&Vs[m][tx*4];
        float wa[4]={w4.x,w4.y,w4.z,w4.w}, va[4]={v4.x,v4.y,v4.z,v4.w};
        #pragma unroll
        for (int i = 0; i < 4; i++)
            #pragma unroll
            for (int j = 0; j < 4; j++) acc[i][j] = fmaf(wa[i], va[j], acc[i][j]);
    }
    #pragma unroll
    for (int i = 0; i < 4; i++) {
        float4 o = {tf32r(acc[i][0]), tf32r(acc[i][1]), tf32r(acc[i][2]), tf32r(acc[i][3])};
        *(float4*)(O + ((size_t)(b*NSEQ + n0 + ty*4 + i))*CDIM + h*DH + tx*4) = o;
    }
}

// -------- GEGLU (tf32-rounded out) --------
__global__ void geglu_kernel(const float* __restrict__ Hh, float* __restrict__ G)
{
    size_t n4 = (size_t)ROWS * FFD / 4;
    size_t stride = (size_t)gridDim.x * blockDim.x;
    for (size_t i = (size_t)blockIdx.x * blockDim.x + threadIdx.x; i < n4; i += stride) {
        size_t col4 = i % (FFD / 4), row = i / (FFD / 4);
        float4 a4 = *(const float4*)(Hh + row * FF2D + col4 * 4);
        float4 g4 = *(const float4*)(Hh + row * FF2D + FFD + col4 * 4);
        float4 o;
        o.x = tf32r(a4.x * gelu_tanh(g4.x)); o.y = tf32r(a4.y * gelu_tanh(g4.y));
        o.z = tf32r(a4.z * gelu_tanh(g4.z)); o.w = tf32r(a4.w * gelu_tanh(g4.w));
        *(float4*)(G + i * 4) = o;
    }
}

extern "C" void kernel_launch(void* const* d_in, const int* in_sizes, int n_in,
                              void* d_out, int out_size)
{
    const float* x    = (const float*)d_in[0];
    const float* ctx  = (const float*)d_in[1];
    const float* ln1g = (const float*)d_in[2];
    const float* ln1b = (const float*)d_in[3];
    const float* ln2g = (const float*)d_in[4];
    const float* ln2b = (const float*)d_in[5];
    const float* ln3g = (const float*)d_in[6];
    const float* ln3b = (const float*)d_in[7];
    const float* Wq1  = (const float*)d_in[8];
    const float* Wk1  = (const float*)d_in[9];
    const float* Wv1  = (const float*)d_in[10];
    const float* Wo1  = (const float*)d_in[11];
    const float* bo1  = (const float*)d_in[12];
    const float* Wq2  = (const float*)d_in[13];
    const float* Wk2  = (const float*)d_in[14];
    const float* Wv2  = (const float*)d_in[15];
    const float* Wo2  = (const float*)d_in[16];
    const float* bo2  = (const float*)d_in[17];
    const float* Wff1 = (const float*)d_in[18];
    const float* bff1 = (const float*)d_in[19];
    const float* Wff2 = (const float*)d_in[20];
    const float* bff2 = (const float*)d_in[21];
    float* out = (float*)d_out;

    float* sc = nullptr;
    cudaGetSymbolAddress((void**)&sc, g_scratch);
    float* XN  = sc + OFF_XN;
    float* QKV = sc + OFF_Q;
    float* Qc  = sc + OFF_Q;
    float* KV2 = sc + OFF_K;
    float* O   = sc + OFF_O;
    float* X1  = sc + OFF_X1;
    float* S   = sc + OFF_S;
    float* Hb  = sc + OFF_H;
    float* G   = sc + OFF_G;
    float* RM  = sc + OFF_RM;
    float* RZ  = sc + OFF_RZ;
    unsigned* AM = (unsigned*)(sc + OFF_AM);
    float* cWqkv = sc + OFF_WQKV;
    float* cWo1  = sc + OFF_WO1;
    float* cWq2  = sc + OFF_WQ2;
    float* cWo2  = sc + OFF_WO2;
    float* cWkv2 = sc + OFF_WKV2;
    float* cWf1  = sc + OFF_WF1;
    float* cWf2  = sc + OFF_WF2;
    float* cCtx  = sc + OFF_CTX;
    int8_t* LQ8 = (int8_t*)(sc + OFF_LQ8);
    int8_t* LK8 = (int8_t*)(sc + OFF_LK8);
    int8_t* LVT = (int8_t*)(sc + OFF_LVT);

    dim3 g1280(CDIM / 128, ROWS / 128);
    dim3 gqkv(QKVN / 128, ROWS / 128);
    dim3 gkv2(KV2N / 128, (CROSSROWS + 127) / 128);
    dim3 gff1(FF2D / 128, ROWS / 128);
    long long n4 = (long long)ROWS * CDIM / 4;

    init_amax_kernel<<<1, 32>>>(AM);

    conv_pack_kernel<<<512,256>>>(Wq1, cWqkv + 0,      CDIM, CDIM, QKVN);
    conv_pack_kernel<<<512,256>>>(Wk1, cWqkv + CDIM,   CDIM, CDIM, QKVN);
    conv_pack_kernel<<<512,256>>>(Wv1, cWqkv + 2*CDIM, CDIM, CDIM, QKVN);
    conv_pack_kernel<<<512,256>>>(Wk2, cWkv2 + 0,    CTXC, CDIM, KV2N);
    conv_pack_kernel<<<512,256>>>(Wv2, cWkv2 + CDIM, CTXC, CDIM, KV2N);
    conv_tf32_kernel<<<1024,256>>>(Wo1,  cWo1, (long long)SZ_W1/4);
    conv_tf32_kernel<<<1024,256>>>(Wq2,  cWq2, (long long)SZ_W1/4);
    conv_tf32_kernel<<<1024,256>>>(Wo2,  cWo2, (long long)SZ_W1/4);
    conv_tf32_kernel<<<2048,256>>>(Wff1, cWf1, (long long)SZ_WF1/4);
    conv_tf32_kernel<<<2048,256>>>(Wff2, cWf2, (long long)SZ_WF2/4);
    conv_tf32_kernel<<<512,256>>>(ctx,   cCtx, (long long)SZ_CTXB/4);

    // ---- block 1: self attention (fused flash-style int8 path) ----
    ln_kernel<<<ROWS, 256>>>(x, ln1g, ln1b, XN);
    tgemm_kernel<false,false,true,true><<<gqkv,256>>>(XN, cWqkv, QKV, ROWS, QKVN, CDIM, nullptr, nullptr, AM+0);
    quant_s8_strided<<<1024,256>>>(QKV + 0,    LQ8, AM+0);
    quant_s8_strided<<<1024,256>>>(QKV + CDIM, LK8, AM+1);
    quant_v_t_kernel<<<dim3(NSEQ/64, BHD),256>>>(QKV + 2*CDIM, LVT, AM+2);
    self_stats_i8_kernel<<<dim3(8,BHD),256>>>(LQ8, LK8, RM, RZ, AM);
    self_pv_i8_kernel<<<dim3(8,BHD),256>>>(LQ8, LK8, LVT, RM, RZ, AM, O);
    tgemm_kernel<true,true,false,false><<<g1280,256>>>(O, cWo1, X1, ROWS, CDIM, CDIM, bo1, x, nullptr);

    // ---- block 2: cross attention ----
    ln_kernel<<<ROWS,256>>>(X1, ln2g, ln2b, XN);
    tgemm_kernel<false,false,true,false><<<g1280,256>>>(XN, cWq2, Qc, ROWS, CDIM, CDIM, nullptr, nullptr, AM+4);
    tgemm_kernel<false,false,true,true><<<gkv2,256>>>(cCtx, cWkv2, KV2, CROSSROWS, KV2N, CTXC, nullptr, nullptr, AM+5);
    quant_sym_kernel<<<2048,256>>>(Qc, n4, AM+4);
    quant_kv2_kernel<<<1024,256>>>(KV2, AM+5);
    cross_scores_kernel<<<dim3(16,BHD),256>>>(Qc, KV2, KV2N, S);
    softmax_stats_kernel<<<BHD*NSEQ,256>>>(S, RM, RZ, AM+7, MCTX, 80);
    cross_pv_kernel<<<dim3(16,BHD),256>>>(S, KV2 + CDIM, KV2N, RM, RZ, AM+7, O);
    tgemm_kernel<true,true,false,false><<<g1280,256>>>(O, cWo2, X1, ROWS, CDIM, CDIM, bo2, X1, nullptr);

    // ---- block 3: GEGLU FF ----
    ln_kernel<<<ROWS,256>>>(X1, ln3g, ln3b, XN);
    tgemm_kernel<true,false,false,false><<<gff1,256>>>(XN, cWf1, Hb, ROWS, FF2D, CDIM, bff1, nullptr, nullptr);
    geglu_kernel<<<4096,256>>>(Hb, G);
    tgemm_kernel<true,true,false,false><<<g1280,256>>>(G, cWf2, out, ROWS, CDIM, FFD, bff2, X1, nullptr);
}

// round 12
// speedup vs baseline: 1.2506x; 1.0202x over previous
#include <cuda_runtime.h>
#include <cstdint>

#define NB 8
#define NSEQ 1024
#define CDIM 1280
#define NH 20
#define DH 64
#define MCTX 77
#define CTXC 768
#define FFD 5120
#define FF2D 10240
#define ROWS (NB*NSEQ)
#define BHD (NB*NH)
#define CROSSROWS (NB*MCTX)
#define QKVN 3840
#define KV2N 2560

static constexpr size_t SZ_XC = (size_t)ROWS * CDIM;
static constexpr size_t OFF_XN = 0;
static constexpr size_t OFF_Q  = OFF_XN + SZ_XC;     // QKV fused buffer [ROWS][3840]
static constexpr size_t OFF_K  = OFF_Q + SZ_XC;      // cross-phase: KV2 [616][2560]
static constexpr size_t OFF_V  = OFF_K + SZ_XC;
static constexpr size_t OFF_O  = OFF_V + SZ_XC;
static constexpr size_t OFF_X1 = OFF_O + SZ_XC;
static constexpr size_t OFF_S  = OFF_X1 + SZ_XC;     // cross scores only
static constexpr size_t SZ_S   = (size_t)BHD * NSEQ * 80;
static constexpr size_t OFF_G  = OFF_S + SZ_S;
static constexpr size_t SZ_G   = (size_t)ROWS * FFD;
static constexpr size_t OFF_RM = OFF_G + SZ_G;
static constexpr size_t OFF_RZ = OFF_RM + (size_t)BHD * NSEQ;
static constexpr size_t OFF_AM = OFF_RZ + (size_t)BHD * NSEQ;
static constexpr size_t SZ_W1  = (size_t)CDIM * CDIM;
static constexpr size_t SZ_WK2 = (size_t)CTXC * CDIM;
static constexpr size_t SZ_WF1 = (size_t)CDIM * FF2D;
static constexpr size_t SZ_WF2 = (size_t)FFD * CDIM;
static constexpr size_t SZ_CTXB = (size_t)CROSSROWS * CTXC;
static constexpr size_t OFF_WQKV = OFF_AM + 8;
static constexpr size_t OFF_WO1  = OFF_WQKV + 3 * SZ_W1;
static constexpr size_t OFF_WQ2  = OFF_WO1 + SZ_W1;
static constexpr size_t OFF_WO2  = OFF_WQ2 + SZ_W1;
static constexpr size_t OFF_WKV2 = OFF_WO2 + SZ_W1;
static constexpr size_t OFF_WF1  = OFF_WKV2 + 2 * SZ_WK2;   // interleaved a|g columns
static constexpr size_t OFF_WF2  = OFF_WF1 + SZ_WF1;
static constexpr size_t OFF_CTX  = OFF_WF2 + SZ_WF2;
static constexpr size_t SZ_S8F   = (size_t)ROWS * CDIM / 4;
static constexpr size_t OFF_LQ8  = OFF_CTX + SZ_CTXB;
static constexpr size_t OFF_LK8  = OFF_LQ8 + SZ_S8F;
static constexpr size_t OFF_LVT  = OFF_LK8 + SZ_S8F;
static constexpr size_t TOTAL_SCRATCH = OFF_LVT + SZ_S8F;

__device__ __align__(256) float g_scratch[TOTAL_SCRATCH];

__global__ void init_amax_kernel(unsigned* amax) {
    if (threadIdx.x < 8) amax[threadIdx.x] = 0u;
}

__device__ __forceinline__ float gelu_tanh(float x) {
    float x3 = x * x * x;
    return 0.5f * x * (1.0f + tanhf(0.7978845608028654f * (x + 0.044715f * x3)));
}

__device__ __forceinline__ uint32_t f2tf32(float f) {
    uint32_t r;
    asm("cvt.rna.tf32.f32 %0, %1;" : "=r"(r) : "f"(f));
    return r;
}
__device__ __forceinline__ float tf32r(float f) { return __uint_as_float(f2tf32(f)); }

__device__ __forceinline__ void mma_tf32(float* d, const uint32_t* a, const uint32_t* b) {
    asm volatile("mma.sync.aligned.m16n8k8.row.col.f32.tf32.tf32.f32 "
        "{%0,%1,%2,%3}, {%4,%5,%6,%7}, {%8,%9}, {%0,%1,%2,%3};"
        : "+f"(d[0]), "+f"(d[1]), "+f"(d[2]), "+f"(d[3])
        : "r"(a[0]), "r"(a[1]), "r"(a[2]), "r"(a[3]), "r"(b[0]), "r"(b[1]));
}

__device__ __forceinline__ void mma_s8(int* d, const uint32_t* a, const uint32_t* b) {
    asm volatile("mma.sync.aligned.m16n8k32.row.col.s32.s8.s8.s32 "
        "{%0,%1,%2,%3}, {%4,%5,%6,%7}, {%8,%9}, {%0,%1,%2,%3};"
        : "+r"(d[0]), "+r"(d[1]), "+r"(d[2]), "+r"(d[3])
        : "r"(a[0]), "r"(a[1]), "r"(a[2]), "r"(a[3]), "r"(b[0]), "r"(b[1]));
}

__device__ __forceinline__ void mma_u8s8(int* d, const uint32_t* a, const uint32_t* b) {
    asm volatile("mma.sync.aligned.m16n8k32.row.col.s32.u8.s8.s32 "
        "{%0,%1,%2,%3}, {%4,%5,%6,%7}, {%8,%9}, {%0,%1,%2,%3};"
        : "+r"(d[0]), "+r"(d[1]), "+r"(d[2]), "+r"(d[3])
        : "r"(a[0]), "r"(a[1]), "r"(a[2]), "r"(a[3]), "r"(b[0]), "r"(b[1]));
}

__device__ __forceinline__ void ldsm4(uint32_t& r0, uint32_t& r1, uint32_t& r2, uint32_t& r3,
                                      uint32_t addr) {
    asm volatile("ldmatrix.sync.aligned.m8n8.x4.shared.b16 {%0,%1,%2,%3}, [%4];"
        : "=r"(r0), "=r"(r1), "=r"(r2), "=r"(r3) : "r"(addr));
}

__device__ __forceinline__ void cp_async16(uint32_t dst, const void* src, int srcsize) {
    asm volatile("cp.async.cg.shared.global [%0], [%1], 16, %2;"
                 :: "r"(dst), "l"(src), "r"(srcsize));
}

__device__ __forceinline__ int clamp_i(int v, int lo, int hi) {
    return v < lo ? lo : (v > hi ? hi : v);
}

__device__ __forceinline__ uint32_t pack_s8x4(float4 v, float inv) {
    int a = clamp_i(__float2int_rn(v.x * inv), -128, 127);
    int b = clamp_i(__float2int_rn(v.y * inv), -128, 127);
    int c = clamp_i(__float2int_rn(v.z * inv), -128, 127);
    int d = clamp_i(__float2int_rn(v.w * inv), -128, 127);
    return (a & 255) | ((b & 255) << 8) | ((c & 255) << 16) | ((d & 255) << 24);
}

// -------- tf32 convert (contiguous) --------
__global__ void conv_tf32_kernel(const float* __restrict__ src, float* __restrict__ dst,
                                 long long n4)
{
    long long stride = (long long)gridDim.x * blockDim.x;
    for (long long i = (long long)blockIdx.x * blockDim.x + threadIdx.x; i < n4; i += stride) {
        float4 v = *(const float4*)(src + i * 4);
        v.x = tf32r(v.x); v.y = tf32r(v.y); v.z = tf32r(v.z); v.w = tf32r(v.w);
        *(float4*)(dst + i * 4) = v;
    }
}

// -------- tf32 convert + column-pack --------
__global__ void conv_pack_kernel(const float* __restrict__ src, float* __restrict__ dst,
                                 int Kn, int Nn, int dstStride)
{
    long long n4 = (long long)Kn * Nn / 4;
    long long stride = (long long)gridDim.x * blockDim.x;
    for (long long i = (long long)blockIdx.x * blockDim.x + threadIdx.x; i < n4; i += stride) {
        long long e = i * 4;
        int row = (int)(e / Nn), col = (int)(e % Nn);
        float4 v = *(const float4*)(src + e);
        v.x = tf32r(v.x); v.y = tf32r(v.y); v.z = tf32r(v.z); v.w = tf32r(v.w);
        *(float4*)(dst + (size_t)row * dstStride + col) = v;
    }
}

// -------- FF1 weight interleave: dst[k][2j]=src[k][j] (a), dst[k][2j+1]=src[k][j+FFD] (g) --------
__global__ void conv_ileave_kernel(const float* __restrict__ src, float* __restrict__ dst)
{
    long long n = (long long)CDIM * FFD;
    long long stride = (long long)gridDim.x * blockDim.x;
    for (long long i = (long long)blockIdx.x * blockDim.x + threadIdx.x; i < n; i += stride) {
        int k = (int)(i / FFD), j = (int)(i % FFD);
        float a = src[(size_t)k * FF2D + j];
        float g = src[(size_t)k * FF2D + FFD + j];
        float2 o = {tf32r(a), tf32r(g)};
        *(float2*)(dst + (size_t)k * FF2D + 2 * j) = o;
    }
}

// ---------------- LayerNorm (tf32-rounded out) ----------------
__global__ void ln_kernel(const float* __restrict__ x, const float* __restrict__ g,
                          const float* __restrict__ bta, float* __restrict__ out)
{
    __shared__ float sx[CDIM];
    __shared__ float red[8];
    int row = blockIdx.x, tid = threadIdx.x;
    const float* xr = x + (size_t)row * CDIM;
    float s = 0.f;
    for (int i = tid; i < CDIM; i += 256) { float v = xr[i]; sx[i] = v; s += v; }
    #pragma unroll
    for (int o = 16; o; o >>= 1) s += __shfl_xor_sync(0xffffffffu, s, o);
    if ((tid & 31) == 0) red[tid >> 5] = s;
    __syncthreads();
    float tot = 0.f;
    #pragma unroll
    for (int w = 0; w < 8; w++) tot += red[w];
    float mean = tot * (1.0f / (float)CDIM);
    float vs = 0.f;
    for (int i = tid; i < CDIM; i += 256) { float d = sx[i] - mean; vs += d * d; }
    __syncthreads();
    #pragma unroll
    for (int o = 16; o; o >>= 1) vs += __shfl_xor_sync(0xffffffffu, vs, o);
    if ((tid & 31) == 0) red[tid >> 5] = vs;
    __syncthreads();
    float tot2 = 0.f;
    #pragma unroll
    for (int w = 0; w < 8; w++) tot2 += red[w];
    float rstd = rsqrtf(tot2 * (1.0f / (float)CDIM) + 1e-5f);
    for (int i = tid; i < CDIM; i += 256)
        out[(size_t)row * CDIM + i] = tf32r((sx[i] - mean) * rstd * g[i] + bta[i]);
}

// ============ TF32 GEMM: 4-stage cp.async, 1 barrier / 2 ktiles ============
// GEGLU: B columns are interleaved (a,g) pairs; epilogue emits a*gelu(g) to
// Cm[row][col0/2] (width FFD), bias indexed bias[j] / bias[FFD+j].
template<bool HAS_BIAS, bool HAS_RES, bool DO_AMAX, bool SEG, bool GEGLU>
__global__ void __launch_bounds__(256, 2) tgemm_kernel(
    const float* __restrict__ A, const float* __restrict__ Bm, float* __restrict__ Cm,
    int Mn, int Nn, int Kn,
    const float* __restrict__ bias, const float* __restrict__ res, unsigned* amax)
{
    constexpr int ST = 4;
    constexpr uint32_t ABYTES = 128 * 20 * 4;
    constexpr uint32_t BBYTES = 16 * 136 * 4;
    __shared__ __align__(16) uint32_t As[ST][128][20];
    __shared__ __align__(16) float    Bs[ST][16][136];
    __shared__ float reds[8];

    int tid  = threadIdx.x;
    int lane = tid & 31;
    int warp = tid >> 5;
    int wm = warp & 1;
    int wn = warp >> 1;
    int nBase = blockIdx.x * 128;
    int mBase = blockIdx.y * 128;

    uint32_t asmb = (uint32_t)__cvta_generic_to_shared(&As[0][0][0]);
    uint32_t bsmb = (uint32_t)__cvta_generic_to_shared(&Bs[0][0][0]);

    const int aR0 = tid >> 2;
    const int aC  = (tid & 3) << 2;
    const int bK0 = tid >> 5;
    const int bN  = (tid & 31) << 2;

    int r8 = lane & 7, sel = lane >> 3;
    uint32_t aoff = asmb + (((wm * 64 + r8 + ((sel & 1) << 3)) * 20 + ((sel >> 1) << 2)) << 2);

    float acc[4][4][4];
    #pragma unroll
    for (int i = 0; i < 4; i++)
        #pragma unroll
        for (int j = 0; j < 4; j++)
            #pragma unroll
            for (int l = 0; l < 4; l++) acc[i][j][l] = 0.f;

    int KT = Kn >> 4;   // even for all shapes used

    auto issue_stage = [&](int s, int k0) {
        #pragma unroll
        for (int i = 0; i < 2; i++) {
            int r = aR0 + i * 64;
            int gr = mBase + r;
            int ok = (gr < Mn);
            const float* src = A + (size_t)(ok ? gr : 0) * Kn + k0 + aC;
            cp_async16(asmb + s * ABYTES + ((r * 20 + aC) << 2), src, ok ? 16 : 0);
        }
        #pragma unroll
        for (int i = 0; i < 2; i++) {
            int kr = bK0 + i * 8;
            const float* src = Bm + (size_t)(k0 + kr) * Nn + nBase + bN;
            cp_async16(bsmb + s * BBYTES + ((kr * 136 + bN) << 2), src, 16);
        }
        asm volatile("cp.async.commit_group;" ::: "memory");
    };

    issue_stage(0, 0);
    issue_stage(1, 16);

    int lr = lane >> 2, lc = lane & 3;
    for (int kt = 0; kt < KT; kt += 2) {
        asm volatile("cp.async.wait_group 0;" ::: "memory");
        __syncthreads();
        if (kt + 2 < KT) {
            issue_stage((kt + 2) & 3, (kt + 2) << 4);
            issue_stage((kt + 3) & 3, (kt + 3) << 4);
        }
        #pragma unroll
        for (int sub = 0; sub < 2; sub++) {
            int buf = (kt + sub) & 3;
            uint32_t abuf = aoff + buf * ABYTES;
            #pragma unroll
            for (int ks = 0; ks < 2; ks++) {
                uint32_t af[4][4], bf[4][2];
                #pragma unroll
                for (int mt = 0; mt < 4; mt++)
                    ldsm4(af[mt][0], af[mt][1], af[mt][2], af[mt][3],
                          abuf + mt * (16 * 20 * 4) + ks * 32);
                #pragma unroll
                for (int nt = 0; nt < 4; nt++) {
                    int col = wn * 32 + nt * 8 + lr;
                    bf[nt][0] = __float_as_uint(Bs[buf][ks * 8 + lc][col]);
                    bf[nt][1] = __float_as_uint(Bs[buf][ks * 8 + lc + 4][col]);
                }
                #pragma unroll
                for (int mt = 0; mt < 4; mt++)
                    #pragma unroll
                    for (int nt = 0; nt < 4; nt++)
                        mma_tf32(acc[mt][nt], af[mt], bf[nt]);
            }
        }
    }

    float amx = 0.f;
    #pragma unroll
    for (int mt = 0; mt < 4; mt++) {
        #pragma unroll
        for (int nt = 0; nt < 4; nt++) {
            int row0 = mBase + wm * 64 + mt * 16 + lr;
            int col0 = nBase + wn * 32 + nt * 8 + lc * 2;
            #pragma unroll
            for (int half = 0; half < 2; half++) {
                int row = row0 + half * 8;
                if (row < Mn) {
                    float c0 = acc[mt][nt][half * 2 + 0];
                    float c1 = acc[mt][nt][half * 2 + 1];
                    if (GEGLU) {
                        int j = col0 >> 1;
                        float a = c0 + bias[j];
                        float g = c1 + bias[FFD + j];
                        Cm[(size_t)row * FFD + j] = tf32r(a * gelu_tanh(g));
                    } else {
                        if (HAS_BIAS) { c0 += bias[col0]; c1 += bias[col0 + 1]; }
                        if (HAS_RES) {
                            c0 += res[(size_t)row * Nn + col0];
                            c1 += res[(size_t)row * Nn + col0 + 1];
                        }
                        float2 o = {c0, c1};
                        *(float2*)(Cm + (size_t)row * Nn + col0) = o;
                        if (DO_AMAX) amx = fmaxf(amx, fmaxf(fabsf(c0), fabsf(c1)));
                    }
                }
            }
        }
    }
    if (DO_AMAX) {
        #pragma unroll
        for (int o = 16; o; o >>= 1) amx = fmaxf(amx, __shfl_xor_sync(0xffffffffu, amx, o));
        if (lane == 0) reds[warp] = amx;
        __syncthreads();
        if (tid == 0) {
            float m = reds[0];
            #pragma unroll
            for (int w = 1; w < 8; w++) m = fmaxf(m, reds[w]);
            unsigned* tgt = amax + (SEG ? (nBase / 1280) : 0);
            atomicMax(tgt, __float_as_uint(m));
        }
    }
}

// -------- fp32 fake-quant in place (contiguous; cross Q) --------
__global__ void quant_sym_kernel(float* __restrict__ x, long long n4,
                                 const unsigned* __restrict__ amaxbits)
{
    float delta = fmaxf(__uint_as_float(*amaxbits), 1e-8f) / 127.0f;
    long long stride = (long long)gridDim.x * blockDim.x;
    for (long long i = (long long)blockIdx.x * blockDim.x + threadIdx.x; i < n4; i += stride) {
        float4 v = *(float4*)(x + i * 4);
        float l;
        l = rintf(v.x/delta); l = fminf(fmaxf(l,-128.f),127.f); v.x = l*delta;
        l = rintf(v.y/delta); l = fminf(fmaxf(l,-128.f),127.f); v.y = l*delta;
        l = rintf(v.z/delta); l = fminf(fmaxf(l,-128.f),127.f); v.z = l*delta;
        l = rintf(v.w/delta); l = fminf(fmaxf(l,-128.f),127.f); v.w = l*delta;
        *(float4*)(x + i * 4) = v;
    }
}

// -------- fp32 fake-quant, two column segments (cross K|V fused) --------
__global__ void quant_kv2_kernel(float* __restrict__ x, const unsigned* __restrict__ am)
{
    float d0 = fmaxf(__uint_as_float(am[0]), 1e-8f) / 127.0f;
    float d1 = fmaxf(__uint_as_float(am[1]), 1e-8f) / 127.0f;
    long long n4 = (long long)CROSSROWS * KV2N / 4;
    long long stride = (long long)gridDim.x * blockDim.x;
    for (long long i = (long long)blockIdx.x * blockDim.x + threadIdx.x; i < n4; i += stride) {
        int col = (int)((i * 4) % KV2N);
        float delta = (col < CDIM) ? d0 : d1;
        float4 v = *(float4*)(x + i * 4);
        float l;
        l = rintf(v.x/delta); l = fminf(fmaxf(l,-128.f),127.f); v.x = l*delta;
        l = rintf(v.y/delta); l = fminf(fmaxf(l,-128.f),127.f); v.y = l*delta;
        l = rintf(v.z/delta); l = fminf(fmaxf(l,-128.f),127.f); v.z = l*delta;
        l = rintf(v.w/delta); l = fminf(fmaxf(l,-128.f),127.f); v.w = l*delta;
        *(float4*)(x + i * 4) = v;
    }
}

// -------- s8 level quant from strided source --------
__global__ void quant_s8_strided(const float* __restrict__ x, int8_t* __restrict__ L,
                                 const unsigned* __restrict__ amaxbits)
{
    float delta = fmaxf(__uint_as_float(*amaxbits), 1e-8f) / 127.0f;
    float inv = 1.0f / delta;
    long long n16 = (long long)ROWS * (CDIM / 16);
    long long stride = (long long)gridDim.x * blockDim.x;
    for (long long i = (long long)blockIdx.x * blockDim.x + threadIdx.x; i < n16; i += stride) {
        int row = (int)(i / (CDIM / 16));
        int c16 = (int)(i % (CDIM / 16));
        const float4* p = (const float4*)(x + (size_t)row * QKVN + c16 * 16);
        uint4 o;
        o.x = pack_s8x4(p[0], inv);
        o.y = pack_s8x4(p[1], inv);
        o.z = pack_s8x4(p[2], inv);
        o.w = pack_s8x4(p[3], inv);
        *(uint4*)(L + i * 16) = o;
    }
}

// -------- V quant + per-head transpose (strided source) --------
__global__ void __launch_bounds__(256) quant_v_t_kernel(const float* __restrict__ V,
                                                        int8_t* __restrict__ LVT,
                                                        const unsigned* __restrict__ amaxbits)
{
    __shared__ int8_t T[64][80];
    float delta = fmaxf(__uint_as_float(*amaxbits), 1e-8f) / 127.0f;
    float inv = 1.0f / delta;
    int tid = threadIdx.x;
    int bh = blockIdx.y, b = bh / NH, h = bh % NH;
    int m0 = blockIdx.x * 64;
    #pragma unroll
    for (int i = 0; i < 4; i++) {
        int lin = tid + i * 256;
        int r = lin >> 4;
        int c4 = (lin & 15) << 2;
        float4 v = *(const float4*)(V + ((size_t)(b*NSEQ + m0 + r))*QKVN + h*DH + c4);
        T[c4+0][r] = (int8_t)clamp_i(__float2int_rn(v.x*inv), -128, 127);
        T[c4+1][r] = (int8_t)clamp_i(__float2int_rn(v.y*inv), -128, 127);
        T[c4+2][r] = (int8_t)clamp_i(__float2int_rn(v.z*inv), -128, 127);
        T[c4+3][r] = (int8_t)clamp_i(__float2int_rn(v.w*inv), -128, 127);
    }
    __syncthreads();
    int d = tid >> 2, ch = (tid & 3) << 4;
    int4 val = *(int4*)&T[d][ch];
    *(int4*)(LVT + ((size_t)(bh*DH + d))*NSEQ + m0 + ch) = val;
}

// ======== FUSED self-attn stats: recompute scores, online softmax ========
__global__ void __launch_bounds__(256) self_stats_i8_kernel(
    const int8_t* __restrict__ LQ, const int8_t* __restrict__ LK,
    float* __restrict__ RM, float* __restrict__ RZ, unsigned* __restrict__ am)
{
    __shared__ __align__(16) int8_t Qs[128][80];
    __shared__ __align__(16) int8_t Ks[128][80];
    __shared__ float red[128][4];
    __shared__ float tmaxS[128];
    __shared__ float rowmS[128], rowzS[128];
    __shared__ float wred[8];
    float dq = fmaxf(__uint_as_float(am[0]), 1e-8f) / 127.0f;
    float dk = fmaxf(__uint_as_float(am[1]), 1e-8f) / 127.0f;
    float scale = dq * dk * 0.125f;
    int tid = threadIdx.x, lane = tid & 31, warp = tid >> 5;
    int bh = blockIdx.y, b = bh / NH, h = bh % NH;
    int n0 = blockIdx.x * 128;
    int wn = warp & 1, wm = warp >> 1;
    int gr = lane >> 2, gc = lane & 3;

    #pragma unroll
    for (int i = 0; i < 2; i++) {
        int lin = tid + i * 256;
        int r = lin >> 2, ch = (lin & 3) << 4;
        *(int4*)&Qs[r][ch] = *(const int4*)(LQ + ((size_t)(b*NSEQ + n0 + r))*CDIM + h*DH + ch);
    }
    if (tid < 128) { rowmS[tid] = -3.4e38f; rowzS[tid] = 0.f; }

    int rows[8];
    #pragma unroll
    for (int nt = 0; nt < 4; nt++)
        #pragma unroll
        for (int half = 0; half < 2; half++)
            rows[nt*2+half] = wn*64 + nt*16 + gr + half*8;

    for (int mc = 0; mc < 8; mc++) {
        __syncthreads();
        #pragma unroll
        for (int i = 0; i < 2; i++) {
            int lin = tid + i * 256;
            int r = lin >> 2, ch = (lin & 3) << 4;
            *(int4*)&Ks[r][ch] = *(const int4*)(LK + ((size_t)(b*NSEQ + mc*128 + r))*CDIM + h*DH + ch);
        }
        __syncthreads();

        int acc[4][4][4];
        #pragma unroll
        for (int i = 0; i < 4; i++)
            #pragma unroll
            for (int j = 0; j < 4; j++)
                #pragma unroll
                for (int l = 0; l < 4; l++) acc[i][j][l] = 0;
        #pragma unroll
        for (int ks = 0; ks < 2; ks++) {
            uint32_t af[4][4], bf[4][2];
            #pragma unroll
            for (int nt = 0; nt < 4; nt++) {
                int row = wn * 64 + nt * 16 + gr;
                af[nt][0] = *(const uint32_t*)&Qs[row][ks*32 + gc*4];
                af[nt][1] = *(const uint32_t*)&Qs[row + 8][ks*32 + gc*4];
                af[nt][2] = *(const uint32_t*)&Qs[row][ks*32 + 16 + gc*4];
                af[nt][3] = *(const uint32_t*)&Qs[row + 8][ks*32 + 16 + gc*4];
            }
            #pragma unroll
            for (int mt = 0; mt < 4; mt++) {
                int col = wm * 32 + mt * 8 + gr;
                bf[mt][0] = *(const uint32_t*)&Ks[col][ks*32 + gc*4];
                bf[mt][1] = *(const uint32_t*)&Ks[col][ks*32 + 16 + gc*4];
            }
            #pragma unroll
            for (int nt = 0; nt < 4; nt++)
                #pragma unroll
                for (int mt = 0; mt < 4; mt++)
                    mma_s8(acc[nt][mt], af[nt], bf[mt]);
        }

        float lmax[8];
        #pragma unroll
        for (int j = 0; j < 8; j++) lmax[j] = -3.4e38f;
        #pragma unroll
        for (int nt = 0; nt < 4; nt++)
            #pragma unroll
            for (int mt = 0; mt < 4; mt++)
                #pragma unroll
                for (int c = 0; c < 4; c++)
                    lmax[nt*2 + (c>>1)] = fmaxf(lmax[nt*2 + (c>>1)], scale*(float)acc[nt][mt][c]);
        #pragma unroll
        for (int j = 0; j < 8; j++) {
            lmax[j] = fmaxf(lmax[j], __shfl_xor_sync(0xffffffffu, lmax[j], 1));
            lmax[j] = fmaxf(lmax[j], __shfl_xor_sync(0xffffffffu, lmax[j], 2));
        }
        if (gc == 0) {
            #pragma unroll
            for (int j = 0; j < 8; j++) red[rows[j]][wm] = lmax[j];
        }
        __syncthreads();
        if (tid < 128)
            tmaxS[tid] = fmaxf(fmaxf(red[tid][0], red[tid][1]), fmaxf(red[tid][2], red[tid][3]));
        __syncthreads();

        float lsum[8];
        #pragma unroll
        for (int j = 0; j < 8; j++) lsum[j] = 0.f;
        #pragma unroll
        for (int nt = 0; nt < 4; nt++) {
            float tm0 = tmaxS[rows[nt*2]];
            float tm1 = tmaxS[rows[nt*2+1]];
            #pragma unroll
            for (int mt = 0; mt < 4; mt++) {
                lsum[nt*2]   += __expf(scale*(float)acc[nt][mt][0] - tm0)
                              + __expf(scale*(float)acc[nt][mt][1] - tm0);
                lsum[nt*2+1] += __expf(scale*(float)acc[nt][mt][2] - tm1)
                              + __expf(scale*(float)acc[nt][mt][3] - tm1);
            }
        }
        #pragma unroll
        for (int j = 0; j < 8; j++) {
            lsum[j] += __shfl_xor_sync(0xffffffffu, lsum[j], 1);
            lsum[j] += __shfl_xor_sync(0xffffffffu, lsum[j], 2);
        }
        if (gc == 0) {
            #pragma unroll
            for (int j = 0; j < 8; j++) red[rows[j]][wm] = lsum[j];
        }
        __syncthreads();
        if (tid < 128) {
            float ts = red[tid][0] + red[tid][1] + red[tid][2] + red[tid][3];
            float tm = tmaxS[tid];
            float om = rowmS[tid];
            float nm = fmaxf(om, tm);
            rowzS[tid] = rowzS[tid] * __expf(om - nm) + ts * __expf(tm - nm);
            rowmS[tid] = nm;
        }
    }
    __syncthreads();
    float invz = -3.4e38f;
    if (tid < 128) {
        float z = rowzS[tid];
        RM[(size_t)bh*NSEQ + n0 + tid] = rowmS[tid];
        RZ[(size_t)bh*NSEQ + n0 + tid] = z;
        invz = 1.0f / z;
    }
    #pragma unroll
    for (int o = 16; o; o >>= 1) invz = fmaxf(invz, __shfl_xor_sync(0xffffffffu, invz, o));
    if (lane == 0) wred[warp] = invz;
    __syncthreads();
    if (tid == 0) {
        float m = wred[0];
        #pragma unroll
        for (int w = 1; w < 8; w++) m = fmaxf(m, wred[w]);
        atomicMax(am + 3, __float_as_uint(m));
    }
}

// ======== FUSED self-attn PV: recompute scores, fq_zero, u8xs8 PV ========
__global__ void __launch_bounds__(256) self_pv_i8_kernel(
    const int8_t* __restrict__ LQ, const int8_t* __restrict__ LK,
    const int8_t* __restrict__ LVT,
    const float* __restrict__ RM, const float* __restrict__ RZ,
    const unsigned* __restrict__ am, float* __restrict__ O)
{
    __shared__ __align__(16) int8_t  Qs[128][80];
    __shared__ __align__(16) int8_t  Ks[128][80];
    __shared__ __align__(16) uint8_t Lws[128][144];
    __shared__ __align__(16) int8_t  VTs[64][144];
    __shared__ float rmS[128], riS[128];
    float dq = fmaxf(__uint_as_float(am[0]), 1e-8f) / 127.0f;
    float dk = fmaxf(__uint_as_float(am[1]), 1e-8f) / 127.0f;
    float scale = dq * dk * 0.125f;
    float dv = fmaxf(__uint_as_float(am[2]), 1e-8f) / 127.0f;
    float dw = fmaxf(__uint_as_float(am[3]), 1e-8f) / 255.0f;
    float inv_dw = 1.0f / dw;
    float oscale = dw * dv;
    int tid = threadIdx.x, lane = tid & 31, warp = tid >> 5;
    int bh = blockIdx.y, b = bh / NH, h = bh % NH;
    int n0 = blockIdx.x * 128;
    int wn = warp & 1, wm = warp >> 1, wd = warp >> 1;
    int gr = lane >> 2, gc = lane & 3;

    #pragma unroll
    for (int i = 0; i < 2; i++) {
        int lin = tid + i * 256;
        int r = lin >> 2, ch = (lin & 3) << 4;
        *(int4*)&Qs[r][ch] = *(const int4*)(LQ + ((size_t)(b*NSEQ + n0 + r))*CDIM + h*DH + ch);
    }
    if (tid < 128) {
        rmS[tid] = RM[(size_t)bh*NSEQ + n0 + tid];
        riS[tid] = 1.0f / RZ[(size_t)bh*NSEQ + n0 + tid];
    }

    int acc[4][2][4];
    #pragma unroll
    for (int i = 0; i < 4; i++)
        #pragma unroll
        for (int j = 0; j < 2; j++)
            #pragma unroll
            for (int l = 0; l < 4; l++) acc[i][j][l] = 0;

    for (int mc = 0; mc < 8; mc++) {
        __syncthreads();
        #pragma unroll
        for (int i = 0; i < 2; i++) {
            int lin = tid + i * 256;
            int r = lin >> 2, ch = (lin & 3) << 4;
            *(int4*)&Ks[r][ch] = *(const int4*)(LK + ((size_t)(b*NSEQ + mc*128 + r))*CDIM + h*DH + ch);
        }
        #pragma unroll
        for (int i = 0; i < 2; i++) {
            int lin = tid + i * 256;
            int d = lin >> 3, ch = (lin & 7) << 4;
            *(int4*)&VTs[d][ch] = *(const int4*)(LVT + ((size_t)(bh*DH + d))*NSEQ + mc*128 + ch);
        }
        __syncthreads();

        int sacc[4][4][4];
        #pragma unroll
        for (int i = 0; i < 4; i++)
            #pragma unroll
            for (int j = 0; j < 4; j++)
                #pragma unroll
                for (int l = 0; l < 4; l++) sacc[i][j][l] = 0;
        #pragma unroll
        for (int ks = 0; ks < 2; ks++) {
            uint32_t af[4][4], bf[4][2];
            #pragma unroll
            for (int nt = 0; nt < 4; nt++) {
                int row = wn * 64 + nt * 16 + gr;
                af[nt][0] = *(const uint32_t*)&Qs[row][ks*32 + gc*4];
                af[nt][1] = *(const uint32_t*)&Qs[row + 8][ks*32 + gc*4];
                af[nt][2] = *(const uint32_t*)&Qs[row][ks*32 + 16 + gc*4];
                af[nt][3] = *(const uint32_t*)&Qs[row + 8][ks*32 + 16 + gc*4];
            }
            #pragma unroll
            for (int mt = 0; mt < 4; mt++) {
                int col = wm * 32 + mt * 8 + gr;
                bf[mt][0] = *(const uint32_t*)&Ks[col][ks*32 + gc*4];
                bf[mt][1] = *(const uint32_t*)&Ks[col][ks*32 + 16 + gc*4];
            }
            #pragma unroll
            for (int nt = 0; nt < 4; nt++)
                #pragma unroll
                for (int mt = 0; mt < 4; mt++)
                    mma_s8(sacc[nt][mt], af[nt], bf[mt]);
        }
        #pragma unroll
        for (int nt = 0; nt < 4; nt++) {
            #pragma unroll
            for (int half = 0; half < 2; half++) {
                int row = wn*64 + nt*16 + gr + half*8;
                float rm = rmS[row];
                float f = riS[row] * inv_dw;
                #pragma unroll
                for (int mt = 0; mt < 4; mt++) {
                    int col = wm*32 + mt*8 + gc*2;
                    int l0 = min(255, __float2int_rn(__expf(scale*(float)sacc[nt][mt][half*2+0] - rm) * f));
                    int l1 = min(255, __float2int_rn(__expf(scale*(float)sacc[nt][mt][half*2+1] - rm) * f));
                    *(uint16_t*)&Lws[row][col] = (uint16_t)(l0 | (l1 << 8));
                }
            }
        }
        __syncthreads();

        #pragma unroll
        for (int ks = 0; ks < 4; ks++) {
            uint32_t af[4][4], bf[2][2];
            #pragma unroll
            for (int nt = 0; nt < 4; nt++) {
                int row = wn * 64 + nt * 16 + gr;
                af[nt][0] = *(const uint32_t*)&Lws[row][ks*32 + gc*4];
                af[nt][1] = *(const uint32_t*)&Lws[row + 8][ks*32 + gc*4];
                af[nt][2] = *(const uint32_t*)&Lws[row][ks*32 + 16 + gc*4];
                af[nt][3] = *(const uint32_t*)&Lws[row + 8][ks*32 + 16 + gc*4];
            }
            #pragma unroll
            for (int dt = 0; dt < 2; dt++) {
                int col = wd * 16 + dt * 8 + gr;
                bf[dt][0] = *(const uint32_t*)&VTs[col][ks*32 + gc*4];
                bf[dt][1] = *(const uint32_t*)&VTs[col][ks*32 + 16 + gc*4];
            }
            #pragma unroll
            for (int nt = 0; nt < 4; nt++)
                #pragma unroll
                for (int dt = 0; dt < 2; dt++)
                    mma_u8s8(acc[nt][dt], af[nt], bf[dt]);
        }
    }
    #pragma unroll
    for (int nt = 0; nt < 4; nt++) {
        #pragma unroll
        for (int dt = 0; dt < 2; dt++) {
            int row0 = n0 + wn * 64 + nt * 16 + gr;
            int col0 = wd * 16 + dt * 8 + gc * 2;
            #pragma unroll
            for (int half = 0; half < 2; half++) {
                int row = row0 + half * 8;
                float2 o = {tf32r(oscale * (float)acc[nt][dt][half*2+0]),
                            tf32r(oscale * (float)acc[nt][dt][half*2+1])};
                *(float2*)(O + ((size_t)(b*NSEQ + row))*CDIM + h*DH + col0) = o;
            }
        }
    }
}

// -------- softmax row stats (cross path) --------
__global__ void softmax_stats_kernel(const float* __restrict__ S, float* __restrict__ rowmax,
                                     float* __restrict__ rowz, unsigned* wmax, int cols, int stride)
{
    int row = blockIdx.x, tid = threadIdx.x;
    const float* s = S + (size_t)row * stride;
    __shared__ float red[8];
    float m = -3.4e38f;
    for (int i = tid; i < cols; i += 256) m = fmaxf(m, s[i]);
    #pragma unroll
    for (int o = 16; o; o >>= 1) m = fmaxf(m, __shfl_xor_sync(0xffffffffu, m, o));
    if ((tid & 31) == 0) red[tid >> 5] = m;
    __syncthreads();
    float mm = red[0];
    #pragma unroll
    for (int w = 1; w < 8; w++) mm = fmaxf(mm, red[w]);
    __syncthreads();
    float z = 0.f;
    for (int i = tid; i < cols; i += 256) z += __expf(s[i] - mm);
    #pragma unroll
    for (int o = 16; o; o >>= 1) z += __shfl_xor_sync(0xffffffffu, z, o);
    if ((tid & 31) == 0) red[tid >> 5] = z;
    __syncthreads();
    if (tid == 0) {
        float zz = 0.f;
        #pragma unroll
        for (int w = 0; w < 8; w++) zz += red[w];
        rowmax[row] = mm; rowz[row] = zz;
        atomicMax(wmax, __float_as_uint(1.0f / zz));
    }
}

// -------- cross-attn scores (fp32, M=77, stride 80; K source strided) --------
__global__ void __launch_bounds__(256) cross_scores_kernel(
    const float* __restrict__ q, const float* __restrict__ k, int kstride,
    float* __restrict__ S)
{
    __shared__ __align__(16) float Qs[64][68];
    __shared__ __align__(16) float Ks[80][68];
    int tid = threadIdx.x;
    int bh = blockIdx.y, b = bh / NH, h = bh % NH;
    int n0 = blockIdx.x * 64;
    #pragma unroll
    for (int it = 0; it < 4; ++it) {
        int r = (tid >> 4) + it * 16, c = (tid & 15) << 2;
        float4 qv = *(const float4*)(q + ((size_t)(b*NSEQ + n0 + r))*CDIM + h*DH + c);
        Qs[c+0][r]=qv.x; Qs[c+1][r]=qv.y; Qs[c+2][r]=qv.z; Qs[c+3][r]=qv.w;
    }
    #pragma unroll
    for (int it = 0; it < 5; ++it) {
        int lin = tid + it * 256;
        if (lin < 80 * 16) {
            int r = lin >> 4, c = (lin & 15) << 2;
            float4 kv = (r < MCTX) ? *(const float4*)(k + ((size_t)(b*MCTX + r))*kstride + h*DH + c)
                                   : make_float4(0.f,0.f,0.f,0.f);
            *(float4*)&Ks[r][c] = kv;
        }
    }
    __syncthreads();
    int tx = tid & 15, ty = tid >> 4;
    float acc[4][5];
    #pragma unroll
    for (int i = 0; i < 4; i++)
        #pragma unroll
        for (int j = 0; j < 5; j++) acc[i][j] = 0.f;
    #pragma unroll 4
    for (int d = 0; d < 64; ++d) {
        float4 q4 = *(const float4*)&Qs[d][ty*4];
        float qa[4]={q4.x,q4.y,q4.z,q4.w};
        #pragma unroll
        for (int jj = 0; jj < 5; jj++) {
            float kv = Ks[tx*5+jj][d];
            #pragma unroll
            for (int i = 0; i < 4; i++) acc[i][jj] = fmaf(qa[i], kv, acc[i][jj]);
        }
    }
    #pragma unroll
    for (int i = 0; i < 4; i++)
        #pragma unroll
        for (int jj = 0; jj < 5; jj++) {
            int m = tx * 5 + jj;
            if (m < MCTX)
                S[((size_t)bh*NSEQ + n0 + ty*4 + i)*80 + m] = acc[i][jj] * 0.125f;
        }
}

// -------- cross-attn PV (fp32; V source strided) --------
__global__ void __launch_bounds__(256) cross_pv_kernel(
    const float* __restrict__ S, const float* __restrict__ v, int vstride,
    const float* __restrict__ rowmax, const float* __restrict__ rowz,
    const unsigned* __restrict__ wmaxbits, float* __restrict__ O)
{
    __shared__ __align__(16) float Ws[80][68];
    __shared__ __align__(16) float Vs[80][68];
    int tid = threadIdx.x;
    int bh = blockIdx.y, b = bh / NH, h = bh % NH;
    int n0 = blockIdx.x * 64;
    int tx = tid & 15, ty = tid >> 4;
    float delta = fmaxf(__uint_as_float(*wmaxbits), 1e-8f) / 255.0f;
    float inv_delta = 1.0f / delta;
    #pragma unroll
    for (int it = 0; it < 5; ++it) {
        int lin = tid + it * 256;
        if (lin < MCTX * 16) {
            int r = lin >> 4, c = (lin & 15) << 2;
            *(float4*)&Vs[r][c] = *(const float4*)(v + ((size_t)(b*MCTX + r))*vstride + h*DH + c);
        }
    }
    #pragma unroll
    for (int it = 0; it < 4; ++it) {
        int r = (tid >> 4) + it * 16;
        float rm = rowmax[(size_t)bh*NSEQ + n0 + r];
        float ri = 1.0f / rowz[(size_t)bh*NSEQ + n0 + r];
        #pragma unroll
        for (int jj = 0; jj < 5; jj++) {
            int m = (tid & 15) * 5 + jj;
            float w = 0.f;
            if (m < MCTX) {
                float s = S[((size_t)bh*NSEQ + n0 + r)*80 + m];
                float p = __expf(s - rm);
                float l = rintf(p * ri * inv_delta);
                l = fminf(fmaxf(l, 0.f), 255.f);
                w = l * delta;
            }
            Ws[m][r] = w;
        }
    }
    __syncthreads();
    float acc[4][4];
    #pragma unroll
    for (int i = 0; i < 4; i++)
        #pragma unroll
        for (int j = 0; j < 4; j++) acc[i][j] = 0.f;
    for (int m = 0; m < MCTX; m++) {
        float4 w4 = *(const float4*)&Ws[m][ty*4];
        float4 v4 = *(const float4*)&Vs[m][tx*4];
        float wa[4]={w4.x,w4.y,w4.z,w4.w}, va[4]={v4.x,v4.y,v4.z,v4.w};
        #pragma unroll
        for (int i = 0; i < 4; i++)
            #pragma unroll
            for (int j = 0; j < 4; j++) acc[i][j] = fmaf(wa[i], va[j], acc[i][j]);
    }
    #pragma unroll
    for (int i = 0; i < 4; i++) {
        float4 o = {tf32r(acc[i][0]), tf32r(acc[i][1]), tf32r(acc[i][2]), tf32r(acc[i][3])};
        *(float4*)(O + ((size_t)(b*NSEQ + n0 + ty*4 + i))*CDIM + h*DH + tx*4) = o;
    }
}

extern "C" void kernel_launch(void* const* d_in, const int* in_sizes, int n_in,
                              void* d_out, int out_size)
{
    const float* x    = (const float*)d_in[0];
    const float* ctx  = (const float*)d_in[1];
    const float* ln1g = (const float*)d_in[2];
    const float* ln1b = (const float*)d_in[3];
    const float* ln2g = (const float*)d_in[4];
    const float* ln2b = (const float*)d_in[5];
    const float* ln3g = (const float*)d_in[6];
    const float* ln3b = (const float*)d_in[7];
    const float* Wq1  = (const float*)d_in[8];
    const float* Wk1  = (const float*)d_in[9];
    const float* Wv1  = (const float*)d_in[10];
    const float* Wo1  = (const float*)d_in[11];
    const float* bo1  = (const float*)d_in[12];
    const float* Wq2  = (const float*)d_in[13];
    const float* Wk2  = (const float*)d_in[14];
    const float* Wv2  = (const float*)d_in[15];
    const float* Wo2  = (const float*)d_in[16];
    const float* bo2  = (const float*)d_in[17];
    const float* Wff1 = (const float*)d_in[18];
    const float* bff1 = (const float*)d_in[19];
    const float* Wff2 = (const float*)d_in[20];
    const float* bff2 = (const float*)d_in[21];
    float* out = (float*)d_out;

    float* sc = nullptr;
    cudaGetSymbolAddress((void**)&sc, g_scratch);
    float* XN  = sc + OFF_XN;
    float* QKV = sc + OFF_Q;
    float* Qc  = sc + OFF_Q;
    float* KV2 = sc + OFF_K;
    float* O   = sc + OFF_O;
    float* X1  = sc + OFF_X1;
    float* S   = sc + OFF_S;
    float* G   = sc + OFF_G;
    float* RM  = sc + OFF_RM;
    float* RZ  = sc + OFF_RZ;
    unsigned* AM = (unsigned*)(sc + OFF_AM);
    float* cWqkv = sc + OFF_WQKV;
    float* cWo1  = sc + OFF_WO1;
    float* cWq2  = sc + OFF_WQ2;
    float* cWo2  = sc + OFF_WO2;
    float* cWkv2 = sc + OFF_WKV2;
    float* cWf1  = sc + OFF_WF1;
    float* cWf2  = sc + OFF_WF2;
    float* cCtx  = sc + OFF_CTX;
    int8_t* LQ8 = (int8_t*)(sc + OFF_LQ8);
    int8_t* LK8 = (int8_t*)(sc + OFF_LK8);
    int8_t* LVT = (int8_t*)(sc + OFF_LVT);

    dim3 g1280(CDIM / 128, ROWS / 128);
    dim3 gqkv(QKVN / 128, ROWS / 128);
    dim3 gkv2(KV2N / 128, (CROSSROWS + 127) / 128);
    dim3 gff1(FF2D / 128, ROWS / 128);
    long long n4 = (long long)ROWS * CDIM / 4;

    init_amax_kernel<<<1, 32>>>(AM);

    conv_pack_kernel<<<512,256>>>(Wq1, cWqkv + 0,      CDIM, CDIM, QKVN);
    conv_pack_kernel<<<512,256>>>(Wk1, cWqkv + CDIM,   CDIM, CDIM, QKVN);
    conv_pack_kernel<<<512,256>>>(Wv1, cWqkv + 2*CDIM, CDIM, CDIM, QKVN);
    conv_pack_kernel<<<512,256>>>(Wk2, cWkv2 + 0,    CTXC, CDIM, KV2N);
    conv_pack_kernel<<<512,256>>>(Wv2, cWkv2 + CDIM, CTXC, CDIM, KV2N);
    conv_tf32_kernel<<<1024,256>>>(Wo1,  cWo1, (long long)SZ_W1/4);
    conv_tf32_kernel<<<1024,256>>>(Wq2,  cWq2, (long long)SZ_W1/4);
    conv_tf32_kernel<<<1024,256>>>(Wo2,  cWo2, (long long)SZ_W1/4);
    conv_ileave_kernel<<<2048,256>>>(Wff1, cWf1);
    conv_tf32_kernel<<<2048,256>>>(Wff2, cWf2, (long long)SZ_WF2/4);
    conv_tf32_kernel<<<512,256>>>(ctx,   cCtx, (long long)SZ_CTXB/4);

    // ---- block 1: self attention (fused flash-style int8 path) ----
    ln_kernel<<<ROWS, 256>>>(x, ln1g, ln1b, XN);
    tgemm_kernel<false,false,true,true,false><<<gqkv,256>>>(XN, cWqkv, QKV, ROWS, QKVN, CDIM, nullptr, nullptr, AM+0);
    quant_s8_strided<<<1024,256>>>(QKV + 0,    LQ8, AM+0);
    quant_s8_strided<<<1024,256>>>(QKV + CDIM, LK8, AM+1);
    quant_v_t_kernel<<<dim3(NSEQ/64, BHD),256>>>(QKV + 2*CDIM, LVT, AM+2);
    self_stats_i8_kernel<<<dim3(8,BHD),256>>>(LQ8, LK8, RM, RZ, AM);
    self_pv_i8_kernel<<<dim3(8,BHD),256>>>(LQ8, LK8, LVT, RM, RZ, AM, O);
    tgemm_kernel<true,true,false,false,false><<<g1280,256>>>(O, cWo1, X1, ROWS, CDIM, CDIM, bo1, x, nullptr);

    // ---- block 2: cross attention ----
    ln_kernel<<<ROWS,256>>>(X1, ln2g, ln2b, XN);
    tgemm_kernel<false,false,true,false,false><<<g1280,256>>>(XN, cWq2, Qc, ROWS, CDIM, CDIM, nullptr, nullptr, AM+4);
    tgemm_kernel<false,false,true,true,false><<<gkv2,256>>>(cCtx, cWkv2, KV2, CROSSROWS, KV2N, CTXC, nullptr, nullptr, AM+5);
    quant_sym_kernel<<<2048,256>>>(Qc, n4, AM+4);
    quant_kv2_kernel<<<1024,256>>>(KV2, AM+5);
    cross_scores_kernel<<<dim3(16,BHD),256>>>(Qc, KV2, KV2N, S);
    softmax_stats_kernel<<<BHD*NSEQ,256>>>(S, RM, RZ, AM+7, MCTX, 80);
    cross_pv_kernel<<<dim3(16,BHD),256>>>(S, KV2 + CDIM, KV2N, RM, RZ, AM+7, O);
    tgemm_kernel<true,true,false,false,false><<<g1280,256>>>(O, cWo2, X1, ROWS, CDIM, CDIM, bo2, X1, nullptr);

    // ---- block 3: GEGLU FF (geglu fused into FF1 epilogue) ----
    ln_kernel<<<ROWS,256>>>(X1, ln3g, ln3b, XN);
    tgemm_kernel<true,false,false,false,true><<<gff1,256>>>(XN, cWf1, G, ROWS, FF2D, CDIM, bff1, nullptr, nullptr);
    tgemm_kernel<true,true,false,false,false><<<g1280,256>>>(G, cWf2, out, ROWS, CDIM, FFD, bff2, X1, nullptr);
}

// round 14
// speedup vs baseline: 1.6806x; 1.3439x over previous
#include <cuda_runtime.h>
#include <cuda_fp16.h>
#include <cstdint>

#define NB 8
#define NSEQ 1024
#define CDIM 1280
#define NH 20
#define DH 64
#define MCTX 77
#define CTXC 768
#define FFD 5120
#define FF2D 10240
#define ROWS (NB*NSEQ)
#define BHD (NB*NH)
#define CROSSROWS (NB*MCTX)
#define QKVN 3840
#define KV2N 2560

static constexpr size_t SZ_XC = (size_t)ROWS * CDIM;
static constexpr size_t OFF_XN = 0;
static constexpr size_t OFF_Q  = OFF_XN + SZ_XC;     // QKV fused fp32 [ROWS][3840]
static constexpr size_t OFF_K  = OFF_Q + SZ_XC;      // cross-phase: KV2 fp32 [616][2560]
static constexpr size_t OFF_V  = OFF_K + SZ_XC;
static constexpr size_t OFF_O  = OFF_V + SZ_XC;      // O: fp16
static constexpr size_t OFF_X1 = OFF_O + SZ_XC;
static constexpr size_t OFF_S  = OFF_X1 + SZ_XC;     // cross scores only
static constexpr size_t SZ_S   = (size_t)BHD * NSEQ * 80;
static constexpr size_t OFF_G  = OFF_S + SZ_S;       // G: fp16
static constexpr size_t SZ_G   = (size_t)ROWS * FFD;
static constexpr size_t OFF_RM = OFF_G + SZ_G;
static constexpr size_t OFF_RZ = OFF_RM + (size_t)BHD * NSEQ;
static constexpr size_t OFF_AM = OFF_RZ + (size_t)BHD * NSEQ;
static constexpr size_t SZ_W1  = (size_t)CDIM * CDIM;
static constexpr size_t SZ_WK2 = (size_t)CTXC * CDIM;
static constexpr size_t SZ_WF1 = (size_t)CDIM * FF2D;
static constexpr size_t SZ_WF2 = (size_t)FFD * CDIM;
static constexpr size_t SZ_CTXB = (size_t)CROSSROWS * CTXC;
static constexpr size_t OFF_WQKV = OFF_AM + 8;       // fp16 weights (offsets in floats)
static constexpr size_t OFF_WO1  = OFF_WQKV + 3 * SZ_W1;
static constexpr size_t OFF_WQ2  = OFF_WO1 + SZ_W1;
static constexpr size_t OFF_WO2  = OFF_WQ2 + SZ_W1;
static constexpr size_t OFF_WKV2 = OFF_WO2 + SZ_W1;
static constexpr size_t OFF_WF1  = OFF_WKV2 + 2 * SZ_WK2;
static constexpr size_t OFF_WF2  = OFF_WF1 + SZ_WF1;
static constexpr size_t OFF_CTX  = OFF_WF2 + SZ_WF2;
static constexpr size_t SZ_S8F   = (size_t)ROWS * CDIM / 4;
static constexpr size_t OFF_LQ8  = OFF_CTX + SZ_CTXB;
static constexpr size_t OFF_LK8  = OFF_LQ8 + SZ_S8F;
static constexpr size_t OFF_LVT  = OFF_LK8 + SZ_S8F;
static constexpr size_t TOTAL_SCRATCH = OFF_LVT + SZ_S8F;

__device__ __align__(256) float g_scratch[TOTAL_SCRATCH];

__global__ void init_amax_kernel(unsigned* amax) {
    if (threadIdx.x < 8) amax[threadIdx.x] = 0u;
}

__device__ __forceinline__ float gelu_tanh(float x) {
    float x3 = x * x * x;
    return 0.5f * x * (1.0f + tanhf(0.7978845608028654f * (x + 0.044715f * x3)));
}

__device__ __forceinline__ void mma_f16(float* d, const uint32_t* a, const uint32_t* b) {
    asm volatile("mma.sync.aligned.m16n8k16.row.col.f32.f16.f16.f32 "
        "{%0,%1,%2,%3}, {%4,%5,%6,%7}, {%8,%9}, {%0,%1,%2,%3};"
        : "+f"(d[0]), "+f"(d[1]), "+f"(d[2]), "+f"(d[3])
        : "r"(a[0]), "r"(a[1]), "r"(a[2]), "r"(a[3]), "r"(b[0]), "r"(b[1]));
}

__device__ __forceinline__ void mma_s8(int* d, const uint32_t* a, const uint32_t* b) {
    asm volatile("mma.sync.aligned.m16n8k32.row.col.s32.s8.s8.s32 "
        "{%0,%1,%2,%3}, {%4,%5,%6,%7}, {%8,%9}, {%0,%1,%2,%3};"
        : "+r"(d[0]), "+r"(d[1]), "+r"(d[2]), "+r"(d[3])
        : "r"(a[0]), "r"(a[1]), "r"(a[2]), "r"(a[3]), "r"(b[0]), "r"(b[1]));
}

__device__ __forceinline__ void mma_u8s8(int* d, const uint32_t* a, const uint32_t* b) {
    asm volatile("mma.sync.aligned.m16n8k32.row.col.s32.u8.s8.s32 "
        "{%0,%1,%2,%3}, {%4,%5,%6,%7}, {%8,%9}, {%0,%1,%2,%3};"
        : "+r"(d[0]), "+r"(d[1]), "+r"(d[2]), "+r"(d[3])
        : "r"(a[0]), "r"(a[1]), "r"(a[2]), "r"(a[3]), "r"(b[0]), "r"(b[1]));
}

__device__ __forceinline__ void ldsm4(uint32_t& r0, uint32_t& r1, uint32_t& r2, uint32_t& r3,
                                      uint32_t addr) {
    asm volatile("ldmatrix.sync.aligned.m8n8.x4.shared.b16 {%0,%1,%2,%3}, [%4];"
        : "=r"(r0), "=r"(r1), "=r"(r2), "=r"(r3) : "r"(addr));
}

__device__ __forceinline__ void ldsm4t(uint32_t& r0, uint32_t& r1, uint32_t& r2, uint32_t& r3,
                                       uint32_t addr) {
    asm volatile("ldmatrix.sync.aligned.m8n8.x4.trans.shared.b16 {%0,%1,%2,%3}, [%4];"
        : "=r"(r0), "=r"(r1), "=r"(r2), "=r"(r3) : "r"(addr));
}

__device__ __forceinline__ void cp_async16(uint32_t dst, const void* src, int srcsize) {
    asm volatile("cp.async.cg.shared.global [%0], [%1], 16, %2;"
                 :: "r"(dst), "l"(src), "r"(srcsize));
}

__device__ __forceinline__ int clamp_i(int v, int lo, int hi) {
    return v < lo ? lo : (v > hi ? hi : v);
}

__device__ __forceinline__ uint32_t pack_s8x4(float4 v, float inv) {
    int a = clamp_i(__float2int_rn(v.x * inv), -128, 127);
    int b = clamp_i(__float2int_rn(v.y * inv), -128, 127);
    int c = clamp_i(__float2int_rn(v.z * inv), -128, 127);
    int d = clamp_i(__float2int_rn(v.w * inv), -128, 127);
    return (a & 255) | ((b & 255) << 8) | ((c & 255) << 16) | ((d & 255) << 24);
}

// -------- fp16 convert (contiguous) --------
__global__ void conv_h_kernel(const float* __restrict__ src, __half* __restrict__ dst,
                              long long n4)
{
    long long stride = (long long)gridDim.x * blockDim.x;
    for (long long i = (long long)blockIdx.x * blockDim.x + threadIdx.x; i < n4; i += stride) {
        float4 v = *(const float4*)(src + i * 4);
        __half2 h0 = __floats2half2_rn(v.x, v.y);
        __half2 h1 = __floats2half2_rn(v.z, v.w);
        uint2 o = { *(uint32_t*)&h0, *(uint32_t*)&h1 };
        *(uint2*)(dst + i * 4) = o;
    }
}

// -------- fp16 convert + column-pack --------
__global__ void conv_pack_kernel(const float* __restrict__ src, __half* __restrict__ dst,
                                 int Kn, int Nn, int dstStride)
{
    long long n4 = (long long)Kn * Nn / 4;
    long long stride = (long long)gridDim.x * blockDim.x;
    for (long long i = (long long)blockIdx.x * blockDim.x + threadIdx.x; i < n4; i += stride) {
        long long e = i * 4;
        int row = (int)(e / Nn), col = (int)(e % Nn);
        float4 v = *(const float4*)(src + e);
        __half2 h0 = __floats2half2_rn(v.x, v.y);
        __half2 h1 = __floats2half2_rn(v.z, v.w);
        uint2 o = { *(uint32_t*)&h0, *(uint32_t*)&h1 };
        *(uint2*)(dst + (size_t)row * dstStride + col) = o;
    }
}

// -------- FF1 weight interleave (fp16): dst[k][2j]=a, dst[k][2j+1]=g --------
__global__ void conv_ileave_kernel(const float* __restrict__ src, __half* __restrict__ dst)
{
    long long n = (long long)CDIM * FFD;
    long long stride = (long long)gridDim.x * blockDim.x;
    for (long long i = (long long)blockIdx.x * blockDim.x + threadIdx.x; i < n; i += stride) {
        int k = (int)(i / FFD), j = (int)(i % FFD);
        float a = src[(size_t)k * FF2D + j];
        float g = src[(size_t)k * FF2D + FFD + j];
        __half2 o = __floats2half2_rn(a, g);
        *(__half2*)(dst + (size_t)k * FF2D + 2 * j) = o;
    }
}

// ---------------- LayerNorm (fp16 out) ----------------
__global__ void ln_kernel(const float* __restrict__ x, const float* __restrict__ g,
                          const float* __restrict__ bta, __half* __restrict__ out)
{
    __shared__ float sx[CDIM];
    __shared__ float red[8];
    int row = blockIdx.x, tid = threadIdx.x;
    const float* xr = x + (size_t)row * CDIM;
    float s = 0.f;
    for (int i = tid; i < CDIM; i += 256) { float v = xr[i]; sx[i] = v; s += v; }
    #pragma unroll
    for (int o = 16; o; o >>= 1) s += __shfl_xor_sync(0xffffffffu, s, o);
    if ((tid & 31) == 0) red[tid >> 5] = s;
    __syncthreads();
    float tot = 0.f;
    #pragma unroll
    for (int w = 0; w < 8; w++) tot += red[w];
    float mean = tot * (1.0f / (float)CDIM);
    float vs = 0.f;
    for (int i = tid; i < CDIM; i += 256) { float d = sx[i] - mean; vs += d * d; }
    __syncthreads();
    #pragma unroll
    for (int o = 16; o; o >>= 1) vs += __shfl_xor_sync(0xffffffffu, vs, o);
    if ((tid & 31) == 0) red[tid >> 5] = vs;
    __syncthreads();
    float tot2 = 0.f;
    #pragma unroll
    for (int w = 0; w < 8; w++) tot2 += red[w];
    float rstd = rsqrtf(tot2 * (1.0f / (float)CDIM) + 1e-5f);
    for (int i = tid; i < CDIM; i += 256)
        out[(size_t)row * CDIM + i] = __float2half_rn((sx[i] - mean) * rstd * g[i] + bta[i]);
}

// ============ FP16 GEMM: m16n8k16, 4-stage cp.async, 1 barrier / 2 ktiles ============
// A [M][K] fp16 row-major (SMEM pitch 24 halfs = 48B, 16B-aligned);
// B [K][N] fp16 row-major (SMEM pitch 136 halfs = 272B).
template<bool HAS_BIAS, bool HAS_RES, bool DO_AMAX, bool SEG, bool GEGLU>
__global__ void __launch_bounds__(256, 2) tgemm_kernel(
    const __half* __restrict__ A, const __half* __restrict__ Bm, float* __restrict__ Cm,
    int Mn, int Nn, int Kn,
    const float* __restrict__ bias, const float* __restrict__ res, unsigned* amax)
{
    constexpr int ST = 4;
    constexpr int APITCH = 24;                       // halfs; 48B row, 16B aligned
    constexpr uint32_t ABYTES = 128 * APITCH * 2;    // 6144
    constexpr uint32_t BBYTES = 16 * 136 * 2;        // 4352
    __shared__ __align__(16) __half As[ST][128][APITCH];
    __shared__ __align__(16) __half Bs[ST][16][136];
    __shared__ float reds[8];

    int tid  = threadIdx.x;
    int lane = tid & 31;
    int warp = tid >> 5;
    int wm = warp & 1;
    int wn = warp >> 1;
    int nBase = blockIdx.x * 128;
    int mBase = blockIdx.y * 128;

    uint32_t asmb = (uint32_t)__cvta_generic_to_shared(&As[0][0][0]);
    uint32_t bsmb = (uint32_t)__cvta_generic_to_shared(&Bs[0][0][0]);

    const int aR  = tid >> 1;          // 0..127
    const int aCk = (tid & 1) << 3;    // 0 or 8 (halfs)
    const int bK  = tid >> 4;          // 0..15
    const int bN  = (tid & 15) << 3;   // 0..120 (halfs)

    int r8 = lane & 7, sel = lane >> 3;
    // A frag: rows wm*64 + r8 (+8 if sel&1), halfs +8 if sel>>1
    uint32_t aoff = asmb + (((wm * 64 + r8 + ((sel & 1) << 3)) * APITCH + ((sel >> 1) << 3)) << 1);
    // B frag (trans): k-rows (sel>>1)*8 + r8, n base wn*32 (+8 if sel&1)
    uint32_t boff = bsmb + ((((sel >> 1) * 8 + r8) * 136 + wn * 32 + ((sel & 1) << 3)) << 1);

    float acc[4][4][4];
    #pragma unroll
    for (int i = 0; i < 4; i++)
        #pragma unroll
        for (int j = 0; j < 4; j++)
            #pragma unroll
            for (int l = 0; l < 4; l++) acc[i][j][l] = 0.f;

    int KT = Kn >> 4;   // even for all shapes used

    auto issue_stage = [&](int s, int k0) {
        int gr = mBase + aR;
        int ok = (gr < Mn);
        const __half* srcA = A + (size_t)(ok ? gr : 0) * Kn + k0 + aCk;
        cp_async16(asmb + s * ABYTES + ((aR * APITCH + aCk) << 1), srcA, ok ? 16 : 0);
        const __half* srcB = Bm + (size_t)(k0 + bK) * Nn + nBase + bN;
        cp_async16(bsmb + s * BBYTES + ((bK * 136 + bN) << 1), srcB, 16);
        asm volatile("cp.async.commit_group;" ::: "memory");
    };

    issue_stage(0, 0);
    issue_stage(1, 16);

    int lr = lane >> 2, lc = lane & 3;
    for (int kt = 0; kt < KT; kt += 2) {
        asm volatile("cp.async.wait_group 0;" ::: "memory");
        __syncthreads();
        if (kt + 2 < KT) {
            issue_stage((kt + 2) & 3, (kt + 2) << 4);
            issue_stage((kt + 3) & 3, (kt + 3) << 4);
        }
        #pragma unroll
        for (int sub = 0; sub < 2; sub++) {
            int buf = (kt + sub) & 3;
            uint32_t abuf = aoff + buf * ABYTES;
            uint32_t bbuf = boff + buf * BBYTES;
            uint32_t af[4][4], bf[4][2];
            #pragma unroll
            for (int mt = 0; mt < 4; mt++)
                ldsm4(af[mt][0], af[mt][1], af[mt][2], af[mt][3],
                      abuf + mt * (16 * APITCH * 2));
            #pragma unroll
            for (int np = 0; np < 2; np++)
                ldsm4t(bf[np*2][0], bf[np*2+1][0], bf[np*2][1], bf[np*2+1][1],
                       bbuf + np * 32);   // +16 halfs = 32B (n +16)
            #pragma unroll
            for (int mt = 0; mt < 4; mt++)
                #pragma unroll
                for (int nt = 0; nt < 4; nt++)
                    mma_f16(acc[mt][nt], af[mt], bf[nt]);
        }
    }

    float amx = 0.f;
    #pragma unroll
    for (int mt = 0; mt < 4; mt++) {
        #pragma unroll
        for (int nt = 0; nt < 4; nt++) {
            int row0 = mBase + wm * 64 + mt * 16 + lr;
            int col0 = nBase + wn * 32 + nt * 8 + lc * 2;
            #pragma unroll
            for (int half = 0; half < 2; half++) {
                int row = row0 + half * 8;
                if (row < Mn) {
                    float c0 = acc[mt][nt][half * 2 + 0];
                    float c1 = acc[mt][nt][half * 2 + 1];
                    if (GEGLU) {
                        int j = col0 >> 1;
                        float a = c0 + bias[j];
                        float g = c1 + bias[FFD + j];
                        ((__half*)Cm)[(size_t)row * FFD + j] = __float2half_rn(a * gelu_tanh(g));
                    } else {
                        if (HAS_BIAS) { c0 += bias[col0]; c1 += bias[col0 + 1]; }
                        if (HAS_RES) {
                            c0 += res[(size_t)row * Nn + col0];
                            c1 += res[(size_t)row * Nn + col0 + 1];
                        }
                        float2 o = {c0, c1};
                        *(float2*)(Cm + (size_t)row * Nn + col0) = o;
                        if (DO_AMAX) amx = fmaxf(amx, fmaxf(fabsf(c0), fabsf(c1)));
                    }
                }
            }
        }
    }
    if (DO_AMAX) {
        #pragma unroll
        for (int o = 16; o; o >>= 1) amx = fmaxf(amx, __shfl_xor_sync(0xffffffffu, amx, o));
        if (lane == 0) reds[warp] = amx;
        __syncthreads();
        if (tid == 0) {
            float m = reds[0];
            #pragma unroll
            for (int w = 1; w < 8; w++) m = fmaxf(m, reds[w]);
            unsigned* tgt = amax + (SEG ? (nBase / 1280) : 0);
            atomicMax(tgt, __float_as_uint(m));
        }
    }
}

// -------- fp32 fake-quant in place (contiguous; cross Q) --------
__global__ void quant_sym_kernel(float* __restrict__ x, long long n4,
                                 const unsigned* __restrict__ amaxbits)
{
    float delta = fmaxf(__uint_as_float(*amaxbits), 1e-8f) / 127.0f;
    long long stride = (long long)gridDim.x * blockDim.x;
    for (long long i = (long long)blockIdx.x * blockDim.x + threadIdx.x; i < n4; i += stride) {
        float4 v = *(float4*)(x + i * 4);
        float l;
        l = rintf(v.x/delta); l = fminf(fmaxf(l,-128.f),127.f); v.x = l*delta;
        l = rintf(v.y/delta); l = fminf(fmaxf(l,-128.f),127.f); v.y = l*delta;
        l = rintf(v.z/delta); l = fminf(fmaxf(l,-128.f),127.f); v.z = l*delta;
        l = rintf(v.w/delta); l = fminf(fmaxf(l,-128.f),127.f); v.w = l*delta;
        *(float4*)(x + i * 4) = v;
    }
}

// -------- fp32 fake-quant, two column segments (cross K|V fused) --------
__global__ void quant_kv2_kernel(float* __restrict__ x, const unsigned* __restrict__ am)
{
    float d0 = fmaxf(__uint_as_float(am[0]), 1e-8f) / 127.0f;
    float d1 = fmaxf(__uint_as_float(am[1]), 1e-8f) / 127.0f;
    long long n4 = (long long)CROSSROWS * KV2N / 4;
    long long stride = (long long)gridDim.x * blockDim.x;
    for (long long i = (long long)blockIdx.x * blockDim.x + threadIdx.x; i < n4; i += stride) {
        int col = (int)((i * 4) % KV2N);
        float delta = (col < CDIM) ? d0 : d1;
        float4 v = *(float4*)(x + i * 4);
        float l;
        l = rintf(v.x/delta); l = fminf(fmaxf(l,-128.f),127.f); v.x = l*delta;
        l = rintf(v.y/delta); l = fminf(fmaxf(l,-128.f),127.f); v.y = l*delta;
        l = rintf(v.z/delta); l = fminf(fmaxf(l,-128.f),127.f); v.z = l*delta;
        l = rintf(v.w/delta); l = fminf(fmaxf(l,-128.f),127.f); v.w = l*delta;
        *(float4*)(x + i * 4) = v;
    }
}

// -------- s8 level quant from strided source --------
__global__ void quant_s8_strided(const float* __restrict__ x, int8_t* __restrict__ L,
                                 const unsigned* __restrict__ amaxbits)
{
    float delta = fmaxf(__uint_as_float(*amaxbits), 1e-8f) / 127.0f;
    float inv = 1.0f / delta;
    long long n16 = (long long)ROWS * (CDIM / 16);
    long long stride = (long long)gridDim.x * blockDim.x;
    for (long long i = (long long)blockIdx.x * blockDim.x + threadIdx.x; i < n16; i += stride) {
        int row = (int)(i / (CDIM / 16));
        int c16 = (int)(i % (CDIM / 16));
        const float4* p = (const float4*)(x + (size_t)row * QKVN + c16 * 16);
        uint4 o;
        o.x = pack_s8x4(p[0], inv);
        o.y = pack_s8x4(p[1], inv);
        o.z = pack_s8x4(p[2], inv);
        o.w = pack_s8x4(p[3], inv);
        *(uint4*)(L + i * 16) = o;
    }
}

// -------- V quant + per-head transpose (strided source) --------
__global__ void __launch_bounds__(256) quant_v_t_kernel(const float* __restrict__ V,
                                                        int8_t* __restrict__ LVT,
                                                        const unsigned* __restrict__ amaxbits)
{
    __shared__ int8_t T[64][80];
    float delta = fmaxf(__uint_as_float(*amaxbits), 1e-8f) / 127.0f;
    float inv = 1.0f / delta;
    int tid = threadIdx.x;
    int bh = blockIdx.y, b = bh / NH, h = bh % NH;
    int m0 = blockIdx.x * 64;
    #pragma unroll
    for (int i = 0; i < 4; i++) {
        int lin = tid + i * 256;
        int r = lin >> 4;
        int c4 = (lin & 15) << 2;
        float4 v = *(const float4*)(V + ((size_t)(b*NSEQ + m0 + r))*QKVN + h*DH + c4);
        T[c4+0][r] = (int8_t)clamp_i(__float2int_rn(v.x*inv), -128, 127);
        T[c4+1][r] = (int8_t)clamp_i(__float2int_rn(v.y*inv), -128, 127);
        T[c4+2][r] = (int8_t)clamp_i(__float2int_rn(v.z*inv), -128, 127);
        T[c4+3][r] = (int8_t)clamp_i(__float2int_rn(v.w*inv), -128, 127);
    }
    __syncthreads();
    int d = tid >> 2, ch = (tid & 3) << 4;
    int4 val = *(int4*)&T[d][ch];
    *(int4*)(LVT + ((size_t)(bh*DH + d))*NSEQ + m0 + ch) = val;
}

// ======== FUSED self-attn stats: recompute scores, online softmax ========
__global__ void __launch_bounds__(256) self_stats_i8_kernel(
    const int8_t* __restrict__ LQ, const int8_t* __restrict__ LK,
    float* __restrict__ RM, float* __restrict__ RZ, unsigned* __restrict__ am)
{
    __shared__ __align__(16) int8_t Qs[128][80];
    __shared__ __align__(16) int8_t Ks[128][80];
    __shared__ float red[128][4];
    __shared__ float tmaxS[128];
    __shared__ float rowmS[128], rowzS[128];
    __shared__ float wred[8];
    float dq = fmaxf(__uint_as_float(am[0]), 1e-8f) / 127.0f;
    float dk = fmaxf(__uint_as_float(am[1]), 1e-8f) / 127.0f;
    float scale = dq * dk * 0.125f;
    int tid = threadIdx.x, lane = tid & 31, warp = tid >> 5;
    int bh = blockIdx.y, b = bh / NH, h = bh % NH;
    int n0 = blockIdx.x * 128;
    int wn = warp & 1, wm = warp >> 1;
    int gr = lane >> 2, gc = lane & 3;

    #pragma unroll
    for (int i = 0; i < 2; i++) {
        int lin = tid + i * 256;
        int r = lin >> 2, ch = (lin & 3) << 4;
        *(int4*)&Qs[r][ch] = *(const int4*)(LQ + ((size_t)(b*NSEQ + n0 + r))*CDIM + h*DH + ch);
    }
    if (tid < 128) { rowmS[tid] = -3.4e38f; rowzS[tid] = 0.f; }

    int rows[8];
    #pragma unroll
    for (int nt = 0; nt < 4; nt++)
        #pragma unroll
        for (int half = 0; half < 2; half++)
            rows[nt*2+half] = wn*64 + nt*16 + gr + half*8;

    for (int mc = 0; mc < 8; mc++) {
        __syncthreads();
        #pragma unroll
        for (int i = 0; i < 2; i++) {
            int lin = tid + i * 256;
            int r = lin >> 2, ch = (lin & 3) << 4;
            *(int4*)&Ks[r][ch] = *(const int4*)(LK + ((size_t)(b*NSEQ + mc*128 + r))*CDIM + h*DH + ch);
        }
        __syncthreads();

        int acc[4][4][4];
        #pragma unroll
        for (int i = 0; i < 4; i++)
            #pragma unroll
            for (int j = 0; j < 4; j++)
                #pragma unroll
                for (int l = 0; l < 4; l++) acc[i][j][l] = 0;
        #pragma unroll
        for (int ks = 0; ks < 2; ks++) {
            uint32_t af[4][4], bf[4][2];
            #pragma unroll
            for (int nt = 0; nt < 4; nt++) {
                int row = wn * 64 + nt * 16 + gr;
                af[nt][0] = *(const uint32_t*)&Qs[row][ks*32 + gc*4];
                af[nt][1] = *(const uint32_t*)&Qs[row + 8][ks*32 + gc*4];
                af[nt][2] = *(const uint32_t*)&Qs[row][ks*32 + 16 + gc*4];
                af[nt][3] = *(const uint32_t*)&Qs[row + 8][ks*32 + 16 + gc*4];
            }
            #pragma unroll
            for (int mt = 0; mt < 4; mt++) {
                int col = wm * 32 + mt * 8 + gr;
                bf[mt][0] = *(const uint32_t*)&Ks[col][ks*32 + gc*4];
                bf[mt][1] = *(const uint32_t*)&Ks[col][ks*32 + 16 + gc*4];
            }
            #pragma unroll
            for (int nt = 0; nt < 4; nt++)
                #pragma unroll
                for (int mt = 0; mt < 4; mt++)
                    mma_s8(acc[nt][mt], af[nt], bf[mt]);
        }

        float lmax[8];
        #pragma unroll
        for (int j = 0; j < 8; j++) lmax[j] = -3.4e38f;
        #pragma unroll
        for (int nt = 0; nt < 4; nt++)
            #pragma unroll
            for (int mt = 0; mt < 4; mt++)
                #pragma unroll
                for (int c = 0; c < 4; c++)
                    lmax[nt*2 + (c>>1)] = fmaxf(lmax[nt*2 + (c>>1)], scale*(float)acc[nt][mt][c]);
        #pragma unroll
        for (int j = 0; j < 8; j++) {
            lmax[j] = fmaxf(lmax[j], __shfl_xor_sync(0xffffffffu, lmax[j], 1));
            lmax[j] = fmaxf(lmax[j], __shfl_xor_sync(0xffffffffu, lmax[j], 2));
        }
        if (gc == 0) {
            #pragma unroll
            for (int j = 0; j < 8; j++) red[rows[j]][wm] = lmax[j];
        }
        __syncthreads();
        if (tid < 128)
            tmaxS[tid] = fmaxf(fmaxf(red[tid][0], red[tid][1]), fmaxf(red[tid][2], red[tid][3]));
        __syncthreads();

        float lsum[8];
        #pragma unroll
        for (int j = 0; j < 8; j++) lsum[j] = 0.f;
        #pragma unroll
        for (int nt = 0; nt < 4; nt++) {
            float tm0 = tmaxS[rows[nt*2]];
            float tm1 = tmaxS[rows[nt*2+1]];
            #pragma unroll
            for (int mt = 0; mt < 4; mt++) {
                lsum[nt*2]   += __expf(scale*(float)acc[nt][mt][0] - tm0)
                              + __expf(scale*(float)acc[nt][mt][1] - tm0);
                lsum[nt*2+1] += __expf(scale*(float)acc[nt][mt][2] - tm1)
                              + __expf(scale*(float)acc[nt][mt][3] - tm1);
            }
        }
        #pragma unroll
        for (int j = 0; j < 8; j++) {
            lsum[j] += __shfl_xor_sync(0xffffffffu, lsum[j], 1);
            lsum[j] += __shfl_xor_sync(0xffffffffu, lsum[j], 2);
        }
        if (gc == 0) {
            #pragma unroll
            for (int j = 0; j < 8; j++) red[rows[j]][wm] = lsum[j];
        }
        __syncthreads();
        if (tid < 128) {
            float ts = red[tid][0] + red[tid][1] + red[tid][2] + red[tid][3];
            float tm = tmaxS[tid];
            float om = rowmS[tid];
            float nm = fmaxf(om, tm);
            rowzS[tid] = rowzS[tid] * __expf(om - nm) + ts * __expf(tm - nm);
            rowmS[tid] = nm;
        }
    }
    __syncthreads();
    float invz = -3.4e38f;
    if (tid < 128) {
        float z = rowzS[tid];
        RM[(size_t)bh*NSEQ + n0 + tid] = rowmS[tid];
        RZ[(size_t)bh*NSEQ + n0 + tid] = z;
        invz = 1.0f / z;
    }
    #pragma unroll
    for (int o = 16; o; o >>= 1) invz = fmaxf(invz, __shfl_xor_sync(0xffffffffu, invz, o));
    if (lane == 0) wred[warp] = invz;
    __syncthreads();
    if (tid == 0) {
        float m = wred[0];
        #pragma unroll
        for (int w = 1; w < 8; w++) m = fmaxf(m, wred[w]);
        atomicMax(am + 3, __float_as_uint(m));
    }
}

// ======== FUSED self-attn PV: recompute scores, fq_zero, u8xs8 PV (fp16 O out) ========
__global__ void __launch_bounds__(256) self_pv_i8_kernel(
    const int8_t* __restrict__ LQ, const int8_t* __restrict__ LK,
    const int8_t* __restrict__ LVT,
    const float* __restrict__ RM, const float* __restrict__ RZ,
    const unsigned* __restrict__ am, __half* __restrict__ O)
{
    __shared__ __align__(16) int8_t  Qs[128][80];
    __shared__ __align__(16) int8_t  Ks[128][80];
    __shared__ __align__(16) uint8_t Lws[128][144];
    __shared__ __align__(16) int8_t  VTs[64][144];
    __shared__ float rmS[128], riS[128];
    float dq = fmaxf(__uint_as_float(am[0]), 1e-8f) / 127.0f;
    float dk = fmaxf(__uint_as_float(am[1]), 1e-8f) / 127.0f;
    float scale = dq * dk * 0.125f;
    float dv = fmaxf(__uint_as_float(am[2]), 1e-8f) / 127.0f;
    float dw = fmaxf(__uint_as_float(am[3]), 1e-8f) / 255.0f;
    float inv_dw = 1.0f / dw;
    float oscale = dw * dv;
    int tid = threadIdx.x, lane = tid & 31, warp = tid >> 5;
    int bh = blockIdx.y, b = bh / NH, h = bh % NH;
    int n0 = blockIdx.x * 128;
    int wn = warp & 1, wm = warp >> 1, wd = warp >> 1;
    int gr = lane >> 2, gc = lane & 3;

    #pragma unroll
    for (int i = 0; i < 2; i++) {
        int lin = tid + i * 256;
        int r = lin >> 2, ch = (lin & 3) << 4;
        *(int4*)&Qs[r][ch] = *(const int4*)(LQ + ((size_t)(b*NSEQ + n0 + r))*CDIM + h*DH + ch);
    }
    if (tid < 128) {
        rmS[tid] = RM[(size_t)bh*NSEQ + n0 + tid];
        riS[tid] = 1.0f / RZ[(size_t)bh*NSEQ + n0 + tid];
    }

    int acc[4][2][4];
    #pragma unroll
    for (int i = 0; i < 4; i++)
        #pragma unroll
        for (int j = 0; j < 2; j++)
            #pragma unroll
            for (int l = 0; l < 4; l++) acc[i][j][l] = 0;

    for (int mc = 0; mc < 8; mc++) {
        __syncthreads();
        #pragma unroll
        for (int i = 0; i < 2; i++) {
            int lin = tid + i * 256;
            int r = lin >> 2, ch = (lin & 3) << 4;
            *(int4*)&Ks[r][ch] = *(const int4*)(LK + ((size_t)(b*NSEQ + mc*128 + r))*CDIM + h*DH + ch);
        }
        #pragma unroll
        for (int i = 0; i < 2; i++) {
            int lin = tid + i * 256;
            int d = lin >> 3, ch = (lin & 7) << 4;
            *(int4*)&VTs[d][ch] = *(const int4*)(LVT + ((size_t)(bh*DH + d))*NSEQ + mc*128 + ch);
        }
        __syncthreads();

        int sacc[4][4][4];
        #pragma unroll
        for (int i = 0; i < 4; i++)
            #pragma unroll
            for (int j = 0; j < 4; j++)
                #pragma unroll
                for (int l = 0; l < 4; l++) sacc[i][j][l] = 0;
        #pragma unroll
        for (int ks = 0; ks < 2; ks++) {
            uint32_t af[4][4], bf[4][2];
            #pragma unroll
            for (int nt = 0; nt < 4; nt++) {
                int row = wn * 64 + nt * 16 + gr;
                af[nt][0] = *(const uint32_t*)&Qs[row][ks*32 + gc*4];
                af[nt][1] = *(const uint32_t*)&Qs[row + 8][ks*32 + gc*4];
                af[nt][2] = *(const uint32_t*)&Qs[row][ks*32 + 16 + gc*4];
                af[nt][3] = *(const uint32_t*)&Qs[row + 8][ks*32 + 16 + gc*4];
            }
            #pragma unroll
            for (int mt = 0; mt < 4; mt++) {
                int col = wm * 32 + mt * 8 + gr;
                bf[mt][0] = *(const uint32_t*)&Ks[col][ks*32 + gc*4];
                bf[mt][1] = *(const uint32_t*)&Ks[col][ks*32 + 16 + gc*4];
            }
            #pragma unroll
            for (int nt = 0; nt < 4; nt++)
                #pragma unroll
                for (int mt = 0; mt < 4; mt++)
                    mma_s8(sacc[nt][mt], af[nt], bf[mt]);
        }
        #pragma unroll
        for (int nt = 0; nt < 4; nt++) {
            #pragma unroll
            for (int half = 0; half < 2; half++) {
                int row = wn*64 + nt*16 + gr + half*8;
                float rm = rmS[row];
                float f = riS[row] * inv_dw;
                #pragma unroll
                for (int mt = 0; mt < 4; mt++) {
                    int col = wm*32 + mt*8 + gc*2;
                    int l0 = min(255, __float2int_rn(__expf(scale*(float)sacc[nt][mt][half*2+0] - rm) * f));
                    int l1 = min(255, __float2int_rn(__expf(scale*(float)sacc[nt][mt][half*2+1] - rm) * f));
                    *(uint16_t*)&Lws[row][col] = (uint16_t)(l0 | (l1 << 8));
                }
            }
        }
        __syncthreads();

        #pragma unroll
        for (int ks = 0; ks < 4; ks++) {
            uint32_t af[4][4], bf[2][2];
            #pragma unroll
            for (int nt = 0; nt < 4; nt++) {
                int row = wn * 64 + nt * 16 + gr;
                af[nt][0] = *(const uint32_t*)&Lws[row][ks*32 + gc*4];
                af[nt][1] = *(const uint32_t*)&Lws[row + 8][ks*32 + gc*4];
                af[nt][2] = *(const uint32_t*)&Lws[row][ks*32 + 16 + gc*4];
                af[nt][3] = *(const uint32_t*)&Lws[row + 8][ks*32 + 16 + gc*4];
            }
            #pragma unroll
            for (int dt = 0; dt < 2; dt++) {
                int col = wd * 16 + dt * 8 + gr;
                bf[dt][0] = *(const uint32_t*)&VTs[col][ks*32 + gc*4];
                bf[dt][1] = *(const uint32_t*)&VTs[col][ks*32 + 16 + gc*4];
            }
            #pragma unroll
            for (int nt = 0; nt < 4; nt++)
                #pragma unroll
                for (int dt = 0; dt < 2; dt++)
                    mma_u8s8(acc[nt][dt], af[nt], bf[dt]);
        }
    }
    #pragma unroll
    for (int nt = 0; nt < 4; nt++) {
        #pragma unroll
        for (int dt = 0; dt < 2; dt++) {
            int row0 = n0 + wn * 64 + nt * 16 + gr;
            int col0 = wd * 16 + dt * 8 + gc * 2;
            #pragma unroll
            for (int half = 0; half < 2; half++) {
                int row = row0 + half * 8;
                __half2 o = __floats2half2_rn(oscale * (float)acc[nt][dt][half*2+0],
                                              oscale * (float)acc[nt][dt][half*2+1]);
                *(__half2*)(O + ((size_t)(b*NSEQ + row))*CDIM + h*DH + col0) = o;
            }
        }
    }
}

// -------- softmax row stats (cross path) --------
__global__ void softmax_stats_kernel(const float* __restrict__ S, float* __restrict__ rowmax,
                                     float* __restrict__ rowz, unsigned* wmax, int cols, int stride)
{
    int row = blockIdx.x, tid = threadIdx.x;
    const float* s = S + (size_t)row * stride;
    __shared__ float red[8];
    float m = -3.4e38f;
    for (int i = tid; i < cols; i += 256) m = fmaxf(m, s[i]);
    #pragma unroll
    for (int o = 16; o; o >>= 1) m = fmaxf(m, __shfl_xor_sync(0xffffffffu, m, o));
    if ((tid & 31) == 0) red[tid >> 5] = m;
    __syncthreads();
    float mm = red[0];
    #pragma unroll
    for (int w = 1; w < 8; w++) mm = fmaxf(mm, red[w]);
    __syncthreads();
    float z = 0.f;
    for (int i = tid; i < cols; i += 256) z += __expf(s[i] - mm);
    #pragma unroll
    for (int o = 16; o; o >>= 1) z += __shfl_xor_sync(0xffffffffu, z, o);
    if ((tid & 31) == 0) red[tid >> 5] = z;
    __syncthreads();
    if (tid == 0) {
        float zz = 0.f;
        #pragma unroll
        for (int w = 0; w < 8; w++) zz += red[w];
        rowmax[row] = mm; rowz[row] = zz;
        atomicMax(wmax, __float_as_uint(1.0f / zz));
    }
}

// -------- cross-attn scores (fp32, M=77, stride 80; K source strided) --------
__global__ void __launch_bounds__(256) cross_scores_kernel(
    const float* __restrict__ q, const float* __restrict__ k, int kstride,
    float* __restrict__ S)
{
    __shared__ __align__(16) float Qs[64][68];
    __shared__ __align__(16) float Ks[80][68];
    int tid = threadIdx.x;
    int bh = blockIdx.y, b = bh / NH, h = bh % NH;
    int n0 = blockIdx.x * 64;
    #pragma unroll
    for (int it = 0; it < 4; ++it) {
        int r = (tid >> 4) + it * 16, c = (tid & 15) << 2;
        float4 qv = *(const float4*)(q + ((size_t)(b*NSEQ + n0 + r))*CDIM + h*DH + c);
        Qs[c+0][r]=qv.x; Qs[c+1][r]=qv.y; Qs[c+2][r]=qv.z; Qs[c+3][r]=qv.w;
    }
    #pragma unroll
    for (int it = 0; it < 5; ++it) {
        int lin = tid + it * 256;
        if (lin < 80 * 16) {
            int r = lin >> 4, c = (lin & 15) << 2;
            float4 kv = (r < MCTX) ? *(const float4*)(k + ((size_t)(b*MCTX + r))*kstride + h*DH + c)
                                   : make_float4(0.f,0.f,0.f,0.f);
            *(float4*)&Ks[r][c] = kv;
        }
    }
    __syncthreads();
    int tx = tid & 15, ty = tid >> 4;
    float acc[4][5];
    #pragma unroll
    for (int i = 0; i < 4; i++)
        #pragma unroll
        for (int j = 0; j < 5; j++) acc[i][j] = 0.f;
    #pragma unroll 4
    for (int d = 0; d < 64; ++d) {
        float4 q4 = *(const float4*)&Qs[d][ty*4];
        float qa[4]={q4.x,q4.y,q4.z,q4.w};
        #pragma unroll
        for (int jj = 0; jj < 5; jj++) {
            float kv = Ks[tx*5+jj][d];
            #pragma unroll
            for (int i = 0; i < 4; i++) acc[i][jj] = fmaf(qa[i], kv, acc[i][jj]);
        }
    }
    #pragma unroll
    for (int i = 0; i < 4; i++)
        #pragma unroll
        for (int jj = 0; jj < 5; jj++) {
            int m = tx * 5 + jj;
            if (m < MCTX)
                S[((size_t)bh*NSEQ + n0 + ty*4 + i)*80 + m] = acc[i][jj] * 0.125f;
        }
}

// -------- cross-attn PV (fp32; V source strided; fp16 O out) --------
__global__ void __launch_bounds__(256) cross_pv_kernel(
    const float* __restrict__ S, const float* __restrict__ v, int vstride,
    const float* __restrict__ rowmax, const float* __restrict__ rowz,
    const unsigned* __restrict__ wmaxbits, __half* __restrict__ O)
{
    __shared__ __align__(16) float Ws[80][68];
    __shared__ __align__(16) float Vs[80][68];
    int tid = threadIdx.x;
    int bh = blockIdx.y, b = bh / NH, h = bh % NH;
    int n0 = blockIdx.x * 64;
    int tx = tid & 15, ty = tid >> 4;
    float delta = fmaxf(__uint_as_float(*wmaxbits), 1e-8f) / 255.0f;
    float inv_delta = 1.0f / delta;
    #pragma unroll
    for (int it = 0; it < 5; ++it) {
        int lin = tid + it * 256;
        if (lin < MCTX * 16) {
            int r = lin >> 4, c = (lin & 15) << 2;
            *(float4*)&Vs[r][c] = *(const float4*)(v + ((size_t)(b*MCTX + r))*vstride + h*DH + c);
        }
    }
    #pragma unroll
    for (int it = 0; it < 4; ++it) {
        int r = (tid >> 4) + it * 16;
        float rm = rowmax[(size_t)bh*NSEQ + n0 + r];
        float ri = 1.0f / rowz[(size_t)bh*NSEQ + n0 + r];
        #pragma unroll
        for (int jj = 0; jj < 5; jj++) {
            int m = (tid & 15) * 5 + jj;
            float w = 0.f;
            if (m < MCTX) {
                float s = S[((size_t)bh*NSEQ + n0 + r)*80 + m];
                float p = __expf(s - rm);
                float l = rintf(p * ri * inv_delta);
                l = fminf(fmaxf(l, 0.f), 255.f);
                w = l * delta;
            }
            Ws[m][r] = w;
        }
    }
    __syncthreads();
    float acc[4][4];
    #pragma unroll
    for (int i = 0; i < 4; i++)
        #pragma unroll
        for (int j = 0; j < 4; j++) acc[i][j] = 0.f;
    for (int m = 0; m < MCTX; m++) {
        float4 w4 = *(const float4*)&Ws[m][ty*4];
        float4 v4 = *(const float4*)&Vs[m][tx*4];
        float wa[4]={w4.x,w4.y,w4.z,w4.w}, va[4]={v4.x,v4.y,v4.z,v4.w};
        #pragma unroll
        for (int i = 0; i < 4; i++)
            #pragma unroll
            for (int j = 0; j < 4; j++) acc[i][j] = fmaf(wa[i], va[j], acc[i][j]);
    }
    #pragma unroll
    for (int i = 0; i < 4; i++) {
        __half* Ob = O + ((size_t)(b*NSEQ + n0 + ty*4 + i))*CDIM + h*DH + tx*4;
        *(__half2*)(Ob + 0) = __floats2half2_rn(acc[i][0], acc[i][1]);
        *(__half2*)(Ob + 2) = __floats2half2_rn(acc[i][2], acc[i][3]);
    }
}

extern "C" void kernel_launch(void* const* d_in, const int* in_sizes, int n_in,
                              void* d_out, int out_size)
{
    const float* x    = (const float*)d_in[0];
    const float* ctx  = (const float*)d_in[1];
    const float* ln1g = (const float*)d_in[2];
    const float* ln1b = (const float*)d_in[3];
    const float* ln2g = (const float*)d_in[4];
    const float* ln2b = (const float*)d_in[5];
    const float* ln3g = (const float*)d_in[6];
    const float* ln3b = (const float*)d_in[7];
    const float* Wq1  = (const float*)d_in[8];
    const float* Wk1  = (const float*)d_in[9];
    const float* Wv1  = (const float*)d_in[10];
    const float* Wo1  = (const float*)d_in[11];
    const float* bo1  = (const float*)d_in[12];
    const float* Wq2  = (const float*)d_in[13];
    const float* Wk2  = (const float*)d_in[14];
    const float* Wv2  = (const float*)d_in[15];
    const float* Wo2  = (const float*)d_in[16];
    const float* bo2  = (const float*)d_in[17];
    const float* Wff1 = (const float*)d_in[18];
    const float* bff1 = (const float*)d_in[19];
    const float* Wff2 = (const float*)d_in[20];
    const float* bff2 = (const float*)d_in[21];
    float* out = (float*)d_out;

    float* sc = nullptr;
    cudaGetSymbolAddress((void**)&sc, g_scratch);
    __half* XN  = (__half*)(sc + OFF_XN);
    float*  QKV = sc + OFF_Q;
    float*  Qc  = sc + OFF_Q;
    float*  KV2 = sc + OFF_K;
    __half* O   = (__half*)(sc + OFF_O);
    float*  X1  = sc + OFF_X1;
    float*  S   = sc + OFF_S;
    __half* G   = (__half*)(sc + OFF_G);
    float*  RM  = sc + OFF_RM;
    float*  RZ  = sc + OFF_RZ;
    unsigned* AM = (unsigned*)(sc + OFF_AM);
    __half* cWqkv = (__half*)(sc + OFF_WQKV);
    __half* cWo1  = (__half*)(sc + OFF_WO1);
    __half* cWq2  = (__half*)(sc + OFF_WQ2);
    __half* cWo2  = (__half*)(sc + OFF_WO2);
    __half* cWkv2 = (__half*)(sc + OFF_WKV2);
    __half* cWf1  = (__half*)(sc + OFF_WF1);
    __half* cWf2  = (__half*)(sc + OFF_WF2);
    __half* cCtx  = (__half*)(sc + OFF_CTX);
    int8_t* LQ8 = (int8_t*)(sc + OFF_LQ8);
    int8_t* LK8 = (int8_t*)(sc + OFF_LK8);
    int8_t* LVT = (int8_t*)(sc + OFF_LVT);

    dim3 g1280(CDIM / 128, ROWS / 128);
    dim3 gqkv(QKVN / 128, ROWS / 128);
    dim3 gkv2(KV2N / 128, (CROSSROWS + 127) / 128);
    dim3 gff1(FF2D / 128, ROWS / 128);
    long long n4 = (long long)ROWS * CDIM / 4;

    init_amax_kernel<<<1, 32>>>(AM);

    conv_pack_kernel<<<512,256>>>(Wq1, cWqkv + 0,      CDIM, CDIM, QKVN);
    conv_pack_kernel<<<512,256>>>(Wk1, cWqkv + CDIM,   CDIM, CDIM, QKVN);
    conv_pack_kernel<<<512,256>>>(Wv1, cWqkv + 2*CDIM, CDIM, CDIM, QKVN);
    conv_pack_kernel<<<512,256>>>(Wk2, cWkv2 + 0,    CTXC, CDIM, KV2N);
    conv_pack_kernel<<<512,256>>>(Wv2, cWkv2 + CDIM, CTXC, CDIM, KV2N);
    conv_h_kernel<<<1024,256>>>(Wo1,  cWo1, (long long)SZ_W1/4);
    conv_h_kernel<<<1024,256>>>(Wq2,  cWq2, (long long)SZ_W1/4);
    conv_h_kernel<<<1024,256>>>(Wo2,  cWo2, (long long)SZ_W1/4);
    conv_ileave_kernel<<<2048,256>>>(Wff1, cWf1);
    conv_h_kernel<<<2048,256>>>(Wff2, cWf2, (long long)SZ_WF2/4);
    conv_h_kernel<<<512,256>>>(ctx,   cCtx, (long long)SZ_CTXB/4);

    // ---- block 1: self attention (fused flash-style int8 path) ----
    ln_kernel<<<ROWS, 256>>>(x, ln1g, ln1b, XN);
    tgemm_kernel<false,false,true,true,false><<<gqkv,256>>>(XN, cWqkv, QKV, ROWS, QKVN, CDIM, nullptr, nullptr, AM+0);
    quant_s8_strided<<<1024,256>>>(QKV + 0,    LQ8, AM+0);
    quant_s8_strided<<<1024,256>>>(QKV + CDIM, LK8, AM+1);
    quant_v_t_kernel<<<dim3(NSEQ/64, BHD),256>>>(QKV + 2*CDIM, LVT, AM+2);
    self_stats_i8_kernel<<<dim3(8,BHD),256>>>(LQ8, LK8, RM, RZ, AM);
    self_pv_i8_kernel<<<dim3(8,BHD),256>>>(LQ8, LK8, LVT, RM, RZ, AM, O);
    tgemm_kernel<true,true,false,false,false><<<g1280,256>>>(O, cWo1, X1, ROWS, CDIM, CDIM, bo1, x, nullptr);

    // ---- block 2: cross attention ----
    ln_kernel<<<ROWS,256>>>(X1, ln2g, ln2b, XN);
    tgemm_kernel<false,false,true,false,false><<<g1280,256>>>(XN, cWq2, Qc, ROWS, CDIM, CDIM, nullptr, nullptr, AM+4);
    tgemm_kernel<false,false,true,true,false><<<gkv2,256>>>(cCtx, cWkv2, KV2, CROSSROWS, KV2N, CTXC, nullptr, nullptr, AM+5);
    quant_sym_kernel<<<2048,256>>>(Qc, n4, AM+4);
    quant_kv2_kernel<<<1024,256>>>(KV2, AM+5);
    cross_scores_kernel<<<dim3(16,BHD),256>>>(Qc, KV2, KV2N, S);
    softmax_stats_kernel<<<BHD*NSEQ,256>>>(S, RM, RZ, AM+7, MCTX, 80);
    cross_pv_kernel<<<dim3(16,BHD),256>>>(S, KV2 + CDIM, KV2N, RM, RZ, AM+7, O);
    tgemm_kernel<true,true,false,false,false><<<g1280,256>>>(O, cWo2, X1, ROWS, CDIM, CDIM, bo2, X1, nullptr);

    // ---- block 3: GEGLU FF (geglu fused into FF1 epilogue, fp16 G) ----
    ln_kernel<<<ROWS,256>>>(X1, ln3g, ln3b, XN);
    tgemm_kernel<true,false,false,false,true><<<gff1,256>>>(XN, cWf1, (float*)G, ROWS, FF2D, CDIM, bff1, nullptr, nullptr);
    tgemm_kernel<true,true,false,false,false><<<g1280,256>>>(G, cWf2, out, ROWS, CDIM, FFD, bff2, X1, nullptr);
}

// round 15
// speedup vs baseline: 1.6871x; 1.0038x over previous
#include <cuda_runtime.h>
#include <cuda_fp16.h>
#include <cstdint>

#define NB 8
#define NSEQ 1024
#define CDIM 1280
#define NH 20
#define DH 64
#define MCTX 77
#define CTXC 768
#define FFD 5120
#define FF2D 10240
#define ROWS (NB*NSEQ)
#define BHD (NB*NH)
#define CROSSROWS (NB*MCTX)
#define QKVN 3840
#define KV2N 2560

static constexpr size_t SZ_XC = (size_t)ROWS * CDIM;
static constexpr size_t OFF_XN = 0;
static constexpr size_t OFF_Q  = OFF_XN + SZ_XC;     // QKV fused fp16 [ROWS][3840] (uses 1.5*SZ_XC floats)
static constexpr size_t OFF_K  = OFF_Q + SZ_XC;      // cross-phase: KV2 fp32 [616][2560]
static constexpr size_t OFF_V  = OFF_K + SZ_XC;
static constexpr size_t OFF_O  = OFF_V + SZ_XC;      // O: fp16
static constexpr size_t OFF_X1 = OFF_O + SZ_XC;
static constexpr size_t OFF_S  = OFF_X1 + SZ_XC;     // cross scores only
static constexpr size_t SZ_S   = (size_t)BHD * NSEQ * 80;
static constexpr size_t OFF_G  = OFF_S + SZ_S;       // G: fp16
static constexpr size_t SZ_G   = (size_t)ROWS * FFD;
static constexpr size_t OFF_RM = OFF_G + SZ_G;
static constexpr size_t OFF_RZ = OFF_RM + (size_t)BHD * NSEQ;
static constexpr size_t OFF_AM = OFF_RZ + (size_t)BHD * NSEQ;
static constexpr size_t SZ_W1  = (size_t)CDIM * CDIM;
static constexpr size_t SZ_WK2 = (size_t)CTXC * CDIM;
static constexpr size_t SZ_WF1 = (size_t)CDIM * FF2D;
static constexpr size_t SZ_WF2 = (size_t)FFD * CDIM;
static constexpr size_t SZ_CTXB = (size_t)CROSSROWS * CTXC;
static constexpr size_t OFF_WQKV = OFF_AM + 8;       // fp16 weights (offsets in floats)
static constexpr size_t OFF_WO1  = OFF_WQKV + 3 * SZ_W1;
static constexpr size_t OFF_WQ2  = OFF_WO1 + SZ_W1;
static constexpr size_t OFF_WO2  = OFF_WQ2 + SZ_W1;
static constexpr size_t OFF_WKV2 = OFF_WO2 + SZ_W1;
static constexpr size_t OFF_WF1  = OFF_WKV2 + 2 * SZ_WK2;
static constexpr size_t OFF_WF2  = OFF_WF1 + SZ_WF1;
static constexpr size_t OFF_CTX  = OFF_WF2 + SZ_WF2;
static constexpr size_t SZ_S8F   = (size_t)ROWS * CDIM / 4;
static constexpr size_t OFF_LQ8  = OFF_CTX + SZ_CTXB;
static constexpr size_t OFF_LK8  = OFF_LQ8 + SZ_S8F;
static constexpr size_t OFF_LVT  = OFF_LK8 + SZ_S8F;
static constexpr size_t TOTAL_SCRATCH = OFF_LVT + SZ_S8F;

__device__ __align__(256) float g_scratch[TOTAL_SCRATCH];

__global__ void init_amax_kernel(unsigned* amax) {
    if (threadIdx.x < 8) amax[threadIdx.x] = 0u;
}

__device__ __forceinline__ float gelu_tanh(float x) {
    float x3 = x * x * x;
    return 0.5f * x * (1.0f + tanhf(0.7978845608028654f * (x + 0.044715f * x3)));
}

__device__ __forceinline__ void mma_f16(float* d, const uint32_t* a, const uint32_t* b) {
    asm volatile("mma.sync.aligned.m16n8k16.row.col.f32.f16.f16.f32 "
        "{%0,%1,%2,%3}, {%4,%5,%6,%7}, {%8,%9}, {%0,%1,%2,%3};"
        : "+f"(d[0]), "+f"(d[1]), "+f"(d[2]), "+f"(d[3])
        : "r"(a[0]), "r"(a[1]), "r"(a[2]), "r"(a[3]), "r"(b[0]), "r"(b[1]));
}

__device__ __forceinline__ void mma_s8(int* d, const uint32_t* a, const uint32_t* b) {
    asm volatile("mma.sync.aligned.m16n8k32.row.col.s32.s8.s8.s32 "
        "{%0,%1,%2,%3}, {%4,%5,%6,%7}, {%8,%9}, {%0,%1,%2,%3};"
        : "+r"(d[0]), "+r"(d[1]), "+r"(d[2]), "+r"(d[3])
        : "r"(a[0]), "r"(a[1]), "r"(a[2]), "r"(a[3]), "r"(b[0]), "r"(b[1]));
}

__device__ __forceinline__ void mma_u8s8(int* d, const uint32_t* a, const uint32_t* b) {
    asm volatile("mma.sync.aligned.m16n8k32.row.col.s32.u8.s8.s32 "
        "{%0,%1,%2,%3}, {%4,%5,%6,%7}, {%8,%9}, {%0,%1,%2,%3};"
        : "+r"(d[0]), "+r"(d[1]), "+r"(d[2]), "+r"(d[3])
        : "r"(a[0]), "r"(a[1]), "r"(a[2]), "r"(a[3]), "r"(b[0]), "r"(b[1]));
}

__device__ __forceinline__ void ldsm4(uint32_t& r0, uint32_t& r1, uint32_t& r2, uint32_t& r3,
                                      uint32_t addr) {
    asm volatile("ldmatrix.sync.aligned.m8n8.x4.shared.b16 {%0,%1,%2,%3}, [%4];"
        : "=r"(r0), "=r"(r1), "=r"(r2), "=r"(r3) : "r"(addr));
}

__device__ __forceinline__ void ldsm4t(uint32_t& r0, uint32_t& r1, uint32_t& r2, uint32_t& r3,
                                       uint32_t addr) {
    asm volatile("ldmatrix.sync.aligned.m8n8.x4.trans.shared.b16 {%0,%1,%2,%3}, [%4];"
        : "=r"(r0), "=r"(r1), "=r"(r2), "=r"(r3) : "r"(addr));
}

__device__ __forceinline__ void cp_async16(uint32_t dst, const void* src, int srcsize) {
    asm volatile("cp.async.cg.shared.global [%0], [%1], 16, %2;"
                 :: "r"(dst), "l"(src), "r"(srcsize));
}

__device__ __forceinline__ int clamp_i(int v, int lo, int hi) {
    return v < lo ? lo : (v > hi ? hi : v);
}

// -------- fp16 convert (contiguous) --------
__global__ void conv_h_kernel(const float* __restrict__ src, __half* __restrict__ dst,
                              long long n4)
{
    long long stride = (long long)gridDim.x * blockDim.x;
    for (long long i = (long long)blockIdx.x * blockDim.x + threadIdx.x; i < n4; i += stride) {
        float4 v = *(const float4*)(src + i * 4);
        __half2 h0 = __floats2half2_rn(v.x, v.y);
        __half2 h1 = __floats2half2_rn(v.z, v.w);
        uint2 o = { *(uint32_t*)&h0, *(uint32_t*)&h1 };
        *(uint2*)(dst + i * 4) = o;
    }
}

// -------- fp16 convert + column-pack --------
__global__ void conv_pack_kernel(const float* __restrict__ src, __half* __restrict__ dst,
                                 int Kn, int Nn, int dstStride)
{
    long long n4 = (long long)Kn * Nn / 4;
    long long stride = (long long)gridDim.x * blockDim.x;
    for (long long i = (long long)blockIdx.x * blockDim.x + threadIdx.x; i < n4; i += stride) {
        long long e = i * 4;
        int row = (int)(e / Nn), col = (int)(e % Nn);
        float4 v = *(const float4*)(src + e);
        __half2 h0 = __floats2half2_rn(v.x, v.y);
        __half2 h1 = __floats2half2_rn(v.z, v.w);
        uint2 o = { *(uint32_t*)&h0, *(uint32_t*)&h1 };
        *(uint2*)(dst + (size_t)row * dstStride + col) = o;
    }
}

// -------- FF1 weight interleave (fp16): dst[k][2j]=a, dst[k][2j+1]=g --------
__global__ void conv_ileave_kernel(const float* __restrict__ src, __half* __restrict__ dst)
{
    long long n = (long long)CDIM * FFD;
    long long stride = (long long)gridDim.x * blockDim.x;
    for (long long i = (long long)blockIdx.x * blockDim.x + threadIdx.x; i < n; i += stride) {
        int k = (int)(i / FFD), j = (int)(i % FFD);
        float a = src[(size_t)k * FF2D + j];
        float g = src[(size_t)k * FF2D + FFD + j];
        __half2 o = __floats2half2_rn(a, g);
        *(__half2*)(dst + (size_t)k * FF2D + 2 * j) = o;
    }
}

// ---------------- LayerNorm (fp16 out) ----------------
__global__ void ln_kernel(const float* __restrict__ x, const float* __restrict__ g,
                          const float* __restrict__ bta, __half* __restrict__ out)
{
    __shared__ float sx[CDIM];
    __shared__ float red[8];
    int row = blockIdx.x, tid = threadIdx.x;
    const float* xr = x + (size_t)row * CDIM;
    float s = 0.f;
    for (int i = tid; i < CDIM; i += 256) { float v = xr[i]; sx[i] = v; s += v; }
    #pragma unroll
    for (int o = 16; o; o >>= 1) s += __shfl_xor_sync(0xffffffffu, s, o);
    if ((tid & 31) == 0) red[tid >> 5] = s;
    __syncthreads();
    float tot = 0.f;
    #pragma unroll
    for (int w = 0; w < 8; w++) tot += red[w];
    float mean = tot * (1.0f / (float)CDIM);
    float vs = 0.f;
    for (int i = tid; i < CDIM; i += 256) { float d = sx[i] - mean; vs += d * d; }
    __syncthreads();
    #pragma unroll
    for (int o = 16; o; o >>= 1) vs += __shfl_xor_sync(0xffffffffu, vs, o);
    if ((tid & 31) == 0) red[tid >> 5] = vs;
    __syncthreads();
    float tot2 = 0.f;
    #pragma unroll
    for (int w = 0; w < 8; w++) tot2 += red[w];
    float rstd = rsqrtf(tot2 * (1.0f / (float)CDIM) + 1e-5f);
    for (int i = tid; i < CDIM; i += 256)
        out[(size_t)row * CDIM + i] = __float2half_rn((sx[i] - mean) * rstd * g[i] + bta[i]);
}

// ============ FP16 GEMM: m16n8k16, 4-stage cp.async, 1 barrier / 2 ktiles ============
// HOUT: write fp16 output (amax still from fp32 accumulators).
template<bool HAS_BIAS, bool HAS_RES, bool DO_AMAX, bool SEG, bool GEGLU, bool HOUT>
__global__ void __launch_bounds__(256, 2) tgemm_kernel(
    const __half* __restrict__ A, const __half* __restrict__ Bm, float* __restrict__ Cm,
    int Mn, int Nn, int Kn,
    const float* __restrict__ bias, const float* __restrict__ res, unsigned* amax)
{
    constexpr int ST = 4;
    constexpr int APITCH = 24;                       // halfs; 48B row, 16B aligned
    constexpr uint32_t ABYTES = 128 * APITCH * 2;
    constexpr uint32_t BBYTES = 16 * 136 * 2;
    __shared__ __align__(16) __half As[ST][128][APITCH];
    __shared__ __align__(16) __half Bs[ST][16][136];
    __shared__ float reds[8];

    int tid  = threadIdx.x;
    int lane = tid & 31;
    int warp = tid >> 5;
    int wm = warp & 1;
    int wn = warp >> 1;
    int nBase = blockIdx.x * 128;
    int mBase = blockIdx.y * 128;

    uint32_t asmb = (uint32_t)__cvta_generic_to_shared(&As[0][0][0]);
    uint32_t bsmb = (uint32_t)__cvta_generic_to_shared(&Bs[0][0][0]);

    const int aR  = tid >> 1;
    const int aCk = (tid & 1) << 3;
    const int bK  = tid >> 4;
    const int bN  = (tid & 15) << 3;

    int r8 = lane & 7, sel = lane >> 3;
    uint32_t aoff = asmb + (((wm * 64 + r8 + ((sel & 1) << 3)) * APITCH + ((sel >> 1) << 3)) << 1);
    uint32_t boff = bsmb + ((((sel >> 1) * 8 + r8) * 136 + wn * 32 + ((sel & 1) << 3)) << 1);

    float acc[4][4][4];
    #pragma unroll
    for (int i = 0; i < 4; i++)
        #pragma unroll
        for (int j = 0; j < 4; j++)
            #pragma unroll
            for (int l = 0; l < 4; l++) acc[i][j][l] = 0.f;

    int KT = Kn >> 4;

    auto issue_stage = [&](int s, int k0) {
        int gr = mBase + aR;
        int ok = (gr < Mn);
        const __half* srcA = A + (size_t)(ok ? gr : 0) * Kn + k0 + aCk;
        cp_async16(asmb + s * ABYTES + ((aR * APITCH + aCk) << 1), srcA, ok ? 16 : 0);
        const __half* srcB = Bm + (size_t)(k0 + bK) * Nn + nBase + bN;
        cp_async16(bsmb + s * BBYTES + ((bK * 136 + bN) << 1), srcB, 16);
        asm volatile("cp.async.commit_group;" ::: "memory");
    };

    issue_stage(0, 0);
    issue_stage(1, 16);

    int lr = lane >> 2, lc = lane & 3;
    for (int kt = 0; kt < KT; kt += 2) {
        asm volatile("cp.async.wait_group 0;" ::: "memory");
        __syncthreads();
        if (kt + 2 < KT) {
            issue_stage((kt + 2) & 3, (kt + 2) << 4);
            issue_stage((kt + 3) & 3, (kt + 3) << 4);
        }
        #pragma unroll
        for (int sub = 0; sub < 2; sub++) {
            int buf = (kt + sub) & 3;
            uint32_t abuf = aoff + buf * ABYTES;
            uint32_t bbuf = boff + buf * BBYTES;
            uint32_t af[4][4], bf[4][2];
            #pragma unroll
            for (int mt = 0; mt < 4; mt++)
                ldsm4(af[mt][0], af[mt][1], af[mt][2], af[mt][3],
                      abuf + mt * (16 * APITCH * 2));
            #pragma unroll
            for (int np = 0; np < 2; np++)
                ldsm4t(bf[np*2][0], bf[np*2+1][0], bf[np*2][1], bf[np*2+1][1],
                       bbuf + np * 32);
            #pragma unroll
            for (int mt = 0; mt < 4; mt++)
                #pragma unroll
                for (int nt = 0; nt < 4; nt++)
                    mma_f16(acc[mt][nt], af[mt], bf[nt]);
        }
    }

    float amx = 0.f;
    #pragma unroll
    for (int mt = 0; mt < 4; mt++) {
        #pragma unroll
        for (int nt = 0; nt < 4; nt++) {
            int row0 = mBase + wm * 64 + mt * 16 + lr;
            int col0 = nBase + wn * 32 + nt * 8 + lc * 2;
            #pragma unroll
            for (int half = 0; half < 2; half++) {
                int row = row0 + half * 8;
                if (row < Mn) {
                    float c0 = acc[mt][nt][half * 2 + 0];
                    float c1 = acc[mt][nt][half * 2 + 1];
                    if (GEGLU) {
                        int j = col0 >> 1;
                        float a = c0 + bias[j];
                        float g = c1 + bias[FFD + j];
                        ((__half*)Cm)[(size_t)row * FFD + j] = __float2half_rn(a * gelu_tanh(g));
                    } else if (HOUT) {
                        __half2 o = __floats2half2_rn(c0, c1);
                        *(__half2*)(((__half*)Cm) + (size_t)row * Nn + col0) = o;
                        if (DO_AMAX) amx = fmaxf(amx, fmaxf(fabsf(c0), fabsf(c1)));
                    } else {
                        if (HAS_BIAS) { c0 += bias[col0]; c1 += bias[col0 + 1]; }
                        if (HAS_RES) {
                            c0 += res[(size_t)row * Nn + col0];
                            c1 += res[(size_t)row * Nn + col0 + 1];
                        }
                        float2 o = {c0, c1};
                        *(float2*)(Cm + (size_t)row * Nn + col0) = o;
                        if (DO_AMAX) amx = fmaxf(amx, fmaxf(fabsf(c0), fabsf(c1)));
                    }
                }
            }
        }
    }
    if (DO_AMAX) {
        #pragma unroll
        for (int o = 16; o; o >>= 1) amx = fmaxf(amx, __shfl_xor_sync(0xffffffffu, amx, o));
        if (lane == 0) reds[warp] = amx;
        __syncthreads();
        if (tid == 0) {
            float m = reds[0];
            #pragma unroll
            for (int w = 1; w < 8; w++) m = fmaxf(m, reds[w]);
            unsigned* tgt = amax + (SEG ? (nBase / 1280) : 0);
            atomicMax(tgt, __float_as_uint(m));
        }
    }
}

// -------- fp32 fake-quant in place (contiguous; cross Q) --------
__global__ void quant_sym_kernel(float* __restrict__ x, long long n4,
                                 const unsigned* __restrict__ amaxbits)
{
    float delta = fmaxf(__uint_as_float(*amaxbits), 1e-8f) / 127.0f;
    long long stride = (long long)gridDim.x * blockDim.x;
    for (long long i = (long long)blockIdx.x * blockDim.x + threadIdx.x; i < n4; i += stride) {
        float4 v = *(float4*)(x + i * 4);
        float l;
        l = rintf(v.x/delta); l = fminf(fmaxf(l,-128.f),127.f); v.x = l*delta;
        l = rintf(v.y/delta); l = fminf(fmaxf(l,-128.f),127.f); v.y = l*delta;
        l = rintf(v.z/delta); l = fminf(fmaxf(l,-128.f),127.f); v.z = l*delta;
        l = rintf(v.w/delta); l = fminf(fmaxf(l,-128.f),127.f); v.w = l*delta;
        *(float4*)(x + i * 4) = v;
    }
}

// -------- fp32 fake-quant, two column segments (cross K|V fused) --------
__global__ void quant_kv2_kernel(float* __restrict__ x, const unsigned* __restrict__ am)
{
    float d0 = fmaxf(__uint_as_float(am[0]), 1e-8f) / 127.0f;
    float d1 = fmaxf(__uint_as_float(am[1]), 1e-8f) / 127.0f;
    long long n4 = (long long)CROSSROWS * KV2N / 4;
    long long stride = (long long)gridDim.x * blockDim.x;
    for (long long i = (long long)blockIdx.x * blockDim.x + threadIdx.x; i < n4; i += stride) {
        int col = (int)((i * 4) % KV2N);
        float delta = (col < CDIM) ? d0 : d1;
        float4 v = *(float4*)(x + i * 4);
        float l;
        l = rintf(v.x/delta); l = fminf(fmaxf(l,-128.f),127.f); v.x = l*delta;
        l = rintf(v.y/delta); l = fminf(fmaxf(l,-128.f),127.f); v.y = l*delta;
        l = rintf(v.z/delta); l = fminf(fmaxf(l,-128.f),127.f); v.z = l*delta;
        l = rintf(v.w/delta); l = fminf(fmaxf(l,-128.f),127.f); v.w = l*delta;
        *(float4*)(x + i * 4) = v;
    }
}

// -------- s8 level quant from strided fp16 source (8 halfs / iter) --------
__global__ void quant_s8_strided_h(const __half* __restrict__ x, int8_t* __restrict__ L,
                                   const unsigned* __restrict__ amaxbits)
{
    float delta = fmaxf(__uint_as_float(*amaxbits), 1e-8f) / 127.0f;
    float inv = 1.0f / delta;
    long long n8 = (long long)ROWS * (CDIM / 8);
    long long stride = (long long)gridDim.x * blockDim.x;
    for (long long i = (long long)blockIdx.x * blockDim.x + threadIdx.x; i < n8; i += stride) {
        int row = (int)(i / (CDIM / 8));
        int c8 = (int)(i % (CDIM / 8));
        uint4 raw = *(const uint4*)(x + (size_t)row * QKVN + c8 * 8);
        const __half2* hp = (const __half2*)&raw;
        uint32_t outw[2];
        #pragma unroll
        for (int w = 0; w < 2; w++) {
            uint32_t o = 0;
            #pragma unroll
            for (int j = 0; j < 2; j++) {
                float2 f = __half22float2(hp[w*2 + j]);
                int a = clamp_i(__float2int_rn(f.x * inv), -128, 127);
                int b = clamp_i(__float2int_rn(f.y * inv), -128, 127);
                o |= ((uint32_t)(a & 255)) << (j*16);
                o |= ((uint32_t)(b & 255)) << (j*16 + 8);
            }
            outw[w] = o;
        }
        *(uint2*)(L + i * 8) = make_uint2(outw[0], outw[1]);
    }
}

// -------- V quant + per-head transpose (fp16 strided source) --------
__global__ void __launch_bounds__(256) quant_v_t_kernel(const __half* __restrict__ V,
                                                        int8_t* __restrict__ LVT,
                                                        const unsigned* __restrict__ amaxbits)
{
    __shared__ int8_t T[64][80];
    float delta = fmaxf(__uint_as_float(*amaxbits), 1e-8f) / 127.0f;
    float inv = 1.0f / delta;
    int tid = threadIdx.x;
    int bh = blockIdx.y, b = bh / NH, h = bh % NH;
    int m0 = blockIdx.x * 64;
    #pragma unroll
    for (int i = 0; i < 2; i++) {
        int lin = tid + i * 256;          // 0..511
        int r = lin >> 3;                 // m 0..63
        int c8 = (lin & 7) << 3;          // d 0..56
        uint4 raw = *(const uint4*)(V + ((size_t)(b*NSEQ + m0 + r))*QKVN + h*DH + c8);
        const __half2* hp = (const __half2*)&raw;
        #pragma unroll
        for (int j = 0; j < 4; j++) {
            float2 f = __half22float2(hp[j]);
            T[c8 + 2*j + 0][r] = (int8_t)clamp_i(__float2int_rn(f.x*inv), -128, 127);
            T[c8 + 2*j + 1][r] = (int8_t)clamp_i(__float2int_rn(f.y*inv), -128, 127);
        }
    }
    __syncthreads();
    int d = tid >> 2, ch = (tid & 3) << 4;
    int4 val = *(int4*)&T[d][ch];
    *(int4*)(LVT + ((size_t)(bh*DH + d))*NSEQ + m0 + ch) = val;
}

// ======== FUSED self-attn stats: recompute scores, online softmax ========
__global__ void __launch_bounds__(256) self_stats_i8_kernel(
    const int8_t* __restrict__ LQ, const int8_t* __restrict__ LK,
    float* __restrict__ RM, float* __restrict__ RZ, unsigned* __restrict__ am)
{
    __shared__ __align__(16) int8_t Qs[128][80];
    __shared__ __align__(16) int8_t Ks[128][80];
    __shared__ float red[128][4];
    __shared__ float tmaxS[128];
    __shared__ float rowmS[128], rowzS[128];
    __shared__ float wred[8];
    float dq = fmaxf(__uint_as_float(am[0]), 1e-8f) / 127.0f;
    float dk = fmaxf(__uint_as_float(am[1]), 1e-8f) / 127.0f;
    float scale = dq * dk * 0.125f;
    int tid = threadIdx.x, lane = tid & 31, warp = tid >> 5;
    int bh = blockIdx.y, b = bh / NH, h = bh % NH;
    int n0 = blockIdx.x * 128;
    int wn = warp & 1, wm = warp >> 1;
    int gr = lane >> 2, gc = lane & 3;

    #pragma unroll
    for (int i = 0; i < 2; i++) {
        int lin = tid + i * 256;
        int r = lin >> 2, ch = (lin & 3) << 4;
        *(int4*)&Qs[r][ch] = *(const int4*)(LQ + ((size_t)(b*NSEQ + n0 + r))*CDIM + h*DH + ch);
    }
    if (tid < 128) { rowmS[tid] = -3.4e38f; rowzS[tid] = 0.f; }

    int rows[8];
    #pragma unroll
    for (int nt = 0; nt < 4; nt++)
        #pragma unroll
        for (int half = 0; half < 2; half++)
            rows[nt*2+half] = wn*64 + nt*16 + gr + half*8;

    for (int mc = 0; mc < 8; mc++) {
        __syncthreads();
        #pragma unroll
        for (int i = 0; i < 2; i++) {
            int lin = tid + i * 256;
            int r = lin >> 2, ch = (lin & 3) << 4;
            *(int4*)&Ks[r][ch] = *(const int4*)(LK + ((size_t)(b*NSEQ + mc*128 + r))*CDIM + h*DH + ch);
        }
        __syncthreads();

        int acc[4][4][4];
        #pragma unroll
        for (int i = 0; i < 4; i++)
            #pragma unroll
            for (int j = 0; j < 4; j++)
                #pragma unroll
                for (int l = 0; l < 4; l++) acc[i][j][l] = 0;
        #pragma unroll
        for (int ks = 0; ks < 2; ks++) {
            uint32_t af[4][4], bf[4][2];
            #pragma unroll
            for (int nt = 0; nt < 4; nt++) {
                int row = wn * 64 + nt * 16 + gr;
                af[nt][0] = *(const uint32_t*)&Qs[row][ks*32 + gc*4];
                af[nt][1] = *(const uint32_t*)&Qs[row + 8][ks*32 + gc*4];
                af[nt][2] = *(const uint32_t*)&Qs[row][ks*32 + 16 + gc*4];
                af[nt][3] = *(const uint32_t*)&Qs[row + 8][ks*32 + 16 + gc*4];
            }
            #pragma unroll
            for (int mt = 0; mt < 4; mt++) {
                int col = wm * 32 + mt * 8 + gr;
                bf[mt][0] = *(const uint32_t*)&Ks[col][ks*32 + gc*4];
                bf[mt][1] = *(const uint32_t*)&Ks[col][ks*32 + 16 + gc*4];
            }
            #pragma unroll
            for (int nt = 0; nt < 4; nt++)
                #pragma unroll
                for (int mt = 0; mt < 4; mt++)
                    mma_s8(acc[nt][mt], af[nt], bf[mt]);
        }

        float lmax[8];
        #pragma unroll
        for (int j = 0; j < 8; j++) lmax[j] = -3.4e38f;
        #pragma unroll
        for (int nt = 0; nt < 4; nt++)
            #pragma unroll
            for (int mt = 0; mt < 4; mt++)
                #pragma unroll
                for (int c = 0; c < 4; c++)
                    lmax[nt*2 + (c>>1)] = fmaxf(lmax[nt*2 + (c>>1)], scale*(float)acc[nt][mt][c]);
        #pragma unroll
        for (int j = 0; j < 8; j++) {
            lmax[j] = fmaxf(lmax[j], __shfl_xor_sync(0xffffffffu, lmax[j], 1));
            lmax[j] = fmaxf(lmax[j], __shfl_xor_sync(0xffffffffu, lmax[j], 2));
        }
        if (gc == 0) {
            #pragma unroll
            for (int j = 0; j < 8; j++) red[rows[j]][wm] = lmax[j];
        }
        __syncthreads();
        if (tid < 128)
            tmaxS[tid] = fmaxf(fmaxf(red[tid][0], red[tid][1]), fmaxf(red[tid][2], red[tid][3]));
        __syncthreads();

        float lsum[8];
        #pragma unroll
        for (int j = 0; j < 8; j++) lsum[j] = 0.f;
        #pragma unroll
        for (int nt = 0; nt < 4; nt++) {
            float tm0 = tmaxS[rows[nt*2]];
            float tm1 = tmaxS[rows[nt*2+1]];
            #pragma unroll
            for (int mt = 0; mt < 4; mt++) {
                lsum[nt*2]   += __expf(scale*(float)acc[nt][mt][0] - tm0)
                              + __expf(scale*(float)acc[nt][mt][1] - tm0);
                lsum[nt*2+1] += __expf(scale*(float)acc[nt][mt][2] - tm1)
                              + __expf(scale*(float)acc[nt][mt][3] - tm1);
            }
        }
        #pragma unroll
        for (int j = 0; j < 8; j++) {
            lsum[j] += __shfl_xor_sync(0xffffffffu, lsum[j], 1);
            lsum[j] += __shfl_xor_sync(0xffffffffu, lsum[j], 2);
        }
        if (gc == 0) {
            #pragma unroll
            for (int j = 0; j < 8; j++) red[rows[j]][wm] = lsum[j];
        }
        __syncthreads();
        if (tid < 128) {
            float ts = red[tid][0] + red[tid][1] + red[tid][2] + red[tid][3];
            float tm = tmaxS[tid];
            float om = rowmS[tid];
            float nm = fmaxf(om, tm);
            rowzS[tid] = rowzS[tid] * __expf(om - nm) + ts * __expf(tm - nm);
            rowmS[tid] = nm;
        }
    }
    __syncthreads();
    float invz = -3.4e38f;
    if (tid < 128) {
        float z = rowzS[tid];
        RM[(size_t)bh*NSEQ + n0 + tid] = rowmS[tid];
        RZ[(size_t)bh*NSEQ + n0 + tid] = z;
        invz = 1.0f / z;
    }
    #pragma unroll
    for (int o = 16; o; o >>= 1) invz = fmaxf(invz, __shfl_xor_sync(0xffffffffu, invz, o));
    if (lane == 0) wred[warp] = invz;
    __syncthreads();
    if (tid == 0) {
        float m = wred[0];
        #pragma unroll
        for (int w = 1; w < 8; w++) m = fmaxf(m, wred[w]);
        atomicMax(am + 3, __float_as_uint(m));
    }
}

// ======== FUSED self-attn PV: recompute scores, fq_zero, u8xs8 PV (fp16 O out) ========
__global__ void __launch_bounds__(256) self_pv_i8_kernel(
    const int8_t* __restrict__ LQ, const int8_t* __restrict__ LK,
    const int8_t* __restrict__ LVT,
    const float* __restrict__ RM, const float* __restrict__ RZ,
    const unsigned* __restrict__ am, __half* __restrict__ O)
{
    __shared__ __align__(16) int8_t  Qs[128][80];
    __shared__ __align__(16) int8_t  Ks[128][80];
    __shared__ __align__(16) uint8_t Lws[128][144];
    __shared__ __align__(16) int8_t  VTs[64][144];
    __shared__ float rmS[128], riS[128];
    float dq = fmaxf(__uint_as_float(am[0]), 1e-8f) / 127.0f;
    float dk = fmaxf(__uint_as_float(am[1]), 1e-8f) / 127.0f;
    float scale = dq * dk * 0.125f;
    float dv = fmaxf(__uint_as_float(am[2]), 1e-8f) / 127.0f;
    float dw = fmaxf(__uint_as_float(am[3]), 1e-8f) / 255.0f;
    float inv_dw = 1.0f / dw;
    float oscale = dw * dv;
    int tid = threadIdx.x, lane = tid & 31, warp = tid >> 5;
    int bh = blockIdx.y, b = bh / NH, h = bh % NH;
    int n0 = blockIdx.x * 128;
    int wn = warp & 1, wm = warp >> 1, wd = warp >> 1;
    int gr = lane >> 2, gc = lane & 3;

    #pragma unroll
    for (int i = 0; i < 2; i++) {
        int lin = tid + i * 256;
        int r = lin >> 2, ch = (lin & 3) << 4;
        *(int4*)&Qs[r][ch] = *(const int4*)(LQ + ((size_t)(b*NSEQ + n0 + r))*CDIM + h*DH + ch);
    }
    if (tid < 128) {
        rmS[tid] = RM[(size_t)bh*NSEQ + n0 + tid];
        riS[tid] = 1.0f / RZ[(size_t)bh*NSEQ + n0 + tid];
    }

    int acc[4][2][4];
    #pragma unroll
    for (int i = 0; i < 4; i++)
        #pragma unroll
        for (int j = 0; j < 2; j++)
            #pragma unroll
            for (int l = 0; l < 4; l++) acc[i][j][l] = 0;

    for (int mc = 0; mc < 8; mc++) {
        __syncthreads();
        #pragma unroll
        for (int i = 0; i < 2; i++) {
            int lin = tid + i * 256;
            int r = lin >> 2, ch = (lin & 3) << 4;
            *(int4*)&Ks[r][ch] = *(const int4*)(LK + ((size_t)(b*NSEQ + mc*128 + r))*CDIM + h*DH + ch);
        }
        #pragma unroll
        for (int i = 0; i < 2; i++) {
            int lin = tid + i * 256;
            int d = lin >> 3, ch = (lin & 7) << 4;
            *(int4*)&VTs[d][ch] = *(const int4*)(LVT + ((size_t)(bh*DH + d))*NSEQ + mc*128 + ch);
        }
        __syncthreads();

        int sacc[4][4][4];
        #pragma unroll
        for (int i = 0; i < 4; i++)
            #pragma unroll
            for (int j = 0; j < 4; j++)
                #pragma unroll
                for (int l = 0; l < 4; l++) sacc[i][j][l] = 0;
        #pragma unroll
        for (int ks = 0; ks < 2; ks++) {
            uint32_t af[4][4], bf[4][2];
            #pragma unroll
            for (int nt = 0; nt < 4; nt++) {
                int row = wn * 64 + nt * 16 + gr;
                af[nt][0] = *(const uint32_t*)&Qs[row][ks*32 + gc*4];
                af[nt][1] = *(const uint32_t*)&Qs[row + 8][ks*32 + gc*4];
                af[nt][2] = *(const uint32_t*)&Qs[row][ks*32 + 16 + gc*4];
                af[nt][3] = *(const uint32_t*)&Qs[row + 8][ks*32 + 16 + gc*4];
            }
            #pragma unroll
            for (int mt = 0; mt < 4; mt++) {
                int col = wm * 32 + mt * 8 + gr;
                bf[mt][0] = *(const uint32_t*)&Ks[col][ks*32 + gc*4];
                bf[mt][1] = *(const uint32_t*)&Ks[col][ks*32 + 16 + gc*4];
            }
            #pragma unroll
            for (int nt = 0; nt < 4; nt++)
                #pragma unroll
                for (int mt = 0; mt < 4; mt++)
                    mma_s8(sacc[nt][mt], af[nt], bf[mt]);
        }
        #pragma unroll
        for (int nt = 0; nt < 4; nt++) {
            #pragma unroll
            for (int half = 0; half < 2; half++) {
                int row = wn*64 + nt*16 + gr + half*8;
                float rm = rmS[row];
                float f = riS[row] * inv_dw;
                #pragma unroll
                for (int mt = 0; mt < 4; mt++) {
                    int col = wm*32 + mt*8 + gc*2;
                    int l0 = min(255, __float2int_rn(__expf(scale*(float)sacc[nt][mt][half*2+0] - rm) * f));
                    int l1 = min(255, __float2int_rn(__expf(scale*(float)sacc[nt][mt][half*2+1] - rm) * f));
                    *(uint16_t*)&Lws[row][col] = (uint16_t)(l0 | (l1 << 8));
                }
            }
        }
        __syncthreads();

        #pragma unroll
        for (int ks = 0; ks < 4; ks++) {
            uint32_t af[4][4], bf[2][2];
            #pragma unroll
            for (int nt = 0; nt < 4; nt++) {
                int row = wn * 64 + nt * 16 + gr;
                af[nt][0] = *(const uint32_t*)&Lws[row][ks*32 + gc*4];
                af[nt][1] = *(const uint32_t*)&Lws[row + 8][ks*32 + gc*4];
                af[nt][2] = *(const uint32_t*)&Lws[row][ks*32 + 16 + gc*4];
                af[nt][3] = *(const uint32_t*)&Lws[row + 8][ks*32 + 16 + gc*4];
            }
            #pragma unroll
            for (int dt = 0; dt < 2; dt++) {
                int col = wd * 16 + dt * 8 + gr;
                bf[dt][0] = *(const uint32_t*)&VTs[col][ks*32 + gc*4];
                bf[dt][1] = *(const uint32_t*)&VTs[col][ks*32 + 16 + gc*4];
            }
            #pragma unroll
            for (int nt = 0; nt < 4; nt++)
                #pragma unroll
                for (int dt = 0; dt < 2; dt++)
                    mma_u8s8(acc[nt][dt], af[nt], bf[dt]);
        }
    }
    #pragma unroll
    for (int nt = 0; nt < 4; nt++) {
        #pragma unroll
        for (int dt = 0; dt < 2; dt++) {
            int row0 = n0 + wn * 64 + nt * 16 + gr;
            int col0 = wd * 16 + dt * 8 + gc * 2;
            #pragma unroll
            for (int half = 0; half < 2; half++) {
                int row = row0 + half * 8;
                __half2 o = __floats2half2_rn(oscale * (float)acc[nt][dt][half*2+0],
                                              oscale * (float)acc[nt][dt][half*2+1]);
                *(__half2*)(O + ((size_t)(b*NSEQ + row))*CDIM + h*DH + col0) = o;
            }
        }
    }
}

// -------- softmax row stats (cross path) --------
__global__ void softmax_stats_kernel(const float* __restrict__ S, float* __restrict__ rowmax,
                                     float* __restrict__ rowz, unsigned* wmax, int cols, int stride)
{
    int row = blockIdx.x, tid = threadIdx.x;
    const float* s = S + (size_t)row * stride;
    __shared__ float red[8];
    float m = -3.4e38f;
    for (int i = tid; i < cols; i += 256) m = fmaxf(m, s[i]);
    #pragma unroll
    for (int o = 16; o; o >>= 1) m = fmaxf(m, __shfl_xor_sync(0xffffffffu, m, o));
    if ((tid & 31) == 0) red[tid >> 5] = m;
    __syncthreads();
    float mm = red[0];
    #pragma unroll
    for (int w = 1; w < 8; w++) mm = fmaxf(mm, red[w]);
    __syncthreads();
    float z = 0.f;
    for (int i = tid; i < cols; i += 256) z += __expf(s[i] - mm);
    #pragma unroll
    for (int o = 16; o; o >>= 1) z += __shfl_xor_sync(0xffffffffu, z, o);
    if ((tid & 31) == 0) red[tid >> 5] = z;
    __syncthreads();
    if (tid == 0) {
        float zz = 0.f;
        #pragma unroll
        for (int w = 0; w < 8; w++) zz += red[w];
        rowmax[row] = mm; rowz[row] = zz;
        atomicMax(wmax, __float_as_uint(1.0f / zz));
    }
}

// -------- cross-attn scores (fp32, M=77, stride 80; K source strided) --------
__global__ void __launch_bounds__(256) cross_scores_kernel(
    const float* __restrict__ q, const float* __restrict__ k, int kstride,
    float* __restrict__ S)
{
    __shared__ __align__(16) float Qs[64][68];
    __shared__ __align__(16) float Ks[80][68];
    int tid = threadIdx.x;
    int bh = blockIdx.y, b = bh / NH, h = bh % NH;
    int n0 = blockIdx.x * 64;
    #pragma unroll
    for (int it = 0; it < 4; ++it) {
        int r = (tid >> 4) + it * 16, c = (tid & 15) << 2;
        float4 qv = *(const float4*)(q + ((size_t)(b*NSEQ + n0 + r))*CDIM + h*DH + c);
        Qs[c+0][r]=qv.x; Qs[c+1][r]=qv.y; Qs[c+2][r]=qv.z; Qs[c+3][r]=qv.w;
    }
    #pragma unroll
    for (int it = 0; it < 5; ++it) {
        int lin = tid + it * 256;
        if (lin < 80 * 16) {
            int r = lin >> 4, c = (lin & 15) << 2;
            float4 kv = (r < MCTX) ? *(const float4*)(k + ((size_t)(b*MCTX + r))*kstride + h*DH + c)
                                   : make_float4(0.f,0.f,0.f,0.f);
            *(float4*)&Ks[r][c] = kv;
        }
    }
    __syncthreads();
    int tx = tid & 15, ty = tid >> 4;
    float acc[4][5];
    #pragma unroll
    for (int i = 0; i < 4; i++)
        #pragma unroll
        for (int j = 0; j < 5; j++) acc[i][j] = 0.f;
    #pragma unroll 4
    for (int d = 0; d < 64; ++d) {
        float4 q4 = *(const float4*)&Qs[d][ty*4];
        float qa[4]={q4.x,q4.y,q4.z,q4.w};
        #pragma unroll
        for (int jj = 0; jj < 5; jj++) {
            float kv = Ks[tx*5+jj][d];
            #pragma unroll
            for (int i = 0; i < 4; i++) acc[i][jj] = fmaf(qa[i], kv, acc[i][jj]);
        }
    }
    #pragma unroll
    for (int i = 0; i < 4; i++)
        #pragma unroll
        for (int jj = 0; jj < 5; jj++) {
            int m = tx * 5 + jj;
            if (m < MCTX)
                S[((size_t)bh*NSEQ + n0 + ty*4 + i)*80 + m] = acc[i][jj] * 0.125f;
        }
}

// -------- cross-attn PV (fp32; V source strided; fp16 O out) --------
__global__ void __launch_bounds__(256) cross_pv_kernel(
    const float* __restrict__ S, const float* __restrict__ v, int vstride,
    const float* __restrict__ rowmax, const float* __restrict__ rowz,
    const unsigned* __restrict__ wmaxbits, __half* __restrict__ O)
{
    __shared__ __align__(16) float Ws[80][68];
    __shared__ __align__(16) float Vs[80][68];
    int tid = threadIdx.x;
    int bh = blockIdx.y, b = bh / NH, h = bh % NH;
    int n0 = blockIdx.x * 64;
    int tx = tid & 15, ty = tid >> 4;
    float delta = fmaxf(__uint_as_float(*wmaxbits), 1e-8f) / 255.0f;
    float inv_delta = 1.0f / delta;
    #pragma unroll
    for (int it = 0; it < 5; ++it) {
        int lin = tid + it * 256;
        if (lin < MCTX * 16) {
            int r = lin >> 4, c = (lin & 15) << 2;
            *(float4*)&Vs[r][c] = *(const float4*)(v + ((size_t)(b*MCTX + r))*vstride + h*DH + c);
        }
    }
    #pragma unroll
    for (int it = 0; it < 4; ++it) {
        int r = (tid >> 4) + it * 16;
        float rm = rowmax[(size_t)bh*NSEQ + n0 + r];
        float ri = 1.0f / rowz[(size_t)bh*NSEQ + n0 + r];
        #pragma unroll
        for (int jj = 0; jj < 5; jj++) {
            int m = (tid & 15) * 5 + jj;
            float w = 0.f;
            if (m < MCTX) {
                float s = S[((size_t)bh*NSEQ + n0 + r)*80 + m];
                float p = __expf(s - rm);
                float l = rintf(p * ri * inv_delta);
                l = fminf(fmaxf(l, 0.f), 255.f);
                w = l * delta;
            }
            Ws[m][r] = w;
        }
    }
    __syncthreads();
    float acc[4][4];
    #pragma unroll
    for (int i = 0; i < 4; i++)
        #pragma unroll
        for (int j = 0; j < 4; j++) acc[i][j] = 0.f;
    for (int m = 0; m < MCTX; m++) {
        float4 w4 = *(const float4*)&Ws[m][ty*4];
        float4 v4 = *(const float4*)&Vs[m][tx*4];
        float wa[4]={w4.x,w4.y,w4.z,w4.w}, va[4]={v4.x,v4.y,v4.z,v4.w};
        #pragma unroll
        for (int i = 0; i < 4; i++)
            #pragma unroll
            for (int j = 0; j < 4; j++) acc[i][j] = fmaf(wa[i], va[j], acc[i][j]);
    }
    #pragma unroll
    for (int i = 0; i < 4; i++) {
        __half* Ob = O + ((size_t)(b*NSEQ + n0 + ty*4 + i))*CDIM + h*DH + tx*4;
        *(__half2*)(Ob + 0) = __floats2half2_rn(acc[i][0], acc[i][1]);
        *(__half2*)(Ob + 2) = __floats2half2_rn(acc[i][2], acc[i][3]);
    }
}

extern "C" void kernel_launch(void* const* d_in, const int* in_sizes, int n_in,
                              void* d_out, int out_size)
{
    const float* x    = (const float*)d_in[0];
    const float* ctx  = (const float*)d_in[1];
    const float* ln1g = (const float*)d_in[2];
    const float* ln1b = (const float*)d_in[3];
    const float* ln2g = (const float*)d_in[4];
    const float* ln2b = (const float*)d_in[5];
    const float* ln3g = (const float*)d_in[6];
    const float* ln3b = (const float*)d_in[7];
    const float* Wq1  = (const float*)d_in[8];
    const float* Wk1  = (const float*)d_in[9];
    const float* Wv1  = (const float*)d_in[10];
    const float* Wo1  = (const float*)d_in[11];
    const float* bo1  = (const float*)d_in[12];
    const float* Wq2  = (const float*)d_in[13];
    const float* Wk2  = (const float*)d_in[14];
    const float* Wv2  = (const float*)d_in[15];
    const float* Wo2  = (const float*)d_in[16];
    const float* bo2  = (const float*)d_in[17];
    const float* Wff1 = (const float*)d_in[18];
    const float* bff1 = (const float*)d_in[19];
    const float* Wff2 = (const float*)d_in[20];
    const float* bff2 = (const float*)d_in[21];
    float* out = (float*)d_out;

    float* sc = nullptr;
    cudaGetSymbolAddress((void**)&sc, g_scratch);
    __half* XN  = (__half*)(sc + OFF_XN);
    __half* QKVh = (__half*)(sc + OFF_Q);     // fp16 QKV buffer
    float*  Qc  = sc + OFF_Q;                 // cross-phase fp32 Q (reuses space)
    float*  KV2 = sc + OFF_K;
    __half* O   = (__half*)(sc + OFF_O);
    float*  X1  = sc + OFF_X1;
    float*  S   = sc + OFF_S;
    __half* G   = (__half*)(sc + OFF_G);
    float*  RM  = sc + OFF_RM;
    float*  RZ  = sc + OFF_RZ;
    unsigned* AM = (unsigned*)(sc + OFF_AM);
    __half* cWqkv = (__half*)(sc + OFF_WQKV);
    __half* cWo1  = (__half*)(sc + OFF_WO1);
    __half* cWq2  = (__half*)(sc + OFF_WQ2);
    __half* cWo2  = (__half*)(sc + OFF_WO2);
    __half* cWkv2 = (__half*)(sc + OFF_WKV2);
    __half* cWf1  = (__half*)(sc + OFF_WF1);
    __half* cWf2  = (__half*)(sc + OFF_WF2);
    __half* cCtx  = (__half*)(sc + OFF_CTX);
    int8_t* LQ8 = (int8_t*)(sc + OFF_LQ8);
    int8_t* LK8 = (int8_t*)(sc + OFF_LK8);
    int8_t* LVT = (int8_t*)(sc + OFF_LVT);

    dim3 g1280(CDIM / 128, ROWS / 128);
    dim3 gqkv(QKVN / 128, ROWS / 128);
    dim3 gkv2(KV2N / 128, (CROSSROWS + 127) / 128);
    dim3 gff1(FF2D / 128, ROWS / 128);
    long long n4 = (long long)ROWS * CDIM / 4;

    init_amax_kernel<<<1, 32>>>(AM);

    conv_pack_kernel<<<512,256>>>(Wq1, cWqkv + 0,      CDIM, CDIM, QKVN);
    conv_pack_kernel<<<512,256>>>(Wk1, cWqkv + CDIM,   CDIM, CDIM, QKVN);
    conv_pack_kernel<<<512,256>>>(Wv1, cWqkv + 2*CDIM, CDIM, CDIM, QKVN);
    conv_pack_kernel<<<512,256>>>(Wk2, cWkv2 + 0,    CTXC, CDIM, KV2N);
    conv_pack_kernel<<<512,256>>>(Wv2, cWkv2 + CDIM, CTXC, CDIM, KV2N);
    conv_h_kernel<<<1024,256>>>(Wo1,  cWo1, (long long)SZ_W1/4);
    conv_h_kernel<<<1024,256>>>(Wq2,  cWq2, (long long)SZ_W1/4);
    conv_h_kernel<<<1024,256>>>(Wo2,  cWo2, (long long)SZ_W1/4);
    conv_ileave_kernel<<<2048,256>>>(Wff1, cWf1);
    conv_h_kernel<<<2048,256>>>(Wff2, cWf2, (long long)SZ_WF2/4);
    conv_h_kernel<<<512,256>>>(ctx,   cCtx, (long long)SZ_CTXB/4);

    // ---- block 1: self attention (fp16 QKV intermediate, int8 flash path) ----
    ln_kernel<<<ROWS, 256>>>(x, ln1g, ln1b, XN);
    tgemm_kernel<false,false,true,true,false,true><<<gqkv,256>>>(XN, cWqkv, (float*)QKVh, ROWS, QKVN, CDIM, nullptr, nullptr, AM+0);
    quant_s8_strided_h<<<1024,256>>>(QKVh + 0,    LQ8, AM+0);
    quant_s8_strided_h<<<1024,256>>>(QKVh + CDIM, LK8, AM+1);
    quant_v_t_kernel<<<dim3(NSEQ/64, BHD),256>>>(QKVh + 2*CDIM, LVT, AM+2);
    self_stats_i8_kernel<<<dim3(8,BHD),256>>>(LQ8, LK8, RM, RZ, AM);
    self_pv_i8_kernel<<<dim3(8,BHD),256>>>(LQ8, LK8, LVT, RM, RZ, AM, O);
    tgemm_kernel<true,true,false,false,false,false><<<g1280,256>>>(O, cWo1, X1, ROWS, CDIM, CDIM, bo1, x, nullptr);

    // ---- block 2: cross attention (fp32 intermediates) ----
    ln_kernel<<<ROWS,256>>>(X1, ln2g, ln2b, XN);
    tgemm_kernel<false,false,true,false,false,false><<<g1280,256>>>(XN, cWq2, Qc, ROWS, CDIM, CDIM, nullptr, nullptr, AM+4);
    tgemm_kernel<false,false,true,true,false,false><<<gkv2,256>>>(cCtx, cWkv2, KV2, CROSSROWS, KV2N, CTXC, nullptr, nullptr, AM+5);
    quant_sym_kernel<<<2048,256>>>(Qc, n4, AM+4);
    quant_kv2_kernel<<<1024,256>>>(KV2, AM+5);
    cross_scores_kernel<<<dim3(16,BHD),256>>>(Qc, KV2, KV2N, S);
    softmax_stats_kernel<<<BHD*NSEQ,256>>>(S, RM, RZ, AM+7, MCTX, 80);
    cross_pv_kernel<<<dim3(16,BHD),256>>>(S, KV2 + CDIM, KV2N, RM, RZ, AM+7, O);
    tgemm_kernel<true,true,false,false,false,false><<<g1280,256>>>(O, cWo2, X1, ROWS, CDIM, CDIM, bo2, X1, nullptr);

    // ---- block 3: GEGLU FF (geglu fused into FF1 epilogue, fp16 G) ----
    ln_kernel<<<ROWS,256>>>(X1, ln3g, ln3b, XN);
    tgemm_kernel<true,false,false,false,true,false><<<gff1,256>>>(XN, cWf1, (float*)G, ROWS, FF2D, CDIM, bff1, nullptr, nullptr);
    tgemm_kernel<true,true,false,false,false,false><<<g1280,256>>>(G, cWf2, out, ROWS, CDIM, FFD, bff2, X1, nullptr);
}

// round 16
// speedup vs baseline: 1.7492x; 1.0368x over previous
#include <cuda_runtime.h>
#include <cuda_fp16.h>
#include <cstdint>

#define NB 8
#define NSEQ 1024
#define CDIM 1280
#define NH 20
#define DH 64
#define MCTX 77
#define CTXC 768
#define FFD 5120
#define FF2D 10240
#define ROWS (NB*NSEQ)
#define BHD (NB*NH)
#define CROSSROWS (NB*MCTX)
#define QKVN 3840
#define KV2N 2560

static constexpr size_t SZ_XC = (size_t)ROWS * CDIM;
static constexpr size_t OFF_XN = 0;
static constexpr size_t OFF_Q  = OFF_XN + SZ_XC;     // QKV fused fp16 / cross Q fp16
static constexpr size_t OFF_K  = OFF_Q + SZ_XC;      // cross-phase: KV2 fp16 [616][2560]
static constexpr size_t OFF_V  = OFF_K + SZ_XC;
static constexpr size_t OFF_O  = OFF_V + SZ_XC;      // O: fp16
static constexpr size_t OFF_X1 = OFF_O + SZ_XC;
static constexpr size_t OFF_G  = OFF_X1 + SZ_XC;     // G: fp16
static constexpr size_t SZ_G   = (size_t)ROWS * FFD;
static constexpr size_t OFF_RM = OFF_G + SZ_G;
static constexpr size_t OFF_RZ = OFF_RM + (size_t)BHD * NSEQ;
static constexpr size_t OFF_AM = OFF_RZ + (size_t)BHD * NSEQ;
static constexpr size_t SZ_W1  = (size_t)CDIM * CDIM;
static constexpr size_t SZ_WK2 = (size_t)CTXC * CDIM;
static constexpr size_t SZ_WF1 = (size_t)CDIM * FF2D;
static constexpr size_t SZ_WF2 = (size_t)FFD * CDIM;
static constexpr size_t SZ_CTXB = (size_t)CROSSROWS * CTXC;
static constexpr size_t OFF_WQKV = OFF_AM + 8;
static constexpr size_t OFF_WO1  = OFF_WQKV + 3 * SZ_W1;
static constexpr size_t OFF_WQ2  = OFF_WO1 + SZ_W1;
static constexpr size_t OFF_WO2  = OFF_WQ2 + SZ_W1;
static constexpr size_t OFF_WKV2 = OFF_WO2 + SZ_W1;
static constexpr size_t OFF_WF1  = OFF_WKV2 + 2 * SZ_WK2;
static constexpr size_t OFF_WF2  = OFF_WF1 + SZ_WF1;
static constexpr size_t OFF_CTX  = OFF_WF2 + SZ_WF2;
static constexpr size_t SZ_S8F   = (size_t)ROWS * CDIM / 4;
static constexpr size_t OFF_LQ8  = OFF_CTX + SZ_CTXB;
static constexpr size_t OFF_LK8  = OFF_LQ8 + SZ_S8F;
static constexpr size_t OFF_LVT  = OFF_LK8 + SZ_S8F;
static constexpr size_t TOTAL_SCRATCH = OFF_LVT + SZ_S8F;

__device__ __align__(256) float g_scratch[TOTAL_SCRATCH];

__global__ void init_amax_kernel(unsigned* amax) {
    if (threadIdx.x < 8) amax[threadIdx.x] = 0u;
}

__device__ __forceinline__ float gelu_tanh(float x) {
    float x3 = x * x * x;
    return 0.5f * x * (1.0f + tanhf(0.7978845608028654f * (x + 0.044715f * x3)));
}

__device__ __forceinline__ void mma_f16(float* d, const uint32_t* a, const uint32_t* b) {
    asm volatile("mma.sync.aligned.m16n8k16.row.col.f32.f16.f16.f32 "
        "{%0,%1,%2,%3}, {%4,%5,%6,%7}, {%8,%9}, {%0,%1,%2,%3};"
        : "+f"(d[0]), "+f"(d[1]), "+f"(d[2]), "+f"(d[3])
        : "r"(a[0]), "r"(a[1]), "r"(a[2]), "r"(a[3]), "r"(b[0]), "r"(b[1]));
}

__device__ __forceinline__ void mma_s8(int* d, const uint32_t* a, const uint32_t* b) {
    asm volatile("mma.sync.aligned.m16n8k32.row.col.s32.s8.s8.s32 "
        "{%0,%1,%2,%3}, {%4,%5,%6,%7}, {%8,%9}, {%0,%1,%2,%3};"
        : "+r"(d[0]), "+r"(d[1]), "+r"(d[2]), "+r"(d[3])
        : "r"(a[0]), "r"(a[1]), "r"(a[2]), "r"(a[3]), "r"(b[0]), "r"(b[1]));
}

__device__ __forceinline__ void mma_u8s8(int* d, const uint32_t* a, const uint32_t* b) {
    asm volatile("mma.sync.aligned.m16n8k32.row.col.s32.u8.s8.s32 "
        "{%0,%1,%2,%3}, {%4,%5,%6,%7}, {%8,%9}, {%0,%1,%2,%3};"
        : "+r"(d[0]), "+r"(d[1]), "+r"(d[2]), "+r"(d[3])
        : "r"(a[0]), "r"(a[1]), "r"(a[2]), "r"(a[3]), "r"(b[0]), "r"(b[1]));
}

__device__ __forceinline__ void ldsm4(uint32_t& r0, uint32_t& r1, uint32_t& r2, uint32_t& r3,
                                      uint32_t addr) {
    asm volatile("ldmatrix.sync.aligned.m8n8.x4.shared.b16 {%0,%1,%2,%3}, [%4];"
        : "=r"(r0), "=r"(r1), "=r"(r2), "=r"(r3) : "r"(addr));
}

__device__ __forceinline__ void ldsm4t(uint32_t& r0, uint32_t& r1, uint32_t& r2, uint32_t& r3,
                                       uint32_t addr) {
    asm volatile("ldmatrix.sync.aligned.m8n8.x4.trans.shared.b16 {%0,%1,%2,%3}, [%4];"
        : "=r"(r0), "=r"(r1), "=r"(r2), "=r"(r3) : "r"(addr));
}

__device__ __forceinline__ void cp_async16(uint32_t dst, const void* src, int srcsize) {
    asm volatile("cp.async.cg.shared.global [%0], [%1], 16, %2;"
                 :: "r"(dst), "l"(src), "r"(srcsize));
}

__device__ __forceinline__ int clamp_i(int v, int lo, int hi) {
    return v < lo ? lo : (v > hi ? hi : v);
}

__device__ __forceinline__ float fq_h(__half h, float inv, float delta) {
    float v = __half2float(h);
    float l = rintf(v * inv);
    l = fminf(fmaxf(l, -128.f), 127.f);
    return l * delta;
}

// -------- fp16 convert (contiguous) --------
__global__ void conv_h_kernel(const float* __restrict__ src, __half* __restrict__ dst,
                              long long n4)
{
    long long stride = (long long)gridDim.x * blockDim.x;
    for (long long i = (long long)blockIdx.x * blockDim.x + threadIdx.x; i < n4; i += stride) {
        float4 v = *(const float4*)(src + i * 4);
        __half2 h0 = __floats2half2_rn(v.x, v.y);
        __half2 h1 = __floats2half2_rn(v.z, v.w);
        uint2 o = { *(uint32_t*)&h0, *(uint32_t*)&h1 };
        *(uint2*)(dst + i * 4) = o;
    }
}

// -------- fp16 convert + column-pack --------
__global__ void conv_pack_kernel(const float* __restrict__ src, __half* __restrict__ dst,
                                 int Kn, int Nn, int dstStride)
{
    long long n4 = (long long)Kn * Nn / 4;
    long long stride = (long long)gridDim.x * blockDim.x;
    for (long long i = (long long)blockIdx.x * blockDim.x + threadIdx.x; i < n4; i += stride) {
        long long e = i * 4;
        int row = (int)(e / Nn), col = (int)(e % Nn);
        float4 v = *(const float4*)(src + e);
        __half2 h0 = __floats2half2_rn(v.x, v.y);
        __half2 h1 = __floats2half2_rn(v.z, v.w);
        uint2 o = { *(uint32_t*)&h0, *(uint32_t*)&h1 };
        *(uint2*)(dst + (size_t)row * dstStride + col) = o;
    }
}

// -------- FF1 weight interleave (fp16) --------
__global__ void conv_ileave_kernel(const float* __restrict__ src, __half* __restrict__ dst)
{
    long long n = (long long)CDIM * FFD;
    long long stride = (long long)gridDim.x * blockDim.x;
    for (long long i = (long long)blockIdx.x * blockDim.x + threadIdx.x; i < n; i += stride) {
        int k = (int)(i / FFD), j = (int)(i % FFD);
        float a = src[(size_t)k * FF2D + j];
        float g = src[(size_t)k * FF2D + FFD + j];
        __half2 o = __floats2half2_rn(a, g);
        *(__half2*)(dst + (size_t)k * FF2D + 2 * j) = o;
    }
}

// ---------------- LayerNorm (fp16 out) ----------------
__global__ void ln_kernel(const float* __restrict__ x, const float* __restrict__ g,
                          const float* __restrict__ bta, __half* __restrict__ out)
{
    __shared__ float sx[CDIM];
    __shared__ float red[8];
    int row = blockIdx.x, tid = threadIdx.x;
    const float* xr = x + (size_t)row * CDIM;
    float s = 0.f;
    for (int i = tid; i < CDIM; i += 256) { float v = xr[i]; sx[i] = v; s += v; }
    #pragma unroll
    for (int o = 16; o; o >>= 1) s += __shfl_xor_sync(0xffffffffu, s, o);
    if ((tid & 31) == 0) red[tid >> 5] = s;
    __syncthreads();
    float tot = 0.f;
    #pragma unroll
    for (int w = 0; w < 8; w++) tot += red[w];
    float mean = tot * (1.0f / (float)CDIM);
    float vs = 0.f;
    for (int i = tid; i < CDIM; i += 256) { float d = sx[i] - mean; vs += d * d; }
    __syncthreads();
    #pragma unroll
    for (int o = 16; o; o >>= 1) vs += __shfl_xor_sync(0xffffffffu, vs, o);
    if ((tid & 31) == 0) red[tid >> 5] = vs;
    __syncthreads();
    float tot2 = 0.f;
    #pragma unroll
    for (int w = 0; w < 8; w++) tot2 += red[w];
    float rstd = rsqrtf(tot2 * (1.0f / (float)CDIM) + 1e-5f);
    for (int i = tid; i < CDIM; i += 256)
        out[(size_t)row * CDIM + i] = __float2half_rn((sx[i] - mean) * rstd * g[i] + bta[i]);
}

// ============ FP16 GEMM: m16n8k16, 4-stage cp.async, 1 barrier / 2 ktiles ============
template<bool HAS_BIAS, bool HAS_RES, bool DO_AMAX, bool SEG, bool GEGLU, bool HOUT>
__global__ void __launch_bounds__(256, 2) tgemm_kernel(
    const __half* __restrict__ A, const __half* __restrict__ Bm, float* __restrict__ Cm,
    int Mn, int Nn, int Kn,
    const float* __restrict__ bias, const float* __restrict__ res, unsigned* amax)
{
    constexpr int ST = 4;
    constexpr int APITCH = 24;
    constexpr uint32_t ABYTES = 128 * APITCH * 2;
    constexpr uint32_t BBYTES = 16 * 136 * 2;
    __shared__ __align__(16) __half As[ST][128][APITCH];
    __shared__ __align__(16) __half Bs[ST][16][136];
    __shared__ float reds[8];

    int tid  = threadIdx.x;
    int lane = tid & 31;
    int warp = tid >> 5;
    int wm = warp & 1;
    int wn = warp >> 1;
    int nBase = blockIdx.x * 128;
    int mBase = blockIdx.y * 128;

    uint32_t asmb = (uint32_t)__cvta_generic_to_shared(&As[0][0][0]);
    uint32_t bsmb = (uint32_t)__cvta_generic_to_shared(&Bs[0][0][0]);

    const int aR  = tid >> 1;
    const int aCk = (tid & 1) << 3;
    const int bK  = tid >> 4;
    const int bN  = (tid & 15) << 3;

    int r8 = lane & 7, sel = lane >> 3;
    uint32_t aoff = asmb + (((wm * 64 + r8 + ((sel & 1) << 3)) * APITCH + ((sel >> 1) << 3)) << 1);
    uint32_t boff = bsmb + ((((sel >> 1) * 8 + r8) * 136 + wn * 32 + ((sel & 1) << 3)) << 1);

    float acc[4][4][4];
    #pragma unroll
    for (int i = 0; i < 4; i++)
        #pragma unroll
        for (int j = 0; j < 4; j++)
            #pragma unroll
            for (int l = 0; l < 4; l++) acc[i][j][l] = 0.f;

    int KT = Kn >> 4;

    auto issue_stage = [&](int s, int k0) {
        int gr = mBase + aR;
        int ok = (gr < Mn);
        const __half* srcA = A + (size_t)(ok ? gr : 0) * Kn + k0 + aCk;
        cp_async16(asmb + s * ABYTES + ((aR * APITCH + aCk) << 1), srcA, ok ? 16 : 0);
        const __half* srcB = Bm + (size_t)(k0 + bK) * Nn + nBase + bN;
        cp_async16(bsmb + s * BBYTES + ((bK * 136 + bN) << 1), srcB, 16);
        asm volatile("cp.async.commit_group;" ::: "memory");
    };

    issue_stage(0, 0);
    issue_stage(1, 16);

    int lr = lane >> 2, lc = lane & 3;
    for (int kt = 0; kt < KT; kt += 2) {
        asm volatile("cp.async.wait_group 0;" ::: "memory");
        __syncthreads();
        if (kt + 2 < KT) {
            issue_stage((kt + 2) & 3, (kt + 2) << 4);
            issue_stage((kt + 3) & 3, (kt + 3) << 4);
        }
        #pragma unroll
        for (int sub = 0; sub < 2; sub++) {
            int buf = (kt + sub) & 3;
            uint32_t abuf = aoff + buf * ABYTES;
            uint32_t bbuf = boff + buf * BBYTES;
            uint32_t af[4][4], bf[4][2];
            #pragma unroll
            for (int mt = 0; mt < 4; mt++)
                ldsm4(af[mt][0], af[mt][1], af[mt][2], af[mt][3],
                      abuf + mt * (16 * APITCH * 2));
            #pragma unroll
            for (int np = 0; np < 2; np++)
                ldsm4t(bf[np*2][0], bf[np*2+1][0], bf[np*2][1], bf[np*2+1][1],
                       bbuf + np * 32);
            #pragma unroll
            for (int mt = 0; mt < 4; mt++)
                #pragma unroll
                for (int nt = 0; nt < 4; nt++)
                    mma_f16(acc[mt][nt], af[mt], bf[nt]);
        }
    }

    float amx = 0.f;
    #pragma unroll
    for (int mt = 0; mt < 4; mt++) {
        #pragma unroll
        for (int nt = 0; nt < 4; nt++) {
            int row0 = mBase + wm * 64 + mt * 16 + lr;
            int col0 = nBase + wn * 32 + nt * 8 + lc * 2;
            #pragma unroll
            for (int half = 0; half < 2; half++) {
                int row = row0 + half * 8;
                if (row < Mn) {
                    float c0 = acc[mt][nt][half * 2 + 0];
                    float c1 = acc[mt][nt][half * 2 + 1];
                    if (GEGLU) {
                        int j = col0 >> 1;
                        float a = c0 + bias[j];
                        float g = c1 + bias[FFD + j];
                        ((__half*)Cm)[(size_t)row * FFD + j] = __float2half_rn(a * gelu_tanh(g));
                    } else if (HOUT) {
                        __half2 o = __floats2half2_rn(c0, c1);
                        *(__half2*)(((__half*)Cm) + (size_t)row * Nn + col0) = o;
                        if (DO_AMAX) amx = fmaxf(amx, fmaxf(fabsf(c0), fabsf(c1)));
                    } else {
                        if (HAS_BIAS) { c0 += bias[col0]; c1 += bias[col0 + 1]; }
                        if (HAS_RES) {
                            c0 += res[(size_t)row * Nn + col0];
                            c1 += res[(size_t)row * Nn + col0 + 1];
                        }
                        float2 o = {c0, c1};
                        *(float2*)(Cm + (size_t)row * Nn + col0) = o;
                        if (DO_AMAX) amx = fmaxf(amx, fmaxf(fabsf(c0), fabsf(c1)));
                    }
                }
            }
        }
    }
    if (DO_AMAX) {
        #pragma unroll
        for (int o = 16; o; o >>= 1) amx = fmaxf(amx, __shfl_xor_sync(0xffffffffu, amx, o));
        if (lane == 0) reds[warp] = amx;
        __syncthreads();
        if (tid == 0) {
            float m = reds[0];
            #pragma unroll
            for (int w = 1; w < 8; w++) m = fmaxf(m, reds[w]);
            unsigned* tgt = amax + (SEG ? (nBase / 1280) : 0);
            atomicMax(tgt, __float_as_uint(m));
        }
    }
}

// -------- s8 level quant from strided fp16 source --------
__global__ void quant_s8_strided_h(const __half* __restrict__ x, int8_t* __restrict__ L,
                                   const unsigned* __restrict__ amaxbits)
{
    float delta = fmaxf(__uint_as_float(*amaxbits), 1e-8f) / 127.0f;
    float inv = 1.0f / delta;
    long long n8 = (long long)ROWS * (CDIM / 8);
    long long stride = (long long)gridDim.x * blockDim.x;
    for (long long i = (long long)blockIdx.x * blockDim.x + threadIdx.x; i < n8; i += stride) {
        int row = (int)(i / (CDIM / 8));
        int c8 = (int)(i % (CDIM / 8));
        uint4 raw = *(const uint4*)(x + (size_t)row * QKVN + c8 * 8);
        const __half2* hp = (const __half2*)&raw;
        uint32_t outw[2];
        #pragma unroll
        for (int w = 0; w < 2; w++) {
            uint32_t o = 0;
            #pragma unroll
            for (int j = 0; j < 2; j++) {
                float2 f = __half22float2(hp[w*2 + j]);
                int a = clamp_i(__float2int_rn(f.x * inv), -128, 127);
                int b = clamp_i(__float2int_rn(f.y * inv), -128, 127);
                o |= ((uint32_t)(a & 255)) << (j*16);
                o |= ((uint32_t)(b & 255)) << (j*16 + 8);
            }
            outw[w] = o;
        }
        *(uint2*)(L + i * 8) = make_uint2(outw[0], outw[1]);
    }
}

// -------- V quant + per-head transpose (fp16 strided source) --------
__global__ void __launch_bounds__(256) quant_v_t_kernel(const __half* __restrict__ V,
                                                        int8_t* __restrict__ LVT,
                                                        const unsigned* __restrict__ amaxbits)
{
    __shared__ int8_t T[64][80];
    float delta = fmaxf(__uint_as_float(*amaxbits), 1e-8f) / 127.0f;
    float inv = 1.0f / delta;
    int tid = threadIdx.x;
    int bh = blockIdx.y, b = bh / NH, h = bh % NH;
    int m0 = blockIdx.x * 64;
    #pragma unroll
    for (int i = 0; i < 2; i++) {
        int lin = tid + i * 256;
        int r = lin >> 3;
        int c8 = (lin & 7) << 3;
        uint4 raw = *(const uint4*)(V + ((size_t)(b*NSEQ + m0 + r))*QKVN + h*DH + c8);
        const __half2* hp = (const __half2*)&raw;
        #pragma unroll
        for (int j = 0; j < 4; j++) {
            float2 f = __half22float2(hp[j]);
            T[c8 + 2*j + 0][r] = (int8_t)clamp_i(__float2int_rn(f.x*inv), -128, 127);
            T[c8 + 2*j + 1][r] = (int8_t)clamp_i(__float2int_rn(f.y*inv), -128, 127);
        }
    }
    __syncthreads();
    int d = tid >> 2, ch = (tid & 3) << 4;
    int4 val = *(int4*)&T[d][ch];
    *(int4*)(LVT + ((size_t)(bh*DH + d))*NSEQ + m0 + ch) = val;
}

// ======== FUSED self-attn stats: recompute scores, online softmax ========
__global__ void __launch_bounds__(256) self_stats_i8_kernel(
    const int8_t* __restrict__ LQ, const int8_t* __restrict__ LK,
    float* __restrict__ RM, float* __restrict__ RZ, unsigned* __restrict__ am)
{
    __shared__ __align__(16) int8_t Qs[128][80];
    __shared__ __align__(16) int8_t Ks[128][80];
    __shared__ float red[128][4];
    __shared__ float tmaxS[128];
    __shared__ float rowmS[128], rowzS[128];
    __shared__ float wred[8];
    float dq = fmaxf(__uint_as_float(am[0]), 1e-8f) / 127.0f;
    float dk = fmaxf(__uint_as_float(am[1]), 1e-8f) / 127.0f;
    float scale = dq * dk * 0.125f;
    int tid = threadIdx.x, lane = tid & 31, warp = tid >> 5;
    int bh = blockIdx.y, b = bh / NH, h = bh % NH;
    int n0 = blockIdx.x * 128;
    int wn = warp & 1, wm = warp >> 1;
    int gr = lane >> 2, gc = lane & 3;

    #pragma unroll
    for (int i = 0; i < 2; i++) {
        int lin = tid + i * 256;
        int r = lin >> 2, ch = (lin & 3) << 4;
        *(int4*)&Qs[r][ch] = *(const int4*)(LQ + ((size_t)(b*NSEQ + n0 + r))*CDIM + h*DH + ch);
    }
    if (tid < 128) { rowmS[tid] = -3.4e38f; rowzS[tid] = 0.f; }

    int rows[8];
    #pragma unroll
    for (int nt = 0; nt < 4; nt++)
        #pragma unroll
        for (int half = 0; half < 2; half++)
            rows[nt*2+half] = wn*64 + nt*16 + gr + half*8;

    for (int mc = 0; mc < 8; mc++) {
        __syncthreads();
        #pragma unroll
        for (int i = 0; i < 2; i++) {
            int lin = tid + i * 256;
            int r = lin >> 2, ch = (lin & 3) << 4;
            *(int4*)&Ks[r][ch] = *(const int4*)(LK + ((size_t)(b*NSEQ + mc*128 + r))*CDIM + h*DH + ch);
        }
        __syncthreads();

        int acc[4][4][4];
        #pragma unroll
        for (int i = 0; i < 4; i++)
            #pragma unroll
            for (int j = 0; j < 4; j++)
                #pragma unroll
                for (int l = 0; l < 4; l++) acc[i][j][l] = 0;
        #pragma unroll
        for (int ks = 0; ks < 2; ks++) {
            uint32_t af[4][4], bf[4][2];
            #pragma unroll
            for (int nt = 0; nt < 4; nt++) {
                int row = wn * 64 + nt * 16 + gr;
                af[nt][0] = *(const uint32_t*)&Qs[row][ks*32 + gc*4];
                af[nt][1] = *(const uint32_t*)&Qs[row + 8][ks*32 + gc*4];
                af[nt][2] = *(const uint32_t*)&Qs[row][ks*32 + 16 + gc*4];
                af[nt][3] = *(const uint32_t*)&Qs[row + 8][ks*32 + 16 + gc*4];
            }
            #pragma unroll
            for (int mt = 0; mt < 4; mt++) {
                int col = wm * 32 + mt * 8 + gr;
                bf[mt][0] = *(const uint32_t*)&Ks[col][ks*32 + gc*4];
                bf[mt][1] = *(const uint32_t*)&Ks[col][ks*32 + 16 + gc*4];
            }
            #pragma unroll
            for (int nt = 0; nt < 4; nt++)
                #pragma unroll
                for (int mt = 0; mt < 4; mt++)
                    mma_s8(acc[nt][mt], af[nt], bf[mt]);
        }

        float lmax[8];
        #pragma unroll
        for (int j = 0; j < 8; j++) lmax[j] = -3.4e38f;
        #pragma unroll
        for (int nt = 0; nt < 4; nt++)
            #pragma unroll
            for (int mt = 0; mt < 4; mt++)
                #pragma unroll
                for (int c = 0; c < 4; c++)
                    lmax[nt*2 + (c>>1)] = fmaxf(lmax[nt*2 + (c>>1)], scale*(float)acc[nt][mt][c]);
        #pragma unroll
        for (int j = 0; j < 8; j++) {
            lmax[j] = fmaxf(lmax[j], __shfl_xor_sync(0xffffffffu, lmax[j], 1));
            lmax[j] = fmaxf(lmax[j], __shfl_xor_sync(0xffffffffu, lmax[j], 2));
        }
        if (gc == 0) {
            #pragma unroll
            for (int j = 0; j < 8; j++) red[rows[j]][wm] = lmax[j];
        }
        __syncthreads();
        if (tid < 128)
            tmaxS[tid] = fmaxf(fmaxf(red[tid][0], red[tid][1]), fmaxf(red[tid][2], red[tid][3]));
        __syncthreads();

        float lsum[8];
        #pragma unroll
        for (int j = 0; j < 8; j++) lsum[j] = 0.f;
        #pragma unroll
        for (int nt = 0; nt < 4; nt++) {
            float tm0 = tmaxS[rows[nt*2]];
            float tm1 = tmaxS[rows[nt*2+1]];
            #pragma unroll
            for (int mt = 0; mt < 4; mt++) {
                lsum[nt*2]   += __expf(scale*(float)acc[nt][mt][0] - tm0)
                              + __expf(scale*(float)acc[nt][mt][1] - tm0);
                lsum[nt*2+1] += __expf(scale*(float)acc[nt][mt][2] - tm1)
                              + __expf(scale*(float)acc[nt][mt][3] - tm1);
            }
        }
        #pragma unroll
        for (int j = 0; j < 8; j++) {
            lsum[j] += __shfl_xor_sync(0xffffffffu, lsum[j], 1);
            lsum[j] += __shfl_xor_sync(0xffffffffu, lsum[j], 2);
        }
        if (gc == 0) {
            #pragma unroll
            for (int j = 0; j < 8; j++) red[rows[j]][wm] = lsum[j];
        }
        __syncthreads();
        if (tid < 128) {
            float ts = red[tid][0] + red[tid][1] + red[tid][2] + red[tid][3];
            float tm = tmaxS[tid];
            float om = rowmS[tid];
            float nm = fmaxf(om, tm);
            rowzS[tid] = rowzS[tid] * __expf(om - nm) + ts * __expf(tm - nm);
            rowmS[tid] = nm;
        }
    }
    __syncthreads();
    float invz = -3.4e38f;
    if (tid < 128) {
        float z = rowzS[tid];
        RM[(size_t)bh*NSEQ + n0 + tid] = rowmS[tid];
        RZ[(size_t)bh*NSEQ + n0 + tid] = z;
        invz = 1.0f / z;
    }
    #pragma unroll
    for (int o = 16; o; o >>= 1) invz = fmaxf(invz, __shfl_xor_sync(0xffffffffu, invz, o));
    if (lane == 0) wred[warp] = invz;
    __syncthreads();
    if (tid == 0) {
        float m = wred[0];
        #pragma unroll
        for (int w = 1; w < 8; w++) m = fmaxf(m, wred[w]);
        atomicMax(am + 3, __float_as_uint(m));
    }
}

// ======== FUSED self-attn PV ========
__global__ void __launch_bounds__(256) self_pv_i8_kernel(
    const int8_t* __restrict__ LQ, const int8_t* __restrict__ LK,
    const int8_t* __restrict__ LVT,
    const float* __restrict__ RM, const float* __restrict__ RZ,
    const unsigned* __restrict__ am, __half* __restrict__ O)
{
    __shared__ __align__(16) int8_t  Qs[128][80];
    __shared__ __align__(16) int8_t  Ks[128][80];
    __shared__ __align__(16) uint8_t Lws[128][144];
    __shared__ __align__(16) int8_t  VTs[64][144];
    __shared__ float rmS[128], riS[128];
    float dq = fmaxf(__uint_as_float(am[0]), 1e-8f) / 127.0f;
    float dk = fmaxf(__uint_as_float(am[1]), 1e-8f) / 127.0f;
    float scale = dq * dk * 0.125f;
    float dv = fmaxf(__uint_as_float(am[2]), 1e-8f) / 127.0f;
    float dw = fmaxf(__uint_as_float(am[3]), 1e-8f) / 255.0f;
    float inv_dw = 1.0f / dw;
    float oscale = dw * dv;
    int tid = threadIdx.x, lane = tid & 31, warp = tid >> 5;
    int bh = blockIdx.y, b = bh / NH, h = bh % NH;
    int n0 = blockIdx.x * 128;
    int wn = warp & 1, wm = warp >> 1, wd = warp >> 1;
    int gr = lane >> 2, gc = lane & 3;

    #pragma unroll
    for (int i = 0; i < 2; i++) {
        int lin = tid + i * 256;
        int r = lin >> 2, ch = (lin & 3) << 4;
        *(int4*)&Qs[r][ch] = *(const int4*)(LQ + ((size_t)(b*NSEQ + n0 + r))*CDIM + h*DH + ch);
    }
    if (tid < 128) {
        rmS[tid] = RM[(size_t)bh*NSEQ + n0 + tid];
        riS[tid] = 1.0f / RZ[(size_t)bh*NSEQ + n0 + tid];
    }

    int acc[4][2][4];
    #pragma unroll
    for (int i = 0; i < 4; i++)
        #pragma unroll
        for (int j = 0; j < 2; j++)
            #pragma unroll
            for (int l = 0; l < 4; l++) acc[i][j][l] = 0;

    for (int mc = 0; mc < 8; mc++) {
        __syncthreads();
        #pragma unroll
        for (int i = 0; i < 2; i++) {
            int lin = tid + i * 256;
            int r = lin >> 2, ch = (lin & 3) << 4;
            *(int4*)&Ks[r][ch] = *(const int4*)(LK + ((size_t)(b*NSEQ + mc*128 + r))*CDIM + h*DH + ch);
        }
        #pragma unroll
        for (int i = 0; i < 2; i++) {
            int lin = tid + i * 256;
            int d = lin >> 3, ch = (lin & 7) << 4;
            *(int4*)&VTs[d][ch] = *(const int4*)(LVT + ((size_t)(bh*DH + d))*NSEQ + mc*128 + ch);
        }
        __syncthreads();

        int sacc[4][4][4];
        #pragma unroll
        for (int i = 0; i < 4; i++)
            #pragma unroll
            for (int j = 0; j < 4; j++)
                #pragma unroll
                for (int l = 0; l < 4; l++) sacc[i][j][l] = 0;
        #pragma unroll
        for (int ks = 0; ks < 2; ks++) {
            uint32_t af[4][4], bf[4][2];
            #pragma unroll
            for (int nt = 0; nt < 4; nt++) {
                int row = wn * 64 + nt * 16 + gr;
                af[nt][0] = *(const uint32_t*)&Qs[row][ks*32 + gc*4];
                af[nt][1] = *(const uint32_t*)&Qs[row + 8][ks*32 + gc*4];
                af[nt][2] = *(const uint32_t*)&Qs[row][ks*32 + 16 + gc*4];
                af[nt][3] = *(const uint32_t*)&Qs[row + 8][ks*32 + 16 + gc*4];
            }
            #pragma unroll
            for (int mt = 0; mt < 4; mt++) {
                int col = wm * 32 + mt * 8 + gr;
                bf[mt][0] = *(const uint32_t*)&Ks[col][ks*32 + gc*4];
                bf[mt][1] = *(const uint32_t*)&Ks[col][ks*32 + 16 + gc*4];
            }
            #pragma unroll
            for (int nt = 0; nt < 4; nt++)
                #pragma unroll
                for (int mt = 0; mt < 4; mt++)
                    mma_s8(sacc[nt][mt], af[nt], bf[mt]);
        }
        #pragma unroll
        for (int nt = 0; nt < 4; nt++) {
            #pragma unroll
            for (int half = 0; half < 2; half++) {
                int row = wn*64 + nt*16 + gr + half*8;
                float rm = rmS[row];
                float f = riS[row] * inv_dw;
                #pragma unroll
                for (int mt = 0; mt < 4; mt++) {
                    int col = wm*32 + mt*8 + gc*2;
                    int l0 = min(255, __float2int_rn(__expf(scale*(float)sacc[nt][mt][half*2+0] - rm) * f));
                    int l1 = min(255, __float2int_rn(__expf(scale*(float)sacc[nt][mt][half*2+1] - rm) * f));
                    *(uint16_t*)&Lws[row][col] = (uint16_t)(l0 | (l1 << 8));
                }
            }
        }
        __syncthreads();

        #pragma unroll
        for (int ks = 0; ks < 4; ks++) {
            uint32_t af[4][4], bf[2][2];
            #pragma unroll
            for (int nt = 0; nt < 4; nt++) {
                int row = wn * 64 + nt * 16 + gr;
                af[nt][0] = *(const uint32_t*)&Lws[row][ks*32 + gc*4];
                af[nt][1] = *(const uint32_t*)&Lws[row + 8][ks*32 + gc*4];
                af[nt][2] = *(const uint32_t*)&Lws[row][ks*32 + 16 + gc*4];
                af[nt][3] = *(const uint32_t*)&Lws[row + 8][ks*32 + 16 + gc*4];
            }
            #pragma unroll
            for (int dt = 0; dt < 2; dt++) {
                int col = wd * 16 + dt * 8 + gr;
                bf[dt][0] = *(const uint32_t*)&VTs[col][ks*32 + gc*4];
                bf[dt][1] = *(const uint32_t*)&VTs[col][ks*32 + 16 + gc*4];
            }
            #pragma unroll
            for (int nt = 0; nt < 4; nt++)
                #pragma unroll
                for (int dt = 0; dt < 2; dt++)
                    mma_u8s8(acc[nt][dt], af[nt], bf[dt]);
        }
    }
    #pragma unroll
    for (int nt = 0; nt < 4; nt++) {
        #pragma unroll
        for (int dt = 0; dt < 2; dt++) {
            int row0 = n0 + wn * 64 + nt * 16 + gr;
            int col0 = wd * 16 + dt * 8 + gc * 2;
            #pragma unroll
            for (int half = 0; half < 2; half++) {
                int row = row0 + half * 8;
                __half2 o = __floats2half2_rn(oscale * (float)acc[nt][dt][half*2+0],
                                              oscale * (float)acc[nt][dt][half*2+1]);
                *(__half2*)(O + ((size_t)(b*NSEQ + row))*CDIM + h*DH + col0) = o;
            }
        }
    }
}

// ======== FUSED cross stats: quantize-on-load, scores in regs, no S ========
// grid (16, BHD), block 256. q fp16 [ROWS][CDIM]; kv fp16 [CROSSROWS][KV2N] (K at 0).
__global__ void __launch_bounds__(256) cross_stats_f(
    const __half* __restrict__ q, const __half* __restrict__ kv,
    float* __restrict__ RM, float* __restrict__ RZ, unsigned* __restrict__ am)
{
    __shared__ float SQ[64][68];   // [d][n]
    __shared__ float SK[80][68];   // [m][d]
    __shared__ float red16[16];
    float dq = fmaxf(__uint_as_float(am[4]), 1e-8f) / 127.0f;
    float dk = fmaxf(__uint_as_float(am[5]), 1e-8f) / 127.0f;
    float iq = 1.0f / dq, ik = 1.0f / dk;
    int tid = threadIdx.x;
    int bh = blockIdx.y, b = bh / NH, h = bh % NH;
    int n0 = blockIdx.x * 64;

    #pragma unroll
    for (int it = 0; it < 4; ++it) {
        int r = (tid >> 4) + it * 16, c = (tid & 15) << 2;
        uint2 raw = *(const uint2*)(q + ((size_t)(b*NSEQ + n0 + r))*CDIM + h*DH + c);
        const __half* hp = (const __half*)&raw;
        #pragma unroll
        for (int j = 0; j < 4; j++) SQ[c+j][r] = fq_h(hp[j], iq, dq);
    }
    #pragma unroll
    for (int it = 0; it < 5; ++it) {
        int lin = tid + it * 256;
        if (lin < 80 * 16) {
            int r = lin >> 4, c = (lin & 15) << 2;
            if (r < MCTX) {
                uint2 raw = *(const uint2*)(kv + ((size_t)(b*MCTX + r))*KV2N + h*DH + c);
                const __half* hp = (const __half*)&raw;
                #pragma unroll
                for (int j = 0; j < 4; j++) SK[r][c+j] = fq_h(hp[j], ik, dk);
            } else {
                #pragma unroll
                for (int j = 0; j < 4; j++) SK[r][c+j] = 0.f;
            }
        }
    }
    __syncthreads();
    int tx = tid & 15, ty = tid >> 4;
    float acc[4][5];
    #pragma unroll
    for (int i = 0; i < 4; i++)
        #pragma unroll
        for (int j = 0; j < 5; j++) acc[i][j] = 0.f;
    #pragma unroll 4
    for (int d = 0; d < 64; ++d) {
        float4 q4 = *(const float4*)&SQ[d][ty*4];
        float qa[4]={q4.x,q4.y,q4.z,q4.w};
        #pragma unroll
        for (int jj = 0; jj < 5; jj++) {
            float kvv = SK[tx*5+jj][d];
            #pragma unroll
            for (int i = 0; i < 4; i++) acc[i][jj] = fmaf(qa[i], kvv, acc[i][jj]);
        }
    }
    float lm[4], lz[4];
    #pragma unroll
    for (int i = 0; i < 4; i++) {
        lm[i] = -3.4e38f;
        #pragma unroll
        for (int jj = 0; jj < 5; jj++)
            if (tx*5+jj < MCTX) lm[i] = fmaxf(lm[i], acc[i][jj] * 0.125f);
    }
    #pragma unroll
    for (int i = 0; i < 4; i++) {
        #pragma unroll
        for (int o = 1; o < 16; o <<= 1)
            lm[i] = fmaxf(lm[i], __shfl_xor_sync(0xffffffffu, lm[i], o));
    }
    #pragma unroll
    for (int i = 0; i < 4; i++) {
        lz[i] = 0.f;
        #pragma unroll
        for (int jj = 0; jj < 5; jj++)
            if (tx*5+jj < MCTX) lz[i] += __expf(acc[i][jj] * 0.125f - lm[i]);
    }
    #pragma unroll
    for (int i = 0; i < 4; i++) {
        #pragma unroll
        for (int o = 1; o < 16; o <<= 1)
            lz[i] += __shfl_xor_sync(0xffffffffu, lz[i], o);
    }
    float invz = -3.4e38f;
    if (tx == 0) {
        #pragma unroll
        for (int i = 0; i < 4; i++) {
            size_t row = (size_t)bh*NSEQ + n0 + ty*4 + i;
            RM[row] = lm[i];
            RZ[row] = lz[i];
            invz = fmaxf(invz, 1.0f / lz[i]);
        }
        red16[ty] = invz;
    }
    __syncthreads();
    if (tid == 0) {
        float m = red16[0];
        #pragma unroll
        for (int w = 1; w < 16; w++) m = fmaxf(m, red16[w]);
        atomicMax(am + 7, __float_as_uint(m));
    }
}

// ======== FUSED cross PV: recompute scores, fq_zero, PV — no S ========
__global__ void __launch_bounds__(256) cross_pv_f(
    const __half* __restrict__ q, const __half* __restrict__ kv,
    const float* __restrict__ RM, const float* __restrict__ RZ,
    const unsigned* __restrict__ am, __half* __restrict__ O)
{
    __shared__ float raw[80*68*2];   // phaseA: SQ[64][68]+SK[80][68]; phaseB: SW[80][68]+SV[80][68]
    float* SQ = raw;                  // [d][n] 64x68
    float* SK = raw + 64*68;          // [m][d] 80x68
    float* SW = raw;                  // [m][n] 80x68
    float* SV = raw + 80*68;          // [m][d] 80x68
    float dq = fmaxf(__uint_as_float(am[4]), 1e-8f) / 127.0f;
    float dk = fmaxf(__uint_as_float(am[5]), 1e-8f) / 127.0f;
    float dv = fmaxf(__uint_as_float(am[6]), 1e-8f) / 127.0f;
    float dw = fmaxf(__uint_as_float(am[7]), 1e-8f) / 255.0f;
    float iq = 1.0f/dq, ik = 1.0f/dk, iv = 1.0f/dv, inv_dw = 1.0f/dw;
    int tid = threadIdx.x;
    int bh = blockIdx.y, b = bh / NH, h = bh % NH;
    int n0 = blockIdx.x * 64;
    int tx = tid & 15, ty = tid >> 4;

    // phase A: Q,K
    #pragma unroll
    for (int it = 0; it < 4; ++it) {
        int r = (tid >> 4) + it * 16, c = (tid & 15) << 2;
        uint2 rawq = *(const uint2*)(q + ((size_t)(b*NSEQ + n0 + r))*CDIM + h*DH + c);
        const __half* hp = (const __half*)&rawq;
        #pragma unroll
        for (int j = 0; j < 4; j++) SQ[(c+j)*68 + r] = fq_h(hp[j], iq, dq);
    }
    #pragma unroll
    for (int it = 0; it < 5; ++it) {
        int lin = tid + it * 256;
        if (lin < 80 * 16) {
            int r = lin >> 4, c = (lin & 15) << 2;
            if (r < MCTX) {
                uint2 rawk = *(const uint2*)(kv + ((size_t)(b*MCTX + r))*KV2N + h*DH + c);
                const __half* hp = (const __half*)&rawk;
                #pragma unroll
                for (int j = 0; j < 4; j++) SK[r*68 + c+j] = fq_h(hp[j], ik, dk);
            } else {
                #pragma unroll
                for (int j = 0; j < 4; j++) SK[r*68 + c+j] = 0.f;
            }
        }
    }
    __syncthreads();
    float acc[4][5];
    #pragma unroll
    for (int i = 0; i < 4; i++)
        #pragma unroll
        for (int j = 0; j < 5; j++) acc[i][j] = 0.f;
    #pragma unroll 4
    for (int d = 0; d < 64; ++d) {
        float4 q4 = *(const float4*)&SQ[d*68 + ty*4];
        float qa[4]={q4.x,q4.y,q4.z,q4.w};
        #pragma unroll
        for (int jj = 0; jj < 5; jj++) {
            float kvv = SK[(tx*5+jj)*68 + d];
            #pragma unroll
            for (int i = 0; i < 4; i++) acc[i][jj] = fmaf(qa[i], kvv, acc[i][jj]);
        }
    }
    __syncthreads();   // done reading SQ/SK

    // phase B: V load + prob quantize
    #pragma unroll
    for (int it = 0; it < 5; ++it) {
        int lin = tid + it * 256;
        if (lin < MCTX * 16) {
            int r = lin >> 4, c = (lin & 15) << 2;
            uint2 rawv = *(const uint2*)(kv + ((size_t)(b*MCTX + r))*KV2N + CDIM + h*DH + c);
            const __half* hp = (const __half*)&rawv;
            #pragma unroll
            for (int j = 0; j < 4; j++) SV[r*68 + c+j] = fq_h(hp[j], iv, dv);
        }
    }
    #pragma unroll
    for (int i = 0; i < 4; i++) {
        int rrow = ty*4 + i;
        float rm = RM[(size_t)bh*NSEQ + n0 + rrow];
        float ri = 1.0f / RZ[(size_t)bh*NSEQ + n0 + rrow];
        #pragma unroll
        for (int jj = 0; jj < 5; jj++) {
            int m = tx*5 + jj;
            float w = 0.f;
            if (m < MCTX) {
                float p = __expf(acc[i][jj] * 0.125f - rm);
                float l = fminf(rintf(p * ri * inv_dw), 255.f);
                w = l * dw;
            }
            SW[m*68 + rrow] = w;
        }
    }
    __syncthreads();

    float oacc[4][4];
    #pragma unroll
    for (int i = 0; i < 4; i++)
        #pragma unroll
        for (int j = 0; j < 4; j++) oacc[i][j] = 0.f;
    for (int m = 0; m < MCTX; m++) {
        float4 w4 = *(const float4*)&SW[m*68 + ty*4];
        float4 v4 = *(const float4*)&SV[m*68 + tx*4];
        float wa[4]={w4.x,w4.y,w4.z,w4.w}, va[4]={v4.x,v4.y,v4.z,v4.w};
        #pragma unroll
        for (int i = 0; i < 4; i++)
            #pragma unroll
            for (int j = 0; j < 4; j++) oacc[i][j] = fmaf(wa[i], va[j], oacc[i][j]);
    }
    #pragma unroll
    for (int i = 0; i < 4; i++) {
        __half* Ob = O + ((size_t)(b*NSEQ + n0 + ty*4 + i))*CDIM + h*DH + tx*4;
        *(__half2*)(Ob + 0) = __floats2half2_rn(oacc[i][0], oacc[i][1]);
        *(__half2*)(Ob + 2) = __floats2half2_rn(oacc[i][2], oacc[i][3]);
    }
}

extern "C" void kernel_launch(void* const* d_in, const int* in_sizes, int n_in,
                              void* d_out, int out_size)
{
    const float* x    = (const float*)d_in[0];
    const float* ctx  = (const float*)d_in[1];
    const float* ln1g = (const float*)d_in[2];
    const float* ln1b = (const float*)d_in[3];
    const float* ln2g = (const float*)d_in[4];
    const float* ln2b = (const float*)d_in[5];
    const float* ln3g = (const float*)d_in[6];
    const float* ln3b = (const float*)d_in[7];
    const float* Wq1  = (const float*)d_in[8];
    const float* Wk1  = (const float*)d_in[9];
    const float* Wv1  = (const float*)d_in[10];
    const float* Wo1  = (const float*)d_in[11];
    const float* bo1  = (const float*)d_in[12];
    const float* Wq2  = (const float*)d_in[13];
    const float* Wk2  = (const float*)d_in[14];
    const float* Wv2  = (const float*)d_in[15];
    const float* Wo2  = (const float*)d_in[16];
    const float* bo2  = (const float*)d_in[17];
    const float* Wff1 = (const float*)d_in[18];
    const float* bff1 = (const float*)d_in[19];
    const float* Wff2 = (const float*)d_in[20];
    const float* bff2 = (const float*)d_in[21];
    float* out = (float*)d_out;

    float* sc = nullptr;
    cudaGetSymbolAddress((void**)&sc, g_scratch);
    __half* XN   = (__half*)(sc + OFF_XN);
    __half* QKVh = (__half*)(sc + OFF_Q);
    __half* Qch  = (__half*)(sc + OFF_Q);
    __half* KV2h = (__half*)(sc + OFF_K);
    __half* O    = (__half*)(sc + OFF_O);
    float*  X1   = sc + OFF_X1;
    __half* G    = (__half*)(sc + OFF_G);
    float*  RM   = sc + OFF_RM;
    float*  RZ   = sc + OFF_RZ;
    unsigned* AM = (unsigned*)(sc + OFF_AM);
    __half* cWqkv = (__half*)(sc + OFF_WQKV);
    __half* cWo1  = (__half*)(sc + OFF_WO1);
    __half* cWq2  = (__half*)(sc + OFF_WQ2);
    __half* cWo2  = (__half*)(sc + OFF_WO2);
    __half* cWkv2 = (__half*)(sc + OFF_WKV2);
    __half* cWf1  = (__half*)(sc + OFF_WF1);
    __half* cWf2  = (__half*)(sc + OFF_WF2);
    __half* cCtx  = (__half*)(sc + OFF_CTX);
    int8_t* LQ8 = (int8_t*)(sc + OFF_LQ8);
    int8_t* LK8 = (int8_t*)(sc + OFF_LK8);
    int8_t* LVT = (int8_t*)(sc + OFF_LVT);

    dim3 g1280(CDIM / 128, ROWS / 128);
    dim3 gqkv(QKVN / 128, ROWS / 128);
    dim3 gkv2(KV2N / 128, (CROSSROWS + 127) / 128);
    dim3 gff1(FF2D / 128, ROWS / 128);

    init_amax_kernel<<<1, 32>>>(AM);

    conv_pack_kernel<<<512,256>>>(Wq1, cWqkv + 0,      CDIM, CDIM, QKVN);
    conv_pack_kernel<<<512,256>>>(Wk1, cWqkv + CDIM,   CDIM, CDIM, QKVN);
    conv_pack_kernel<<<512,256>>>(Wv1, cWqkv + 2*CDIM, CDIM, CDIM, QKVN);
    conv_pack_kernel<<<512,256>>>(Wk2, cWkv2 + 0,    CTXC, CDIM, KV2N);
    conv_pack_kernel<<<512,256>>>(Wv2, cWkv2 + CDIM, CTXC, CDIM, KV2N);
    conv_h_kernel<<<1024,256>>>(Wo1,  cWo1, (long long)SZ_W1/4);
    conv_h_kernel<<<1024,256>>>(Wq2,  cWq2, (long long)SZ_W1/4);
    conv_h_kernel<<<1024,256>>>(Wo2,  cWo2, (long long)SZ_W1/4);
    conv_ileave_kernel<<<2048,256>>>(Wff1, cWf1);
    conv_h_kernel<<<2048,256>>>(Wff2, cWf2, (long long)SZ_WF2/4);
    conv_h_kernel<<<512,256>>>(ctx,   cCtx, (long long)SZ_CTXB/4);

    // ---- block 1: self attention (fp16 QKV, int8 flash path) ----
    ln_kernel<<<ROWS, 256>>>(x, ln1g, ln1b, XN);
    tgemm_kernel<false,false,true,true,false,true><<<gqkv,256>>>(XN, cWqkv, (float*)QKVh, ROWS, QKVN, CDIM, nullptr, nullptr, AM+0);
    quant_s8_strided_h<<<1024,256>>>(QKVh + 0,    LQ8, AM+0);
    quant_s8_strided_h<<<1024,256>>>(QKVh + CDIM, LK8, AM+1);
    quant_v_t_kernel<<<dim3(NSEQ/64, BHD),256>>>(QKVh + 2*CDIM, LVT, AM+2);
    self_stats_i8_kernel<<<dim3(8,BHD),256>>>(LQ8, LK8, RM, RZ, AM);
    self_pv_i8_kernel<<<dim3(8,BHD),256>>>(LQ8, LK8, LVT, RM, RZ, AM, O);
    tgemm_kernel<true,true,false,false,false,false><<<g1280,256>>>(O, cWo1, X1, ROWS, CDIM, CDIM, bo1, x, nullptr);

    // ---- block 2: cross attention (fully fused, no S tensor, no quant kernels) ----
    ln_kernel<<<ROWS,256>>>(X1, ln2g, ln2b, XN);
    tgemm_kernel<false,false,true,false,false,true><<<g1280,256>>>(XN, cWq2, (float*)Qch, ROWS, CDIM, CDIM, nullptr, nullptr, AM+4);
    tgemm_kernel<false,false,true,true,false,true><<<gkv2,256>>>(cCtx, cWkv2, (float*)KV2h, CROSSROWS, KV2N, CTXC, nullptr, nullptr, AM+5);
    cross_stats_f<<<dim3(16,BHD),256>>>(Qch, KV2h, RM, RZ, AM);
    cross_pv_f<<<dim3(16,BHD),256>>>(Qch, KV2h, RM, RZ, AM, O);
    tgemm_kernel<true,true,false,false,false,false><<<g1280,256>>>(O, cWo2, X1, ROWS, CDIM, CDIM, bo2, X1, nullptr);

    // ---- block 3: GEGLU FF ----
    ln_kernel<<<ROWS,256>>>(X1, ln3g, ln3b, XN);
    tgemm_kernel<true,false,false,false,true,false><<<gff1,256>>>(XN, cWf1, (float*)G, ROWS, FF2D, CDIM, bff1, nullptr, nullptr);
    tgemm_kernel<true,true,false,false,false,false><<<g1280,256>>>(G, cWf2, out, ROWS, CDIM, FFD, bff2, X1, nullptr);
}